// round 1
// baseline (speedup 1.0000x reference)
#include <cuda_runtime.h>
#include <math.h>

#define LL 2
#define HH 16
#define DD 1024
#define HD 64
#define FFD 4096
#define VV 32000
#define SS 1024
#define BB 4
#define BS (BB*SS)   /* 4096 */

// ---------------- scratch (device globals: the sanctioned no-alloc scratch) ----
__device__ float g_h  [(size_t)BS*DD];        // residual stream      16 MB
__device__ float g_q  [(size_t)HH*BS*HD];     // Q as [H][B*S][HD]    16 MB
__device__ float g_k  [(size_t)HH*BS*HD];
__device__ float g_v  [(size_t)HH*BS*HD];
__device__ float g_att[(size_t)BB*HH*SS*SS];  // [h*B+b][S][S]       268 MB
__device__ float g_o  [(size_t)BS*DD];        // concat-head attn out
__device__ float g_t  [(size_t)BS*DD];        // pre-LN delta
__device__ float g_ff [(size_t)BS*FFD];       // FFN hidden           67 MB

// ---------------- helpers ----------------
__device__ __forceinline__ float warpSum(float v){
    #pragma unroll
    for (int o = 16; o > 0; o >>= 1) v += __shfl_xor_sync(0xffffffffu, v, o);
    return v;
}
__device__ __forceinline__ float warpMax(float v){
    #pragma unroll
    for (int o = 16; o > 0; o >>= 1) v = fmaxf(v, __shfl_xor_sync(0xffffffffu, v, o));
    return v;
}
// 256-thread block sum; sh must have >=8 floats. Safe for repeated calls.
__device__ __forceinline__ float blockSum256(float v, float* sh){
    int lane = threadIdx.x & 31, wid = threadIdx.x >> 5;
    v = warpSum(v);
    if (lane == 0) sh[wid] = v;
    __syncthreads();
    float r = (threadIdx.x < 8) ? sh[threadIdx.x] : 0.f;
    if (threadIdx.x < 32) { r = warpSum(r); if (threadIdx.x == 0) sh[0] = r; }
    __syncthreads();
    float res = sh[0];
    __syncthreads();
    return res;
}
__device__ __forceinline__ float gelu_f(float x){
    return 0.5f * x * (1.0f + erff(x * 0.70710678118654752f));
}

// ---------------- embedding ----------------
__global__ __launch_bounds__(256) void embed_k(const int* __restrict__ x,
                                               const float* __restrict__ tok,
                                               const float* __restrict__ pos){
    int t = blockIdx.x;            // 0..BS-1
    int s = t & (SS - 1);
    int id = x[t];
    int j = threadIdx.x * 4;
    float4 a = *(const float4*)(tok + (size_t)id * DD + j);
    float4 p = *(const float4*)(pos + (size_t)s  * DD + j);
    float4 r; r.x = a.x + p.x; r.y = a.y + p.y; r.z = a.z + p.z; r.w = a.w + p.w;
    *(float4*)(g_h + (size_t)t * DD + j) = r;
}

// ---------------- 128x128x8 NN SGEMM, 8x8/thread ----------------
__global__ __launch_bounds__(256, 2) void gemm128_nn(
    const float* __restrict__ A, int lda, long sAb,
    const float* __restrict__ Bm, int ldb, long sBb,
    const float* __restrict__ bias, long sBiasb,
    float* __restrict__ C, int ldc, int zdiv, long sCbLo, long sCbHi,
    int K, int op)
{
    int z = blockIdx.z;
    A  += (long)z * sAb;
    Bm += (long)z * sBb;
    if (bias) bias += (long)z * sBiasb;
    C  += (long)(z % zdiv) * sCbLo + (long)(z / zdiv) * sCbHi;

    __shared__ __align__(16) float As[8][128];
    __shared__ __align__(16) float Bs[8][128];
    int tid = threadIdx.x;
    long row0 = (long)blockIdx.y * 128;
    int  col0 = blockIdx.x * 128;
    int tx = tid & 15, ty = tid >> 4;
    int trow = ty * 8, tcol = tx * 8;
    float acc[8][8];
    #pragma unroll
    for (int i = 0; i < 8; i++)
        #pragma unroll
        for (int j = 0; j < 8; j++) acc[i][j] = 0.f;

    int a_r = tid >> 1, a_c = (tid & 1) * 4;
    int b_r = tid >> 5, b_c = (tid & 31) * 4;
    const float* Aptr = A  + (row0 + a_r) * (long)lda + a_c;
    const float* Bptr = Bm + (long)b_r * ldb + col0 + b_c;

    for (int k0 = 0; k0 < K; k0 += 8){
        float4 av = *(const float4*)(Aptr + k0);
        float4 bv = *(const float4*)(Bptr + (long)k0 * ldb);
        As[a_c+0][a_r] = av.x; As[a_c+1][a_r] = av.y;
        As[a_c+2][a_r] = av.z; As[a_c+3][a_r] = av.w;
        *(float4*)&Bs[b_r][b_c] = bv;
        __syncthreads();
        #pragma unroll
        for (int kk = 0; kk < 8; kk++){
            float ra[8], rb[8];
            #pragma unroll
            for (int i = 0; i < 8; i++) ra[i] = As[kk][trow + i];
            #pragma unroll
            for (int j = 0; j < 8; j++) rb[j] = Bs[kk][tcol + j];
            #pragma unroll
            for (int i = 0; i < 8; i++)
                #pragma unroll
                for (int j = 0; j < 8; j++) acc[i][j] += ra[i] * rb[j];
        }
        __syncthreads();
    }
    #pragma unroll
    for (int i = 0; i < 8; i++){
        long r = row0 + trow + i;
        #pragma unroll
        for (int j = 0; j < 8; j += 4){
            int c = col0 + tcol + j;
            float4 o;
            o.x = acc[i][j+0]; o.y = acc[i][j+1]; o.z = acc[i][j+2]; o.w = acc[i][j+3];
            if (bias){ o.x += bias[c]; o.y += bias[c+1]; o.z += bias[c+2]; o.w += bias[c+3]; }
            if (op == 1){ o.x = gelu_f(o.x); o.y = gelu_f(o.y); o.z = gelu_f(o.z); o.w = gelu_f(o.w); }
            *(float4*)(C + r * (long)ldc + c) = o;
        }
    }
}

// ---------------- 128x128x8 NT SGEMM (C = A * B^T), for QK^T ----------------
__global__ __launch_bounds__(256, 2) void gemm128_nt(
    const float* __restrict__ A, int lda, long sAb,
    const float* __restrict__ Bm, int ldb, long sBb,
    float* __restrict__ C, int ldc, long sCb, int K)
{
    int z = blockIdx.z;
    A  += (long)z * sAb;
    Bm += (long)z * sBb;
    C  += (long)z * sCb;

    __shared__ __align__(16) float As[8][128];
    __shared__ __align__(16) float Bs[8][128];
    int tid = threadIdx.x;
    long row0 = (long)blockIdx.y * 128;
    int  col0 = blockIdx.x * 128;
    int tx = tid & 15, ty = tid >> 4;
    int trow = ty * 8, tcol = tx * 8;
    float acc[8][8];
    #pragma unroll
    for (int i = 0; i < 8; i++)
        #pragma unroll
        for (int j = 0; j < 8; j++) acc[i][j] = 0.f;

    int a_r = tid >> 1, a_c = (tid & 1) * 4;   // A: [128 rows][8 k]
    int b_n = tid >> 1, b_k = (tid & 1) * 4;   // B^T: row = out col, contiguous k
    const float* Aptr = A  + (row0 + a_r) * (long)lda + a_c;
    const float* Bptr = Bm + (long)(col0 + b_n) * ldb + b_k;

    for (int k0 = 0; k0 < K; k0 += 8){
        float4 av = *(const float4*)(Aptr + k0);
        float4 bv = *(const float4*)(Bptr + k0);
        As[a_c+0][a_r] = av.x; As[a_c+1][a_r] = av.y;
        As[a_c+2][a_r] = av.z; As[a_c+3][a_r] = av.w;
        Bs[b_k+0][b_n] = bv.x; Bs[b_k+1][b_n] = bv.y;
        Bs[b_k+2][b_n] = bv.z; Bs[b_k+3][b_n] = bv.w;
        __syncthreads();
        #pragma unroll
        for (int kk = 0; kk < 8; kk++){
            float ra[8], rb[8];
            #pragma unroll
            for (int i = 0; i < 8; i++) ra[i] = As[kk][trow + i];
            #pragma unroll
            for (int j = 0; j < 8; j++) rb[j] = Bs[kk][tcol + j];
            #pragma unroll
            for (int i = 0; i < 8; i++)
                #pragma unroll
                for (int j = 0; j < 8; j++) acc[i][j] += ra[i] * rb[j];
        }
        __syncthreads();
    }
    #pragma unroll
    for (int i = 0; i < 8; i++){
        long r = row0 + trow + i;
        #pragma unroll
        for (int j = 0; j < 8; j += 4){
            int c = col0 + tcol + j;
            float4 o;
            o.x = acc[i][j+0]; o.y = acc[i][j+1]; o.z = acc[i][j+2]; o.w = acc[i][j+3];
            *(float4*)(C + r * (long)ldc + c) = o;
        }
    }
}

// ---------------- 64x64x16 NN SGEMM, 4x4/thread (N=64 GEMMs: QKV, AV) -------
__global__ __launch_bounds__(256) void gemm64_nn(
    const float* __restrict__ A, int lda, long sAb,
    const float* __restrict__ Bm, int ldb, long sBb,
    const float* __restrict__ bias, long sBiasb,
    float* __restrict__ C, int ldc, int zdiv, long sCbLo, long sCbHi,
    int K)
{
    int z = blockIdx.z;
    A  += (long)z * sAb;
    Bm += (long)z * sBb;
    if (bias) bias += (long)z * sBiasb;
    C  += (long)(z % zdiv) * sCbLo + (long)(z / zdiv) * sCbHi;

    __shared__ __align__(16) float As[16][64];
    __shared__ __align__(16) float Bs[16][64];
    int tid = threadIdx.x;
    long row0 = (long)blockIdx.y * 64;
    int  col0 = blockIdx.x * 64;
    int tx = tid & 15, ty = tid >> 4;
    int trow = ty * 4, tcol = tx * 4;
    float acc[4][4];
    #pragma unroll
    for (int i = 0; i < 4; i++)
        #pragma unroll
        for (int j = 0; j < 4; j++) acc[i][j] = 0.f;

    int a_r = tid >> 2, a_c = (tid & 3) * 4;
    int b_r = tid >> 4, b_c = (tid & 15) * 4;
    const float* Aptr = A  + (row0 + a_r) * (long)lda + a_c;
    const float* Bptr = Bm + (long)b_r * ldb + col0 + b_c;

    for (int k0 = 0; k0 < K; k0 += 16){
        float4 av = *(const float4*)(Aptr + k0);
        float4 bv = *(const float4*)(Bptr + (long)k0 * ldb);
        As[a_c+0][a_r] = av.x; As[a_c+1][a_r] = av.y;
        As[a_c+2][a_r] = av.z; As[a_c+3][a_r] = av.w;
        *(float4*)&Bs[b_r][b_c] = bv;
        __syncthreads();
        #pragma unroll
        for (int kk = 0; kk < 16; kk++){
            float4 ra = *(const float4*)&As[kk][trow];
            float4 rb = *(const float4*)&Bs[kk][tcol];
            float a0[4] = {ra.x, ra.y, ra.z, ra.w};
            float b0[4] = {rb.x, rb.y, rb.z, rb.w};
            #pragma unroll
            for (int i = 0; i < 4; i++)
                #pragma unroll
                for (int j = 0; j < 4; j++) acc[i][j] += a0[i] * b0[j];
        }
        __syncthreads();
    }
    #pragma unroll
    for (int i = 0; i < 4; i++){
        long r = row0 + trow + i;
        int c = col0 + tcol;
        float4 o;
        o.x = acc[i][0]; o.y = acc[i][1]; o.z = acc[i][2]; o.w = acc[i][3];
        if (bias){ o.x += bias[c]; o.y += bias[c+1]; o.z += bias[c+2]; o.w += bias[c+3]; }
        *(float4*)(C + r * (long)ldc + c) = o;
    }
}

// ---------------- causal softmax over a 1024-wide row ----------------
__global__ __launch_bounds__(256) void softmax_k(float* __restrict__ att){
    long rid = blockIdx.x;                   // 0 .. 64*1024-1
    int i = (int)(rid & (SS - 1));           // query position
    float* row = att + rid * (long)SS;
    int tid = threadIdx.x;
    __shared__ float shm[8];
    __shared__ float shs[8];

    float4 v4 = *(const float4*)(row + tid * 4);
    float v[4] = {v4.x, v4.y, v4.z, v4.w};
    float m = -1e30f;
    #pragma unroll
    for (int c = 0; c < 4; c++){
        int j = tid * 4 + c;
        v[c] = (j <= i) ? v[c] * 0.125f : -1e30f;
        m = fmaxf(m, v[c]);
    }
    // block max
    int lane = tid & 31, wid = tid >> 5;
    float wm = warpMax(m);
    if (lane == 0) shm[wid] = wm;
    __syncthreads();
    if (tid < 32){
        float r = (tid < 8) ? shm[tid] : -1e30f;
        r = warpMax(r);
        if (tid == 0) shm[0] = r;
    }
    __syncthreads();
    m = shm[0];

    float s = 0.f;
    #pragma unroll
    for (int c = 0; c < 4; c++){ v[c] = expf(v[c] - m); s += v[c]; }
    float bs = blockSum256(s, shs);
    float inv = 1.f / bs;
    float4 o; o.x = v[0]*inv; o.y = v[1]*inv; o.z = v[2]*inv; o.w = v[3]*inv;
    *(float4*)(row + tid * 4) = o;
}

// ---------------- residual add + LayerNorm, in-place on g_h ----------------
__global__ __launch_bounds__(256) void add_ln_k(float* __restrict__ h,
                                                const float* __restrict__ delta,
                                                const float* __restrict__ w,
                                                const float* __restrict__ b){
    long t = blockIdx.x;
    int tid = threadIdx.x;
    int j = tid * 4;
    __shared__ float sh[8];
    float4 hv = *(const float4*)(h + t * DD + j);
    float4 dv = *(const float4*)(delta + t * DD + j);
    float x[4] = {hv.x + dv.x, hv.y + dv.y, hv.z + dv.z, hv.w + dv.w};
    float s = x[0] + x[1] + x[2] + x[3];
    float mean = blockSum256(s, sh) * (1.f / DD);
    float sq = 0.f;
    #pragma unroll
    for (int c = 0; c < 4; c++){ float d = x[c] - mean; sq += d * d; }
    float var = blockSum256(sq, sh) * (1.f / DD);
    float inv = rsqrtf(var + 1e-5f);
    float4 o;
    o.x = (x[0]-mean)*inv*w[j+0] + b[j+0];
    o.y = (x[1]-mean)*inv*w[j+1] + b[j+1];
    o.z = (x[2]-mean)*inv*w[j+2] + b[j+2];
    o.w = (x[3]-mean)*inv*w[j+3] + b[j+3];
    *(float4*)(h + t * DD + j) = o;
}

// ---------------- copy h -> tail of d_out ----------------
__global__ __launch_bounds__(256) void copy_h_k(float* __restrict__ dst){
    long idx = ((long)blockIdx.x * 256 + threadIdx.x) * 4;
    *(float4*)(dst + idx) = *(const float4*)(g_h + idx);
}

// ---------------- launch ----------------
extern "C" void kernel_launch(void* const* d_in, const int* in_sizes, int n_in,
                              void* d_out, int out_size)
{
    const int*   x      = (const int*)  d_in[0];
    const float* tok    = (const float*)d_in[1];
    const float* pos    = (const float*)d_in[2];
    const float* Wq     = (const float*)d_in[3];
    const float* bq     = (const float*)d_in[4];
    const float* Wk     = (const float*)d_in[5];
    const float* bk     = (const float*)d_in[6];
    const float* Wv     = (const float*)d_in[7];
    const float* bv     = (const float*)d_in[8];
    const float* Wo     = (const float*)d_in[9];
    const float* bo     = (const float*)d_in[10];
    const float* ln1w   = (const float*)d_in[11];
    const float* ln1b   = (const float*)d_in[12];
    const float* ln2w   = (const float*)d_in[13];
    const float* ln2b   = (const float*)d_in[14];
    const float* W1     = (const float*)d_in[15];
    const float* b1     = (const float*)d_in[16];
    const float* W2     = (const float*)d_in[17];
    const float* b2     = (const float*)d_in[18];
    const float* Wout   = (const float*)d_in[19];
    const float* bout   = (const float*)d_in[20];
    float* out = (float*)d_out;

    float *h, *q, *k, *v, *att, *o, *t, *ff;
    cudaGetSymbolAddress((void**)&h,   g_h);
    cudaGetSymbolAddress((void**)&q,   g_q);
    cudaGetSymbolAddress((void**)&k,   g_k);
    cudaGetSymbolAddress((void**)&v,   g_v);
    cudaGetSymbolAddress((void**)&att, g_att);
    cudaGetSymbolAddress((void**)&o,   g_o);
    cudaGetSymbolAddress((void**)&t,   g_t);
    cudaGetSymbolAddress((void**)&ff,  g_ff);

    embed_k<<<BS, 256>>>(x, tok, pos);

    for (int l = 0; l < LL; l++){
        const long wOff = (long)l * HH * DD * HD;
        // QKV: [4096,1024] x [1024,64], batched over heads -> [H][B*S][HD]
        gemm64_nn<<<dim3(1, BS/64, HH), 256>>>(h, DD, 0, Wq + wOff, HD, (long)DD*HD,
                                               bq + (long)l*HH*HD, HD,
                                               q, HD, 1, 0, (long)BS*HD, DD);
        gemm64_nn<<<dim3(1, BS/64, HH), 256>>>(h, DD, 0, Wk + wOff, HD, (long)DD*HD,
                                               bk + (long)l*HH*HD, HD,
                                               k, HD, 1, 0, (long)BS*HD, DD);
        gemm64_nn<<<dim3(1, BS/64, HH), 256>>>(h, DD, 0, Wv + wOff, HD, (long)DD*HD,
                                               bv + (long)l*HH*HD, HD,
                                               v, HD, 1, 0, (long)BS*HD, DD);
        // scores: per (h,b) batch z (z = h*B + b): Q[S,64] * K^T -> att[z][S][S]
        gemm128_nt<<<dim3(SS/128, SS/128, HH*BB), 256>>>(q, HD, (long)SS*HD,
                                                         k, HD, (long)SS*HD,
                                                         att, SS, (long)SS*SS, HD);
        softmax_k<<<HH*BB*SS, 256>>>(att);
        // AV: att[z][S][S] * V[z][S,64] -> o[b*S+s][h*64+e]
        gemm64_nn<<<dim3(1, SS/64, HH*BB), 256>>>(att, SS, (long)SS*SS,
                                                  v, HD, (long)SS*HD,
                                                  (const float*)0, 0,
                                                  o, DD, BB, (long)SS*DD, HD, SS);
        // Wo projection
        gemm128_nn<<<dim3(DD/128, BS/128, 1), 256>>>(o, DD, 0, Wo + (long)l*DD*DD, DD, 0,
                                                     bo + (long)l*DD, 0,
                                                     t, DD, 1, 0, 0, DD, 0);
        add_ln_k<<<BS, 256>>>(h, t, ln1w + (long)l*DD, ln1b + (long)l*DD);
        // FFN
        gemm128_nn<<<dim3(FFD/128, BS/128, 1), 256>>>(h, DD, 0, W1 + (long)l*DD*FFD, FFD, 0,
                                                      b1 + (long)l*FFD, 0,
                                                      ff, FFD, 1, 0, 0, DD, 1 /*gelu*/);
        gemm128_nn<<<dim3(DD/128, BS/128, 1), 256>>>(ff, FFD, 0, W2 + (long)l*FFD*DD, DD, 0,
                                                     b2 + (long)l*DD, 0,
                                                     t, DD, 1, 0, 0, FFD, 0);
        add_ln_k<<<BS, 256>>>(h, t, ln2w + (long)l*DD, ln2b + (long)l*DD);
    }

    // logits -> d_out[0 : BS*V]
    gemm128_nn<<<dim3(VV/128, BS/128, 1), 256>>>(h, DD, 0, Wout, VV, 0,
                                                 bout, 0,
                                                 out, VV, 1, 0, 0, DD, 0);
    // h -> d_out[BS*V : BS*V + BS*D]
    copy_h_k<<<(BS*DD)/1024, 256>>>(out + (long)BS*VV);
}

// round 3
// speedup vs baseline: 2.0418x; 2.0418x over previous
#include <cuda_runtime.h>
#include <cuda_bf16.h>
#include <math.h>
#include <stdint.h>

#define LL 2
#define HH 16
#define DD 1024
#define HD 64
#define FFD 4096
#define VV 32000
#define SS 1024
#define BB 4
#define BS (BB*SS)   /* 4096 */

// ================= scratch (device globals) =================================
__device__ float g_h  [(size_t)BS*DD];
__device__ float g_qkv[(size_t)BS*3*DD];       // [B*S][3072] q|k|v
__device__ float g_att[(size_t)BB*HH*SS*SS];   // [h*4+b][S][S]
__device__ float g_o  [(size_t)BS*DD];
__device__ float g_t  [(size_t)BS*DD];

__device__ __nv_bfloat16 g_hh[(size_t)BS*DD],  g_hl[(size_t)BS*DD];
__device__ __nv_bfloat16 g_oh[(size_t)BS*DD],  g_ol[(size_t)BS*DD];
__device__ __nv_bfloat16 g_ffh[(size_t)BS*FFD], g_ffl[(size_t)BS*FFD];

__device__ __nv_bfloat16 g_wqkv_h[(size_t)LL*3*DD*DD], g_wqkv_l[(size_t)LL*3*DD*DD];
__device__ __nv_bfloat16 g_wo_h [(size_t)LL*DD*DD],    g_wo_l [(size_t)LL*DD*DD];
__device__ __nv_bfloat16 g_w1_h [(size_t)LL*FFD*DD],   g_w1_l [(size_t)LL*FFD*DD];
__device__ __nv_bfloat16 g_w2_h [(size_t)LL*DD*FFD],   g_w2_l [(size_t)LL*DD*FFD];
__device__ __nv_bfloat16 g_wout_h[(size_t)VV*DD],      g_wout_l[(size_t)VV*DD];
__device__ float g_bqkv[(size_t)LL*3*DD];

// ================= small helpers ============================================
__device__ __forceinline__ uint32_t smem_to_u32(const void* smem_ptr) {
    uint32_t addr;
    asm("{ .reg .u64 tmp; cvta.to.shared.u64 tmp, %1; cvt.u32.u64 %0, tmp; }"
        : "=r"(addr) : "l"(smem_ptr));
    return addr;
}
__device__ __forceinline__ void cp16(uint32_t d, const void* s){
    asm volatile("cp.async.cg.shared.global [%0], [%1], 16;" :: "r"(d), "l"(s) : "memory");
}
__device__ __forceinline__ void ldm_x4(uint32_t* r, uint32_t addr){
    asm volatile("ldmatrix.sync.aligned.m8n8.x4.shared.b16 {%0,%1,%2,%3}, [%4];"
        : "=r"(r[0]), "=r"(r[1]), "=r"(r[2]), "=r"(r[3]) : "r"(addr));
}
__device__ __forceinline__ void mma16816(float* c, const uint32_t* a, uint32_t b0, uint32_t b1){
    asm volatile("mma.sync.aligned.m16n8k16.row.col.f32.bf16.bf16.f32 "
        "{%0,%1,%2,%3}, {%4,%5,%6,%7}, {%8,%9}, {%0,%1,%2,%3};"
        : "+f"(c[0]), "+f"(c[1]), "+f"(c[2]), "+f"(c[3])
        : "r"(a[0]), "r"(a[1]), "r"(a[2]), "r"(a[3]), "r"(b0), "r"(b1));
}
__device__ __forceinline__ float warpSum(float v){
    #pragma unroll
    for (int o = 16; o > 0; o >>= 1) v += __shfl_xor_sync(0xffffffffu, v, o);
    return v;
}
__device__ __forceinline__ float warpMax(float v){
    #pragma unroll
    for (int o = 16; o > 0; o >>= 1) v = fmaxf(v, __shfl_xor_sync(0xffffffffu, v, o));
    return v;
}
__device__ __forceinline__ float blockSum256(float v, float* sh){
    int lane = threadIdx.x & 31, wid = threadIdx.x >> 5;
    v = warpSum(v);
    if (lane == 0) sh[wid] = v;
    __syncthreads();
    float r = (threadIdx.x < 8) ? sh[threadIdx.x] : 0.f;
    if (threadIdx.x < 32) { r = warpSum(r); if (threadIdx.x == 0) sh[0] = r; }
    __syncthreads();
    float res = sh[0];
    __syncthreads();
    return res;
}
__device__ __forceinline__ float gelu_f(float x){
    return 0.5f * x * (1.0f + erff(x * 0.70710678118654752f));
}
__device__ __forceinline__ void store_split4(__nv_bfloat16* ph, __nv_bfloat16* pl,
                                             size_t idx, float4 v){
    __nv_bfloat16 h0=__float2bfloat16(v.x), h1=__float2bfloat16(v.y),
                  h2=__float2bfloat16(v.z), h3=__float2bfloat16(v.w);
    *(__nv_bfloat162*)(ph+idx)   = __halves2bfloat162(h0,h1);
    *(__nv_bfloat162*)(ph+idx+2) = __halves2bfloat162(h2,h3);
    __nv_bfloat16 l0=__float2bfloat16(v.x-__bfloat162float(h0));
    __nv_bfloat16 l1=__float2bfloat16(v.y-__bfloat162float(h1));
    __nv_bfloat16 l2=__float2bfloat16(v.z-__bfloat162float(h2));
    __nv_bfloat16 l3=__float2bfloat16(v.w-__bfloat162float(h3));
    *(__nv_bfloat162*)(pl+idx)   = __halves2bfloat162(l0,l1);
    *(__nv_bfloat162*)(pl+idx+2) = __halves2bfloat162(l2,l3);
}
__device__ __forceinline__ void store_split2(__nv_bfloat16* ph, __nv_bfloat16* pl,
                                             size_t idx, float a, float b){
    __nv_bfloat16 h0=__float2bfloat16(a), h1=__float2bfloat16(b);
    *(__nv_bfloat162*)(ph+idx) = __halves2bfloat162(h0,h1);
    __nv_bfloat16 l0=__float2bfloat16(a-__bfloat162float(h0));
    __nv_bfloat16 l1=__float2bfloat16(b-__bfloat162float(h1));
    *(__nv_bfloat162*)(pl+idx) = __halves2bfloat162(l0,l1);
}

// ================= prep kernels =============================================
__global__ __launch_bounds__(256) void packbias_k(const float* __restrict__ bq,
                                                  const float* __restrict__ bk,
                                                  const float* __restrict__ bv){
    int i = blockIdx.x*256 + threadIdx.x;            // 0..6143
    int l = i / (3*DD), n = i % (3*DD);
    float v = (n < DD) ? bq[l*DD + n] : (n < 2*DD) ? bk[l*DD + n - DD] : bv[l*DD + n - 2*DD];
    g_bqkv[i] = v;
}

// transposed split: out[n][k] = split(in_z[k][n]); in [K][ldin], out ld=K
__global__ __launch_bounds__(256) void tsplit_k(
    const float* __restrict__ in, long sInLo, int zdivIn, long sInHi,
    __nv_bfloat16* __restrict__ oh, __nv_bfloat16* __restrict__ ol,
    long sOutLo, int zdivOut, long sOutHi,
    int K, int ldin)
{
    __shared__ float t[32][33];
    int z = blockIdx.z;
    const float* I = in + (long)(z % zdivIn)*sInLo + (long)(z / zdivIn)*sInHi;
    long ob = (long)(z % zdivOut)*sOutLo + (long)(z / zdivOut)*sOutHi;
    int nx = blockIdx.x*32, ky = blockIdx.y*32;
    int tx = threadIdx.x, ty = threadIdx.y;  // (32,8)
    #pragma unroll
    for (int i = 0; i < 4; i++)
        t[ty + i*8][tx] = I[(long)(ky + ty + i*8)*ldin + nx + tx];
    __syncthreads();
    #pragma unroll
    for (int i = 0; i < 4; i++){
        int n = nx + ty + i*8, k = ky + tx;
        float v = t[tx][ty + i*8];
        __nv_bfloat16 hi = __float2bfloat16(v);
        oh[ob + (long)n*K + k] = hi;
        ol[ob + (long)n*K + k] = __float2bfloat16(v - __bfloat162float(hi));
    }
}

__global__ __launch_bounds__(256) void embed_k(const int* __restrict__ x,
                                               const float* __restrict__ tok,
                                               const float* __restrict__ pos){
    int t = blockIdx.x;
    int s = t & (SS - 1);
    int id = x[t];
    int j = threadIdx.x * 4;
    float4 a = *(const float4*)(tok + (size_t)id * DD + j);
    float4 p = *(const float4*)(pos + (size_t)s  * DD + j);
    float4 r; r.x = a.x + p.x; r.y = a.y + p.y; r.z = a.z + p.z; r.w = a.w + p.w;
    size_t idx = (size_t)t * DD + j;
    *(float4*)(g_h + idx) = r;
    store_split4(g_hh, g_hl, idx, r);
}

// ================= split-bf16 GEMM via mma.sync (HMMA) ======================
// C[M,N] = Ah*Bh^T + Ah*Bl^T + Al*Bh^T (+bias).  A:[M][K] bf16, B:[N][K] bf16.
// block tile 128x128, Kc=32, 8 warps (warp tile 32x64), cp.async double buffer.
// op0: f32 out + bias.  op1: gelu(out+bias) -> bf16 hi/lo.
#define GM_SMEM 81920
#define PADK 40            /* row stride in bf16 elems (80B), conflict-free */
#define OPSZ 10240         /* 128*PADK*2 bytes per operand tile */
__global__ __launch_bounds__(256, 1) void gemm_mma(
    const __nv_bfloat16* __restrict__ Ah, const __nv_bfloat16* __restrict__ Al,
    const __nv_bfloat16* __restrict__ Bh, const __nv_bfloat16* __restrict__ Bl,
    const float* __restrict__ bias,
    float* __restrict__ Cf,
    __nv_bfloat16* __restrict__ Chi, __nv_bfloat16* __restrict__ Clo,
    int K_, int ldc, int op)
{
    extern __shared__ char smem[];
    uint32_t sb = smem_to_u32(smem);
    int tid = threadIdx.x, lane = tid & 31, wid = tid >> 5;
    int wm = wid & 3, wn = wid >> 2;            // 4x2 warp grid
    long row0 = (long)blockIdx.x * 128;
    long col0 = (long)blockIdx.y * 128;

    float acc[2][8][4];
    #pragma unroll
    for (int i = 0; i < 2; i++)
        #pragma unroll
        for (int j = 0; j < 8; j++)
            #pragma unroll
            for (int q = 0; q < 4; q++) acc[i][j][q] = 0.f;

    auto load_chunk = [&](int c, int buf){
        long k0 = (long)c * 32;
        uint32_t base = sb + (uint32_t)buf * (4*OPSZ);
        #pragma unroll
        for (int i = tid; i < 512; i += 256){
            int r = i >> 2, seg = (i & 3) * 8;
            uint32_t soff = (uint32_t)(r * PADK + seg) * 2;
            long ga = (row0 + r) * (long)K_ + k0 + seg;
            long gb = (col0 + r) * (long)K_ + k0 + seg;
            cp16(base + soff,           Ah + ga);
            cp16(base + OPSZ   + soff,  Al + ga);
            cp16(base + 2*OPSZ + soff,  Bh + gb);
            cp16(base + 3*OPSZ + soff,  Bl + gb);
        }
        asm volatile("cp.async.commit_group;" ::: "memory");
    };

    const int NC = K_ >> 5;
    load_chunk(0, 0);

    int m_local = (lane & 7) | (lane & 8);
    int k_off = (lane >> 4) * 8;

    for (int c = 0; c < NC; ++c){
        int buf = c & 1;
        asm volatile("cp.async.wait_group 0;" ::: "memory");
        __syncthreads();
        if (c + 1 < NC) load_chunk(c + 1, buf ^ 1);

        uint32_t base = sb + (uint32_t)buf * (4*OPSZ);
        #pragma unroll
        for (int ks = 0; ks < 2; ++ks){
            uint32_t a_h[2][4], a_l[2][4];
            #pragma unroll
            for (int am = 0; am < 2; ++am){
                uint32_t roff = (uint32_t)((wm*32 + am*16 + m_local) * PADK + ks*16 + k_off) * 2;
                ldm_x4(a_h[am], base + roff);
                ldm_x4(a_l[am], base + OPSZ + roff);
            }
            uint32_t b_h[4][4], b_l[4][4];
            #pragma unroll
            for (int nt2 = 0; nt2 < 4; ++nt2){
                uint32_t roff = (uint32_t)((wn*64 + nt2*16 + m_local) * PADK + ks*16 + k_off) * 2;
                ldm_x4(b_h[nt2], base + 2*OPSZ + roff);
                ldm_x4(b_l[nt2], base + 3*OPSZ + roff);
            }
            #pragma unroll
            for (int mt = 0; mt < 2; ++mt)
                #pragma unroll
                for (int nt = 0; nt < 8; ++nt){
                    int q = nt >> 1, rs = nt & 1;
                    uint32_t bh0 = b_h[q][rs], bh1 = b_h[q][rs+2];
                    uint32_t bl0 = b_l[q][rs], bl1 = b_l[q][rs+2];
                    mma16816(acc[mt][nt], a_h[mt], bh0, bh1);
                    mma16816(acc[mt][nt], a_h[mt], bl0, bl1);
                    mma16816(acc[mt][nt], a_l[mt], bh0, bh1);
                }
        }
    }

    // epilogue
    #pragma unroll
    for (int mt = 0; mt < 2; ++mt){
        #pragma unroll
        for (int nt = 0; nt < 8; ++nt){
            long row = row0 + wm*32 + mt*16 + (lane >> 2);
            long col = col0 + wn*64 + nt*8 + (lane & 3)*2;
            float b0 = bias[col], b1 = bias[col+1];
            float v0 = acc[mt][nt][0] + b0, v1 = acc[mt][nt][1] + b1;
            float v2 = acc[mt][nt][2] + b0, v3 = acc[mt][nt][3] + b1;
            if (op == 0){
                *(float2*)(Cf + row*(long)ldc + col)     = make_float2(v0, v1);
                *(float2*)(Cf + (row+8)*(long)ldc + col) = make_float2(v2, v3);
            } else {
                store_split2(Chi, Clo, (size_t)(row*(long)ldc + col),     gelu_f(v0), gelu_f(v1));
                store_split2(Chi, Clo, (size_t)((row+8)*(long)ldc + col), gelu_f(v2), gelu_f(v3));
            }
        }
    }
}

// ================= attention (fp32) =========================================
__global__ __launch_bounds__(256, 2) void scores_k(const float* __restrict__ qkv,
                                                   float* __restrict__ att){
    int z = blockIdx.z; int b = z & 3, hh = z >> 2;
    const float* A  = qkv + (long)b*SS*(3*DD) + hh*HD;         // q
    const float* Bm = A + DD;                                  // k
    float* C = att + (long)z*SS*SS;
    const int lda = 3*DD, ldb = 3*DD, ldc = SS, K = HD;

    __shared__ __align__(16) float As[8][128];
    __shared__ __align__(16) float Bs[8][128];
    int tid = threadIdx.x;
    long row0 = (long)blockIdx.y * 128;
    int  col0 = blockIdx.x * 128;
    int tx = tid & 15, ty = tid >> 4;
    int trow = ty * 8, tcol = tx * 8;
    float acc[8][8];
    #pragma unroll
    for (int i = 0; i < 8; i++)
        #pragma unroll
        for (int j = 0; j < 8; j++) acc[i][j] = 0.f;

    int a_r = tid >> 1, a_c = (tid & 1) * 4;
    int b_n = tid >> 1, b_k = (tid & 1) * 4;
    const float* Aptr = A  + (row0 + a_r) * (long)lda + a_c;
    const float* Bptr = Bm + (long)(col0 + b_n) * ldb + b_k;

    for (int k0 = 0; k0 < K; k0 += 8){
        float4 av = *(const float4*)(Aptr + k0);
        float4 bv = *(const float4*)(Bptr + k0);
        As[a_c+0][a_r] = av.x; As[a_c+1][a_r] = av.y;
        As[a_c+2][a_r] = av.z; As[a_c+3][a_r] = av.w;
        Bs[b_k+0][b_n] = bv.x; Bs[b_k+1][b_n] = bv.y;
        Bs[b_k+2][b_n] = bv.z; Bs[b_k+3][b_n] = bv.w;
        __syncthreads();
        #pragma unroll
        for (int kk = 0; kk < 8; kk++){
            float ra[8], rb[8];
            #pragma unroll
            for (int i = 0; i < 8; i++) ra[i] = As[kk][trow + i];
            #pragma unroll
            for (int j = 0; j < 8; j++) rb[j] = Bs[kk][tcol + j];
            #pragma unroll
            for (int i = 0; i < 8; i++)
                #pragma unroll
                for (int j = 0; j < 8; j++) acc[i][j] += ra[i] * rb[j];
        }
        __syncthreads();
    }
    #pragma unroll
    for (int i = 0; i < 8; i++){
        long r = row0 + trow + i;
        #pragma unroll
        for (int j = 0; j < 8; j += 4){
            int c = col0 + tcol + j;
            float4 o;
            o.x = acc[i][j+0]; o.y = acc[i][j+1]; o.z = acc[i][j+2]; o.w = acc[i][j+3];
            *(float4*)(C + r * (long)ldc + c) = o;
        }
    }
}

__global__ __launch_bounds__(256) void softmax_k(float* __restrict__ att){
    long rid = blockIdx.x;
    int i = (int)(rid & (SS - 1));
    float* row = att + rid * (long)SS;
    int tid = threadIdx.x;
    __shared__ float shm[8];
    __shared__ float shs[8];

    float4 v4 = *(const float4*)(row + tid * 4);
    float v[4] = {v4.x, v4.y, v4.z, v4.w};
    float m = -1e30f;
    #pragma unroll
    for (int c = 0; c < 4; c++){
        int j = tid * 4 + c;
        v[c] = (j <= i) ? v[c] * 0.125f : -1e30f;
        m = fmaxf(m, v[c]);
    }
    int lane = tid & 31, wid = tid >> 5;
    float wm = warpMax(m);
    if (lane == 0) shm[wid] = wm;
    __syncthreads();
    if (tid < 32){
        float r = (tid < 8) ? shm[tid] : -1e30f;
        r = warpMax(r);
        if (tid == 0) shm[0] = r;
    }
    __syncthreads();
    m = shm[0];
    float s = 0.f;
    #pragma unroll
    for (int c = 0; c < 4; c++){ v[c] = expf(v[c] - m); s += v[c]; }
    float bs = blockSum256(s, shs);
    float inv = 1.f / bs;
    float4 o; o.x = v[0]*inv; o.y = v[1]*inv; o.z = v[2]*inv; o.w = v[3]*inv;
    *(float4*)(row + tid * 4) = o;
}

__global__ __launch_bounds__(256) void av_k(const float* __restrict__ att,
                                            const float* __restrict__ qkv,
                                            float* __restrict__ o){
    int z = blockIdx.z; int b = z & 3, hh = z >> 2;
    const float* A  = att + (long)z*SS*SS;
    const float* Bm = qkv + (long)b*SS*(3*DD) + 2*DD + hh*HD;
    float* C = o + (long)b*SS*DD + hh*HD;
    const int lda = SS, ldb = 3*DD, ldc = DD, K = SS;

    __shared__ __align__(16) float As[16][64];
    __shared__ __align__(16) float Bs[16][64];
    int tid = threadIdx.x;
    long row0 = (long)blockIdx.y * 64;
    int tx = tid & 15, ty = tid >> 4;
    int trow = ty * 4, tcol = tx * 4;
    float acc[4][4];
    #pragma unroll
    for (int i = 0; i < 4; i++)
        #pragma unroll
        for (int j = 0; j < 4; j++) acc[i][j] = 0.f;

    int a_r = tid >> 2, a_c = (tid & 3) * 4;
    int b_r = tid >> 4, b_c = (tid & 15) * 4;
    const float* Aptr = A  + (row0 + a_r) * (long)lda + a_c;
    const float* Bptr = Bm + (long)b_r * ldb + b_c;

    for (int k0 = 0; k0 < K; k0 += 16){
        float4 av = *(const float4*)(Aptr + k0);
        float4 bv = *(const float4*)(Bptr + (long)k0 * ldb);
        As[a_c+0][a_r] = av.x; As[a_c+1][a_r] = av.y;
        As[a_c+2][a_r] = av.z; As[a_c+3][a_r] = av.w;
        *(float4*)&Bs[b_r][b_c] = bv;
        __syncthreads();
        #pragma unroll
        for (int kk = 0; kk < 16; kk++){
            float4 ra = *(const float4*)&As[kk][trow];
            float4 rb = *(const float4*)&Bs[kk][tcol];
            float a0[4] = {ra.x, ra.y, ra.z, ra.w};
            float b0[4] = {rb.x, rb.y, rb.z, rb.w};
            #pragma unroll
            for (int i = 0; i < 4; i++)
                #pragma unroll
                for (int j = 0; j < 4; j++) acc[i][j] += a0[i] * b0[j];
        }
        __syncthreads();
    }
    #pragma unroll
    for (int i = 0; i < 4; i++){
        long r = row0 + trow + i;
        float4 ov;
        ov.x = acc[i][0]; ov.y = acc[i][1]; ov.z = acc[i][2]; ov.w = acc[i][3];
        *(float4*)(C + r * (long)ldc + tcol) = ov;
    }
}

// ================= pointwise ================================================
__global__ __launch_bounds__(256) void split_k(const float* __restrict__ in,
                                               __nv_bfloat16* __restrict__ oh,
                                               __nv_bfloat16* __restrict__ ol){
    size_t i = ((size_t)blockIdx.x*256 + threadIdx.x)*4;
    float4 v = *(const float4*)(in + i);
    store_split4(oh, ol, i, v);
}

__global__ __launch_bounds__(256) void add_ln_k(float* __restrict__ h,
                                                const float* __restrict__ delta,
                                                const float* __restrict__ w,
                                                const float* __restrict__ b){
    long t = blockIdx.x;
    int tid = threadIdx.x;
    int j = tid * 4;
    __shared__ float sh[8];
    float4 hv = *(const float4*)(h + t * DD + j);
    float4 dv = *(const float4*)(delta + t * DD + j);
    float x[4] = {hv.x + dv.x, hv.y + dv.y, hv.z + dv.z, hv.w + dv.w};
    float s = x[0] + x[1] + x[2] + x[3];
    float mean = blockSum256(s, sh) * (1.f / DD);
    float sq = 0.f;
    #pragma unroll
    for (int c = 0; c < 4; c++){ float d = x[c] - mean; sq += d * d; }
    float var = blockSum256(sq, sh) * (1.f / DD);
    float inv = rsqrtf(var + 1e-5f);
    float4 o;
    o.x = (x[0]-mean)*inv*w[j+0] + b[j+0];
    o.y = (x[1]-mean)*inv*w[j+1] + b[j+1];
    o.z = (x[2]-mean)*inv*w[j+2] + b[j+2];
    o.w = (x[3]-mean)*inv*w[j+3] + b[j+3];
    size_t idx = (size_t)t * DD + j;
    *(float4*)(h + idx) = o;
    store_split4(g_hh, g_hl, idx, o);
}

__global__ __launch_bounds__(256) void copy_h_k(float* __restrict__ dst){
    size_t idx = ((size_t)blockIdx.x * 256 + threadIdx.x) * 4;
    *(float4*)(dst + idx) = *(const float4*)(g_h + idx);
}

// ================= launch ===================================================
extern "C" void kernel_launch(void* const* d_in, const int* in_sizes, int n_in,
                              void* d_out, int out_size)
{
    const int*   x    = (const int*)  d_in[0];
    const float* tok  = (const float*)d_in[1];
    const float* pos  = (const float*)d_in[2];
    const float* Wq   = (const float*)d_in[3];
    const float* bq   = (const float*)d_in[4];
    const float* Wk   = (const float*)d_in[5];
    const float* bk   = (const float*)d_in[6];
    const float* Wv   = (const float*)d_in[7];
    const float* bv   = (const float*)d_in[8];
    const float* Wo   = (const float*)d_in[9];
    const float* bo   = (const float*)d_in[10];
    const float* ln1w = (const float*)d_in[11];
    const float* ln1b = (const float*)d_in[12];
    const float* ln2w = (const float*)d_in[13];
    const float* ln2b = (const float*)d_in[14];
    const float* W1   = (const float*)d_in[15];
    const float* b1   = (const float*)d_in[16];
    const float* W2   = (const float*)d_in[17];
    const float* b2   = (const float*)d_in[18];
    const float* Wout = (const float*)d_in[19];
    const float* bout = (const float*)d_in[20];
    float* out = (float*)d_out;

    static int attr_set = 0;
    if (!attr_set){
        cudaFuncSetAttribute(gemm_mma, cudaFuncAttributeMaxDynamicSharedMemorySize, GM_SMEM);
        attr_set = 1;
    }

    float *h, *qkv, *att, *o, *t, *bqkv;
    __nv_bfloat16 *hh,*hl,*oh,*ol,*ffh,*ffl;
    __nv_bfloat16 *wqh,*wql,*woh,*wol,*w1h,*w1l,*w2h,*w2l,*wouth,*woutl;
    cudaGetSymbolAddress((void**)&h,   g_h);
    cudaGetSymbolAddress((void**)&qkv, g_qkv);
    cudaGetSymbolAddress((void**)&att, g_att);
    cudaGetSymbolAddress((void**)&o,   g_o);
    cudaGetSymbolAddress((void**)&t,   g_t);
    cudaGetSymbolAddress((void**)&bqkv,g_bqkv);
    cudaGetSymbolAddress((void**)&hh,  g_hh);
    cudaGetSymbolAddress((void**)&hl,  g_hl);
    cudaGetSymbolAddress((void**)&oh,  g_oh);
    cudaGetSymbolAddress((void**)&ol,  g_ol);
    cudaGetSymbolAddress((void**)&ffh, g_ffh);
    cudaGetSymbolAddress((void**)&ffl, g_ffl);
    cudaGetSymbolAddress((void**)&wqh, g_wqkv_h);
    cudaGetSymbolAddress((void**)&wql, g_wqkv_l);
    cudaGetSymbolAddress((void**)&woh, g_wo_h);
    cudaGetSymbolAddress((void**)&wol, g_wo_l);
    cudaGetSymbolAddress((void**)&w1h, g_w1_h);
    cudaGetSymbolAddress((void**)&w1l, g_w1_l);
    cudaGetSymbolAddress((void**)&w2h, g_w2_h);
    cudaGetSymbolAddress((void**)&w2l, g_w2_l);
    cudaGetSymbolAddress((void**)&wouth, g_wout_h);
    cudaGetSymbolAddress((void**)&woutl, g_wout_l);

    dim3 tsb(32, 8);
    // --- weight prep: transpose + bf16 split ---
    packbias_k<<<24, 256>>>(bq, bk, bv);
    tsplit_k<<<dim3(2,32,32), tsb>>>(Wq, (long)DD*HD, 32, 0,
        wqh + 0*DD*DD, wql + 0*DD*DD, (long)HD*DD, 16, (long)3*DD*DD, DD, HD);
    tsplit_k<<<dim3(2,32,32), tsb>>>(Wk, (long)DD*HD, 32, 0,
        wqh + 1*DD*DD, wql + 1*DD*DD, (long)HD*DD, 16, (long)3*DD*DD, DD, HD);
    tsplit_k<<<dim3(2,32,32), tsb>>>(Wv, (long)DD*HD, 32, 0,
        wqh + 2*DD*DD, wql + 2*DD*DD, (long)HD*DD, 16, (long)3*DD*DD, DD, HD);
    tsplit_k<<<dim3(32,32,2), tsb>>>(Wo, (long)DD*DD, 2, 0,
        woh, wol, (long)DD*DD, 2, 0, DD, DD);
    tsplit_k<<<dim3(128,32,2), tsb>>>(W1, (long)DD*FFD, 2, 0,
        w1h, w1l, (long)FFD*DD, 2, 0, DD, FFD);
    tsplit_k<<<dim3(32,128,2), tsb>>>(W2, (long)FFD*DD, 2, 0,
        w2h, w2l, (long)DD*FFD, 2, 0, FFD, DD);
    tsplit_k<<<dim3(1000,32,1), tsb>>>(Wout, 0, 1, 0,
        wouth, woutl, 0, 1, 0, DD, VV);

    embed_k<<<BS, 256>>>(x, tok, pos);

    for (int l = 0; l < LL; l++){
        // QKV: [4096,1024] x [1024,3072] -> g_qkv (f32)
        gemm_mma<<<dim3(BS/128, 3*DD/128), 256, GM_SMEM>>>(
            hh, hl, wqh + (long)l*3*DD*DD, wql + (long)l*3*DD*DD,
            bqkv + (long)l*3*DD, qkv, 0, 0, DD, 3*DD, 0);
        scores_k<<<dim3(SS/128, SS/128, HH*BB), 256>>>(qkv, att);
        softmax_k<<<HH*BB*SS, 256>>>(att);
        av_k<<<dim3(1, SS/64, HH*BB), 256>>>(att, qkv, o);
        split_k<<<(BS*DD)/1024, 256>>>(o, oh, ol);
        // Wo
        gemm_mma<<<dim3(BS/128, DD/128), 256, GM_SMEM>>>(
            oh, ol, woh + (long)l*DD*DD, wol + (long)l*DD*DD,
            bo + (long)l*DD, t, 0, 0, DD, DD, 0);
        add_ln_k<<<BS, 256>>>(h, t, ln1w + (long)l*DD, ln1b + (long)l*DD);
        // W1 + GELU -> ff (bf16 hi/lo)
        gemm_mma<<<dim3(BS/128, FFD/128), 256, GM_SMEM>>>(
            hh, hl, w1h + (long)l*FFD*DD, w1l + (long)l*FFD*DD,
            b1 + (long)l*FFD, 0, ffh, ffl, DD, FFD, 1);
        // W2
        gemm_mma<<<dim3(BS/128, DD/128), 256, GM_SMEM>>>(
            ffh, ffl, w2h + (long)l*DD*FFD, w2l + (long)l*DD*FFD,
            b2 + (long)l*DD, t, 0, 0, FFD, DD, 0);
        add_ln_k<<<BS, 256>>>(h, t, ln2w + (long)l*DD, ln2b + (long)l*DD);
    }

    // logits
    gemm_mma<<<dim3(BS/128, VV/128), 256, GM_SMEM>>>(
        hh, hl, wouth, woutl, bout, out, 0, 0, DD, VV, 0);
    copy_h_k<<<(BS*DD)/1024, 256>>>(out + (long)BS*VV);
}

// round 4
// speedup vs baseline: 3.0283x; 1.4832x over previous
#include <cuda_runtime.h>
#include <cuda_fp16.h>
#include <math.h>
#include <stdint.h>

#define LL 2
#define HH 16
#define DD 1024
#define HD 64
#define FFD 4096
#define VV 32000
#define SS 1024
#define BB 4
#define BS (BB*SS)   /* 4096 */

// ================= scratch (device globals) =================================
__device__ float g_h  [(size_t)BS*DD];
__device__ float g_qkv[(size_t)BS*3*DD];       // [B*S][3072] q|k|v
__device__ float g_att[(size_t)BB*HH*SS*SS];   // [h*4+b][S][S]
__device__ float g_o  [(size_t)BS*DD];
__device__ float g_t  [(size_t)BS*DD];

__device__ __half g_hh[(size_t)BS*DD],  g_hl[(size_t)BS*DD];
__device__ __half g_oh[(size_t)BS*DD],  g_ol[(size_t)BS*DD];
__device__ __half g_ffh[(size_t)BS*FFD], g_ffl[(size_t)BS*FFD];

__device__ __half g_wqkv_h[(size_t)LL*3*DD*DD];
__device__ __half g_wo_h [(size_t)LL*DD*DD];
__device__ __half g_w1_h [(size_t)LL*FFD*DD];
__device__ __half g_w2_h [(size_t)LL*DD*FFD];
__device__ __half g_wout_h[(size_t)VV*DD];
__device__ float g_bqkv[(size_t)LL*3*DD];

// ================= small helpers ============================================
__device__ __forceinline__ uint32_t smem_to_u32(const void* smem_ptr) {
    uint32_t addr;
    asm("{ .reg .u64 tmp; cvta.to.shared.u64 tmp, %1; cvt.u32.u64 %0, tmp; }"
        : "=r"(addr) : "l"(smem_ptr));
    return addr;
}
__device__ __forceinline__ void cp16(uint32_t d, const void* s){
    asm volatile("cp.async.cg.shared.global [%0], [%1], 16;" :: "r"(d), "l"(s) : "memory");
}
__device__ __forceinline__ void ldm_x4(uint32_t* r, uint32_t addr){
    asm volatile("ldmatrix.sync.aligned.m8n8.x4.shared.b16 {%0,%1,%2,%3}, [%4];"
        : "=r"(r[0]), "=r"(r[1]), "=r"(r[2]), "=r"(r[3]) : "r"(addr));
}
__device__ __forceinline__ void mma16816(float* c, const uint32_t* a, uint32_t b0, uint32_t b1){
    asm volatile("mma.sync.aligned.m16n8k16.row.col.f32.f16.f16.f32 "
        "{%0,%1,%2,%3}, {%4,%5,%6,%7}, {%8,%9}, {%0,%1,%2,%3};"
        : "+f"(c[0]), "+f"(c[1]), "+f"(c[2]), "+f"(c[3])
        : "r"(a[0]), "r"(a[1]), "r"(a[2]), "r"(a[3]), "r"(b0), "r"(b1));
}
__device__ __forceinline__ float warpSum(float v){
    #pragma unroll
    for (int o = 16; o > 0; o >>= 1) v += __shfl_xor_sync(0xffffffffu, v, o);
    return v;
}
__device__ __forceinline__ float warpMax(float v){
    #pragma unroll
    for (int o = 16; o > 0; o >>= 1) v = fmaxf(v, __shfl_xor_sync(0xffffffffu, v, o));
    return v;
}
__device__ __forceinline__ float blockSum256(float v, float* sh){
    int lane = threadIdx.x & 31, wid = threadIdx.x >> 5;
    v = warpSum(v);
    if (lane == 0) sh[wid] = v;
    __syncthreads();
    float r = (threadIdx.x < 8) ? sh[threadIdx.x] : 0.f;
    if (threadIdx.x < 32) { r = warpSum(r); if (threadIdx.x == 0) sh[0] = r; }
    __syncthreads();
    float res = sh[0];
    __syncthreads();
    return res;
}
__device__ __forceinline__ float gelu_f(float x){
    return 0.5f * x * (1.0f + erff(x * 0.70710678118654752f));
}
__device__ __forceinline__ void store_split4(__half* ph, __half* pl,
                                             size_t idx, float4 v){
    __half h0=__float2half_rn(v.x), h1=__float2half_rn(v.y),
           h2=__float2half_rn(v.z), h3=__float2half_rn(v.w);
    *(__half2*)(ph+idx)   = __halves2half2(h0,h1);
    *(__half2*)(ph+idx+2) = __halves2half2(h2,h3);
    __half l0=__float2half_rn(v.x-__half2float(h0));
    __half l1=__float2half_rn(v.y-__half2float(h1));
    __half l2=__float2half_rn(v.z-__half2float(h2));
    __half l3=__float2half_rn(v.w-__half2float(h3));
    *(__half2*)(pl+idx)   = __halves2half2(l0,l1);
    *(__half2*)(pl+idx+2) = __halves2half2(l2,l3);
}
__device__ __forceinline__ void store_split2(__half* ph, __half* pl,
                                             size_t idx, float a, float b){
    __half h0=__float2half_rn(a), h1=__float2half_rn(b);
    *(__half2*)(ph+idx) = __halves2half2(h0,h1);
    __half l0=__float2half_rn(a-__half2float(h0));
    __half l1=__float2half_rn(b-__half2float(h1));
    *(__half2*)(pl+idx) = __halves2half2(l0,l1);
}

// ================= prep kernels =============================================
__global__ __launch_bounds__(256) void packbias_k(const float* __restrict__ bq,
                                                  const float* __restrict__ bk,
                                                  const float* __restrict__ bv){
    int i = blockIdx.x*256 + threadIdx.x;            // 0..6143
    int l = i / (3*DD), n = i % (3*DD);
    float v = (n < DD) ? bq[l*DD + n] : (n < 2*DD) ? bk[l*DD + n - DD] : bv[l*DD + n - 2*DD];
    g_bqkv[i] = v;
}

// transposed fp16 cast: out[n][k] = fp16(in_z[k][n]); in [K][ldin], out ld=K
__global__ __launch_bounds__(256) void tsplit_k(
    const float* __restrict__ in, long sInLo, int zdivIn, long sInHi,
    __half* __restrict__ oh,
    long sOutLo, int zdivOut, long sOutHi,
    int K, int ldin)
{
    __shared__ float t[32][33];
    int z = blockIdx.z;
    const float* I = in + (long)(z % zdivIn)*sInLo + (long)(z / zdivIn)*sInHi;
    long ob = (long)(z % zdivOut)*sOutLo + (long)(z / zdivOut)*sOutHi;
    int nx = blockIdx.x*32, ky = blockIdx.y*32;
    int tx = threadIdx.x, ty = threadIdx.y;  // (32,8)
    #pragma unroll
    for (int i = 0; i < 4; i++)
        t[ty + i*8][tx] = I[(long)(ky + ty + i*8)*ldin + nx + tx];
    __syncthreads();
    #pragma unroll
    for (int i = 0; i < 4; i++){
        int n = nx + ty + i*8, k = ky + tx;
        oh[ob + (long)n*K + k] = __float2half_rn(t[tx][ty + i*8]);
    }
}

__global__ __launch_bounds__(256) void embed_k(const int* __restrict__ x,
                                               const float* __restrict__ tok,
                                               const float* __restrict__ pos){
    int t = blockIdx.x;
    int s = t & (SS - 1);
    int id = x[t];
    int j = threadIdx.x * 4;
    float4 a = *(const float4*)(tok + (size_t)id * DD + j);
    float4 p = *(const float4*)(pos + (size_t)s  * DD + j);
    float4 r; r.x = a.x + p.x; r.y = a.y + p.y; r.z = a.z + p.z; r.w = a.w + p.w;
    size_t idx = (size_t)t * DD + j;
    *(float4*)(g_h + idx) = r;
    store_split4(g_hh, g_hl, idx, r);
}

// ================= split-fp16 GEMM via mma.sync (HMMA) ======================
// C[M,N] = Ah*Bh^T + Al*Bh^T (+bias).  A hi/lo fp16 [M][K], B fp16 [N][K].
// block tile 128x128, Kc=32, 8 warps (warp tile 32x64), cp.async double buffer.
// op0: f32 out + bias.  op1: gelu(out+bias) -> fp16 hi/lo.
#define PADK 40            /* row stride in fp16 elems (80B), conflict-free */
#define OPSZ 10240         /* 128*PADK*2 bytes per operand tile */
#define GM_SMEM (2*3*OPSZ) /* 61440 */
__global__ __launch_bounds__(256, 1) void gemm_mma(
    const __half* __restrict__ Ah, const __half* __restrict__ Al,
    const __half* __restrict__ Bh,
    const float* __restrict__ bias,
    float* __restrict__ Cf,
    __half* __restrict__ Chi, __half* __restrict__ Clo,
    int K_, int ldc, int op)
{
    extern __shared__ char smem[];
    uint32_t sb = smem_to_u32(smem);
    int tid = threadIdx.x, lane = tid & 31, wid = tid >> 5;
    int wm = wid & 3, wn = wid >> 2;            // 4x2 warp grid
    long row0 = (long)blockIdx.x * 128;
    long col0 = (long)blockIdx.y * 128;

    float acc[2][8][4];
    #pragma unroll
    for (int i = 0; i < 2; i++)
        #pragma unroll
        for (int j = 0; j < 8; j++)
            #pragma unroll
            for (int q = 0; q < 4; q++) acc[i][j][q] = 0.f;

    auto load_chunk = [&](int c, int buf){
        long k0 = (long)c * 32;
        uint32_t base = sb + (uint32_t)buf * (3*OPSZ);
        #pragma unroll
        for (int i = tid; i < 512; i += 256){
            int r = i >> 2, seg = (i & 3) * 8;
            uint32_t soff = (uint32_t)(r * PADK + seg) * 2;
            long ga = (row0 + r) * (long)K_ + k0 + seg;
            long gb = (col0 + r) * (long)K_ + k0 + seg;
            cp16(base + soff,           Ah + ga);
            cp16(base + OPSZ   + soff,  Al + ga);
            cp16(base + 2*OPSZ + soff,  Bh + gb);
        }
        asm volatile("cp.async.commit_group;" ::: "memory");
    };

    const int NC = K_ >> 5;
    load_chunk(0, 0);

    int m_local = (lane & 7) | (lane & 8);
    int k_off = (lane >> 4) * 8;

    for (int c = 0; c < NC; ++c){
        int buf = c & 1;
        asm volatile("cp.async.wait_group 0;" ::: "memory");
        __syncthreads();
        if (c + 1 < NC) load_chunk(c + 1, buf ^ 1);

        uint32_t base = sb + (uint32_t)buf * (3*OPSZ);
        #pragma unroll
        for (int ks = 0; ks < 2; ++ks){
            uint32_t a_h[2][4], a_l[2][4];
            #pragma unroll
            for (int am = 0; am < 2; ++am){
                uint32_t roff = (uint32_t)((wm*32 + am*16 + m_local) * PADK + ks*16 + k_off) * 2;
                ldm_x4(a_h[am], base + roff);
                ldm_x4(a_l[am], base + OPSZ + roff);
            }
            uint32_t b_h[4][4];
            #pragma unroll
            for (int nt2 = 0; nt2 < 4; ++nt2){
                uint32_t roff = (uint32_t)((wn*64 + nt2*16 + m_local) * PADK + ks*16 + k_off) * 2;
                ldm_x4(b_h[nt2], base + 2*OPSZ + roff);
            }
            #pragma unroll
            for (int mt = 0; mt < 2; ++mt)
                #pragma unroll
                for (int nt = 0; nt < 8; ++nt){
                    int q = nt >> 1, rs = nt & 1;
                    uint32_t bh0 = b_h[q][rs], bh1 = b_h[q][rs+2];
                    mma16816(acc[mt][nt], a_h[mt], bh0, bh1);
                    mma16816(acc[mt][nt], a_l[mt], bh0, bh1);
                }
        }
    }

    // epilogue
    #pragma unroll
    for (int mt = 0; mt < 2; ++mt){
        #pragma unroll
        for (int nt = 0; nt < 8; ++nt){
            long row = row0 + wm*32 + mt*16 + (lane >> 2);
            long col = col0 + wn*64 + nt*8 + (lane & 3)*2;
            float b0 = bias[col], b1 = bias[col+1];
            float v0 = acc[mt][nt][0] + b0, v1 = acc[mt][nt][1] + b1;
            float v2 = acc[mt][nt][2] + b0, v3 = acc[mt][nt][3] + b1;
            if (op == 0){
                *(float2*)(Cf + row*(long)ldc + col)     = make_float2(v0, v1);
                *(float2*)(Cf + (row+8)*(long)ldc + col) = make_float2(v2, v3);
            } else {
                store_split2(Chi, Clo, (size_t)(row*(long)ldc + col),     gelu_f(v0), gelu_f(v1));
                store_split2(Chi, Clo, (size_t)((row+8)*(long)ldc + col), gelu_f(v2), gelu_f(v3));
            }
        }
    }
}

// ================= attention (fp32) =========================================
__global__ __launch_bounds__(256, 2) void scores_k(const float* __restrict__ qkv,
                                                   float* __restrict__ att){
    int z = blockIdx.z; int b = z & 3, hh = z >> 2;
    const float* A  = qkv + (long)b*SS*(3*DD) + hh*HD;         // q
    const float* Bm = A + DD;                                  // k
    float* C = att + (long)z*SS*SS;
    const int lda = 3*DD, ldb = 3*DD, ldc = SS, K = HD;

    __shared__ __align__(16) float As[8][128];
    __shared__ __align__(16) float Bs[8][128];
    int tid = threadIdx.x;
    long row0 = (long)blockIdx.y * 128;
    int  col0 = blockIdx.x * 128;
    int tx = tid & 15, ty = tid >> 4;
    int trow = ty * 8, tcol = tx * 8;
    float acc[8][8];
    #pragma unroll
    for (int i = 0; i < 8; i++)
        #pragma unroll
        for (int j = 0; j < 8; j++) acc[i][j] = 0.f;

    int a_r = tid >> 1, a_c = (tid & 1) * 4;
    int b_n = tid >> 1, b_k = (tid & 1) * 4;
    const float* Aptr = A  + (row0 + a_r) * (long)lda + a_c;
    const float* Bptr = Bm + (long)(col0 + b_n) * ldb + b_k;

    for (int k0 = 0; k0 < K; k0 += 8){
        float4 av = *(const float4*)(Aptr + k0);
        float4 bv = *(const float4*)(Bptr + k0);
        As[a_c+0][a_r] = av.x; As[a_c+1][a_r] = av.y;
        As[a_c+2][a_r] = av.z; As[a_c+3][a_r] = av.w;
        Bs[b_k+0][b_n] = bv.x; Bs[b_k+1][b_n] = bv.y;
        Bs[b_k+2][b_n] = bv.z; Bs[b_k+3][b_n] = bv.w;
        __syncthreads();
        #pragma unroll
        for (int kk = 0; kk < 8; kk++){
            float ra[8], rb[8];
            #pragma unroll
            for (int i = 0; i < 8; i++) ra[i] = As[kk][trow + i];
            #pragma unroll
            for (int j = 0; j < 8; j++) rb[j] = Bs[kk][tcol + j];
            #pragma unroll
            for (int i = 0; i < 8; i++)
                #pragma unroll
                for (int j = 0; j < 8; j++) acc[i][j] += ra[i] * rb[j];
        }
        __syncthreads();
    }
    #pragma unroll
    for (int i = 0; i < 8; i++){
        long r = row0 + trow + i;
        #pragma unroll
        for (int j = 0; j < 8; j += 4){
            int c = col0 + tcol + j;
            float4 o;
            o.x = acc[i][j+0]; o.y = acc[i][j+1]; o.z = acc[i][j+2]; o.w = acc[i][j+3];
            *(float4*)(C + r * (long)ldc + c) = o;
        }
    }
}

__global__ __launch_bounds__(256) void softmax_k(float* __restrict__ att){
    long rid = blockIdx.x;
    int i = (int)(rid & (SS - 1));
    float* row = att + rid * (long)SS;
    int tid = threadIdx.x;
    __shared__ float shm[8];
    __shared__ float shs[8];

    float4 v4 = *(const float4*)(row + tid * 4);
    float v[4] = {v4.x, v4.y, v4.z, v4.w};
    float m = -1e30f;
    #pragma unroll
    for (int c = 0; c < 4; c++){
        int j = tid * 4 + c;
        v[c] = (j <= i) ? v[c] * 0.125f : -1e30f;
        m = fmaxf(m, v[c]);
    }
    int lane = tid & 31, wid = tid >> 5;
    float wm = warpMax(m);
    if (lane == 0) shm[wid] = wm;
    __syncthreads();
    if (tid < 32){
        float r = (tid < 8) ? shm[tid] : -1e30f;
        r = warpMax(r);
        if (tid == 0) shm[0] = r;
    }
    __syncthreads();
    m = shm[0];
    float s = 0.f;
    #pragma unroll
    for (int c = 0; c < 4; c++){ v[c] = expf(v[c] - m); s += v[c]; }
    float bs = blockSum256(s, shs);
    float inv = 1.f / bs;
    float4 o; o.x = v[0]*inv; o.y = v[1]*inv; o.z = v[2]*inv; o.w = v[3]*inv;
    *(float4*)(row + tid * 4) = o;
}

__global__ __launch_bounds__(256) void av_k(const float* __restrict__ att,
                                            const float* __restrict__ qkv,
                                            float* __restrict__ o){
    int z = blockIdx.z; int b = z & 3, hh = z >> 2;
    const float* A  = att + (long)z*SS*SS;
    const float* Bm = qkv + (long)b*SS*(3*DD) + 2*DD + hh*HD;
    float* C = o + (long)b*SS*DD + hh*HD;
    const int lda = SS, ldb = 3*DD, ldc = DD, K = SS;

    __shared__ __align__(16) float As[16][64];
    __shared__ __align__(16) float Bs[16][64];
    int tid = threadIdx.x;
    long row0 = (long)blockIdx.y * 64;
    int tx = tid & 15, ty = tid >> 4;
    int trow = ty * 4, tcol = tx * 4;
    float acc[4][4];
    #pragma unroll
    for (int i = 0; i < 4; i++)
        #pragma unroll
        for (int j = 0; j < 4; j++) acc[i][j] = 0.f;

    int a_r = tid >> 2, a_c = (tid & 3) * 4;
    int b_r = tid >> 4, b_c = (tid & 15) * 4;
    const float* Aptr = A  + (row0 + a_r) * (long)lda + a_c;
    const float* Bptr = Bm + (long)b_r * ldb + b_c;

    for (int k0 = 0; k0 < K; k0 += 16){
        float4 av = *(const float4*)(Aptr + k0);
        float4 bv = *(const float4*)(Bptr + (long)k0 * ldb);
        As[a_c+0][a_r] = av.x; As[a_c+1][a_r] = av.y;
        As[a_c+2][a_r] = av.z; As[a_c+3][a_r] = av.w;
        *(float4*)&Bs[b_r][b_c] = bv;
        __syncthreads();
        #pragma unroll
        for (int kk = 0; kk < 16; kk++){
            float4 ra = *(const float4*)&As[kk][trow];
            float4 rb = *(const float4*)&Bs[kk][tcol];
            float a0[4] = {ra.x, ra.y, ra.z, ra.w};
            float b0[4] = {rb.x, rb.y, rb.z, rb.w};
            #pragma unroll
            for (int i = 0; i < 4; i++)
                #pragma unroll
                for (int j = 0; j < 4; j++) acc[i][j] += a0[i] * b0[j];
        }
        __syncthreads();
    }
    #pragma unroll
    for (int i = 0; i < 4; i++){
        long r = row0 + trow + i;
        float4 ov;
        ov.x = acc[i][0]; ov.y = acc[i][1]; ov.z = acc[i][2]; ov.w = acc[i][3];
        *(float4*)(C + r * (long)ldc + tcol) = ov;
    }
}

// ================= pointwise ================================================
__global__ __launch_bounds__(256) void split_k(const float* __restrict__ in,
                                               __half* __restrict__ oh,
                                               __half* __restrict__ ol){
    size_t i = ((size_t)blockIdx.x*256 + threadIdx.x)*4;
    float4 v = *(const float4*)(in + i);
    store_split4(oh, ol, i, v);
}

__global__ __launch_bounds__(256) void add_ln_k(float* __restrict__ h,
                                                const float* __restrict__ delta,
                                                const float* __restrict__ w,
                                                const float* __restrict__ b){
    long t = blockIdx.x;
    int tid = threadIdx.x;
    int j = tid * 4;
    __shared__ float sh[8];
    float4 hv = *(const float4*)(h + t * DD + j);
    float4 dv = *(const float4*)(delta + t * DD + j);
    float x[4] = {hv.x + dv.x, hv.y + dv.y, hv.z + dv.z, hv.w + dv.w};
    float s = x[0] + x[1] + x[2] + x[3];
    float mean = blockSum256(s, sh) * (1.f / DD);
    float sq = 0.f;
    #pragma unroll
    for (int c = 0; c < 4; c++){ float d = x[c] - mean; sq += d * d; }
    float var = blockSum256(sq, sh) * (1.f / DD);
    float inv = rsqrtf(var + 1e-5f);
    float4 o;
    o.x = (x[0]-mean)*inv*w[j+0] + b[j+0];
    o.y = (x[1]-mean)*inv*w[j+1] + b[j+1];
    o.z = (x[2]-mean)*inv*w[j+2] + b[j+2];
    o.w = (x[3]-mean)*inv*w[j+3] + b[j+3];
    size_t idx = (size_t)t * DD + j;
    *(float4*)(h + idx) = o;
    store_split4(g_hh, g_hl, idx, o);
}

__global__ __launch_bounds__(256) void copy_h_k(float* __restrict__ dst){
    size_t idx = ((size_t)blockIdx.x * 256 + threadIdx.x) * 4;
    *(float4*)(dst + idx) = *(const float4*)(g_h + idx);
}

// ================= launch ===================================================
extern "C" void kernel_launch(void* const* d_in, const int* in_sizes, int n_in,
                              void* d_out, int out_size)
{
    const int*   x    = (const int*)  d_in[0];
    const float* tok  = (const float*)d_in[1];
    const float* pos  = (const float*)d_in[2];
    const float* Wq   = (const float*)d_in[3];
    const float* bq   = (const float*)d_in[4];
    const float* Wk   = (const float*)d_in[5];
    const float* bk   = (const float*)d_in[6];
    const float* Wv   = (const float*)d_in[7];
    const float* bv   = (const float*)d_in[8];
    const float* Wo   = (const float*)d_in[9];
    const float* bo   = (const float*)d_in[10];
    const float* ln1w = (const float*)d_in[11];
    const float* ln1b = (const float*)d_in[12];
    const float* ln2w = (const float*)d_in[13];
    const float* ln2b = (const float*)d_in[14];
    const float* W1   = (const float*)d_in[15];
    const float* b1   = (const float*)d_in[16];
    const float* W2   = (const float*)d_in[17];
    const float* b2   = (const float*)d_in[18];
    const float* Wout = (const float*)d_in[19];
    const float* bout = (const float*)d_in[20];
    float* out = (float*)d_out;

    static int attr_set = 0;
    if (!attr_set){
        cudaFuncSetAttribute(gemm_mma, cudaFuncAttributeMaxDynamicSharedMemorySize, GM_SMEM);
        attr_set = 1;
    }

    float *h, *qkv, *att, *o, *t, *bqkv;
    __half *hh,*hl,*oh,*ol,*ffh,*ffl;
    __half *wqh,*woh,*w1h,*w2h,*wouth;
    cudaGetSymbolAddress((void**)&h,   g_h);
    cudaGetSymbolAddress((void**)&qkv, g_qkv);
    cudaGetSymbolAddress((void**)&att, g_att);
    cudaGetSymbolAddress((void**)&o,   g_o);
    cudaGetSymbolAddress((void**)&t,   g_t);
    cudaGetSymbolAddress((void**)&bqkv,g_bqkv);
    cudaGetSymbolAddress((void**)&hh,  g_hh);
    cudaGetSymbolAddress((void**)&hl,  g_hl);
    cudaGetSymbolAddress((void**)&oh,  g_oh);
    cudaGetSymbolAddress((void**)&ol,  g_ol);
    cudaGetSymbolAddress((void**)&ffh, g_ffh);
    cudaGetSymbolAddress((void**)&ffl, g_ffl);
    cudaGetSymbolAddress((void**)&wqh, g_wqkv_h);
    cudaGetSymbolAddress((void**)&woh, g_wo_h);
    cudaGetSymbolAddress((void**)&w1h, g_w1_h);
    cudaGetSymbolAddress((void**)&w2h, g_w2_h);
    cudaGetSymbolAddress((void**)&wouth, g_wout_h);

    dim3 tsb(32, 8);
    // --- weight prep: transpose + fp16 cast ---
    packbias_k<<<24, 256>>>(bq, bk, bv);
    tsplit_k<<<dim3(2,32,32), tsb>>>(Wq, (long)DD*HD, 32, 0,
        wqh + 0*DD*DD, (long)HD*DD, 16, (long)3*DD*DD, DD, HD);
    tsplit_k<<<dim3(2,32,32), tsb>>>(Wk, (long)DD*HD, 32, 0,
        wqh + 1*DD*DD, (long)HD*DD, 16, (long)3*DD*DD, DD, HD);
    tsplit_k<<<dim3(2,32,32), tsb>>>(Wv, (long)DD*HD, 32, 0,
        wqh + 2*DD*DD, (long)HD*DD, 16, (long)3*DD*DD, DD, HD);
    tsplit_k<<<dim3(32,32,2), tsb>>>(Wo, (long)DD*DD, 2, 0,
        woh, (long)DD*DD, 2, 0, DD, DD);
    tsplit_k<<<dim3(128,32,2), tsb>>>(W1, (long)DD*FFD, 2, 0,
        w1h, (long)FFD*DD, 2, 0, DD, FFD);
    tsplit_k<<<dim3(32,128,2), tsb>>>(W2, (long)FFD*DD, 2, 0,
        w2h, (long)DD*FFD, 2, 0, FFD, DD);
    tsplit_k<<<dim3(1000,32,1), tsb>>>(Wout, 0, 1, 0,
        wouth, 0, 1, 0, DD, VV);

    embed_k<<<BS, 256>>>(x, tok, pos);

    for (int l = 0; l < LL; l++){
        // QKV: [4096,1024] x [1024,3072] -> g_qkv (f32)
        gemm_mma<<<dim3(BS/128, 3*DD/128), 256, GM_SMEM>>>(
            hh, hl, wqh + (long)l*3*DD*DD,
            bqkv + (long)l*3*DD, qkv, 0, 0, DD, 3*DD, 0);
        scores_k<<<dim3(SS/128, SS/128, HH*BB), 256>>>(qkv, att);
        softmax_k<<<HH*BB*SS, 256>>>(att);
        av_k<<<dim3(1, SS/64, HH*BB), 256>>>(att, qkv, o);
        split_k<<<(BS*DD)/1024, 256>>>(o, oh, ol);
        // Wo
        gemm_mma<<<dim3(BS/128, DD/128), 256, GM_SMEM>>>(
            oh, ol, woh + (long)l*DD*DD,
            bo + (long)l*DD, t, 0, 0, DD, DD, 0);
        add_ln_k<<<BS, 256>>>(h, t, ln1w + (long)l*DD, ln1b + (long)l*DD);
        // W1 + GELU -> ff (fp16 hi/lo)
        gemm_mma<<<dim3(BS/128, FFD/128), 256, GM_SMEM>>>(
            hh, hl, w1h + (long)l*FFD*DD,
            b1 + (long)l*FFD, 0, ffh, ffl, DD, FFD, 1);
        // W2
        gemm_mma<<<dim3(BS/128, DD/128), 256, GM_SMEM>>>(
            ffh, ffl, w2h + (long)l*DD*FFD,
            b2 + (long)l*DD, t, 0, 0, FFD, DD, 0);
        add_ln_k<<<BS, 256>>>(h, t, ln2w + (long)l*DD, ln2b + (long)l*DD);
    }

    // logits
    gemm_mma<<<dim3(BS/128, VV/128), 256, GM_SMEM>>>(
        hh, hl, wouth, bout, out, 0, 0, DD, VV, 0);
    copy_h_k<<<(BS*DD)/1024, 256>>>(out + (long)BS*VV);
}

// round 5
// speedup vs baseline: 3.6511x; 1.2057x over previous
#include <cuda_runtime.h>
#include <cuda_fp16.h>
#include <math.h>
#include <stdint.h>

#define LL 2
#define HH 16
#define DD 1024
#define HD 64
#define FFD 4096
#define VV 32000
#define SS 1024
#define BB 4
#define BS (BB*SS)   /* 4096 */

// ================= scratch (device globals) =================================
__device__ float g_h  [(size_t)BS*DD];
__device__ float g_att[(size_t)BB*HH*SS*SS];   // [h*4+b][S][S] fp32 scores
__device__ __half g_atth[(size_t)BB*HH*SS*SS]; // fp16 softmaxed att
__device__ float g_t  [(size_t)BS*DD];

__device__ __half g_hh[(size_t)BS*DD],  g_hl[(size_t)BS*DD];
__device__ __half g_qkvh[(size_t)BS*3*DD], g_qkvl[(size_t)BS*3*DD];
__device__ __half g_oh[(size_t)BS*DD],  g_ol[(size_t)BS*DD];
__device__ __half g_ffh[(size_t)BS*FFD], g_ffl[(size_t)BS*FFD];

__device__ __half g_wqkv_h[(size_t)LL*3*DD*DD];
__device__ __half g_wo_h [(size_t)LL*DD*DD];
__device__ __half g_w1_h [(size_t)LL*FFD*DD];
__device__ __half g_w2_h [(size_t)LL*DD*FFD];
__device__ __half g_wout_h[(size_t)VV*DD];
__device__ float g_bqkv[(size_t)LL*3*DD];

// ================= small helpers ============================================
__device__ __forceinline__ uint32_t smem_to_u32(const void* smem_ptr) {
    uint32_t addr;
    asm("{ .reg .u64 tmp; cvta.to.shared.u64 tmp, %1; cvt.u32.u64 %0, tmp; }"
        : "=r"(addr) : "l"(smem_ptr));
    return addr;
}
__device__ __forceinline__ void cp16(uint32_t d, const void* s){
    asm volatile("cp.async.cg.shared.global [%0], [%1], 16;" :: "r"(d), "l"(s) : "memory");
}
__device__ __forceinline__ void ldm_x4(uint32_t* r, uint32_t addr){
    asm volatile("ldmatrix.sync.aligned.m8n8.x4.shared.b16 {%0,%1,%2,%3}, [%4];"
        : "=r"(r[0]), "=r"(r[1]), "=r"(r[2]), "=r"(r[3]) : "r"(addr));
}
__device__ __forceinline__ void ldm_x4_t(uint32_t* r, uint32_t addr){
    asm volatile("ldmatrix.sync.aligned.m8n8.x4.trans.shared.b16 {%0,%1,%2,%3}, [%4];"
        : "=r"(r[0]), "=r"(r[1]), "=r"(r[2]), "=r"(r[3]) : "r"(addr));
}
__device__ __forceinline__ void mma16816(float* c, const uint32_t* a, uint32_t b0, uint32_t b1){
    asm volatile("mma.sync.aligned.m16n8k16.row.col.f32.f16.f16.f32 "
        "{%0,%1,%2,%3}, {%4,%5,%6,%7}, {%8,%9}, {%0,%1,%2,%3};"
        : "+f"(c[0]), "+f"(c[1]), "+f"(c[2]), "+f"(c[3])
        : "r"(a[0]), "r"(a[1]), "r"(a[2]), "r"(a[3]), "r"(b0), "r"(b1));
}
__device__ __forceinline__ float warpSum(float v){
    #pragma unroll
    for (int o = 16; o > 0; o >>= 1) v += __shfl_xor_sync(0xffffffffu, v, o);
    return v;
}
__device__ __forceinline__ float warpMax(float v){
    #pragma unroll
    for (int o = 16; o > 0; o >>= 1) v = fmaxf(v, __shfl_xor_sync(0xffffffffu, v, o));
    return v;
}
__device__ __forceinline__ float blockSum256(float v, float* sh){
    int lane = threadIdx.x & 31, wid = threadIdx.x >> 5;
    v = warpSum(v);
    if (lane == 0) sh[wid] = v;
    __syncthreads();
    float r = (threadIdx.x < 8) ? sh[threadIdx.x] : 0.f;
    if (threadIdx.x < 32) { r = warpSum(r); if (threadIdx.x == 0) sh[0] = r; }
    __syncthreads();
    float res = sh[0];
    __syncthreads();
    return res;
}
__device__ __forceinline__ float gelu_f(float x){
    return 0.5f * x * (1.0f + erff(x * 0.70710678118654752f));
}
__device__ __forceinline__ void store_split4(__half* ph, __half* pl,
                                             size_t idx, float4 v){
    __half h0=__float2half_rn(v.x), h1=__float2half_rn(v.y),
           h2=__float2half_rn(v.z), h3=__float2half_rn(v.w);
    *(__half2*)(ph+idx)   = __halves2half2(h0,h1);
    *(__half2*)(ph+idx+2) = __halves2half2(h2,h3);
    __half l0=__float2half_rn(v.x-__half2float(h0));
    __half l1=__float2half_rn(v.y-__half2float(h1));
    __half l2=__float2half_rn(v.z-__half2float(h2));
    __half l3=__float2half_rn(v.w-__half2float(h3));
    *(__half2*)(pl+idx)   = __halves2half2(l0,l1);
    *(__half2*)(pl+idx+2) = __halves2half2(l2,l3);
}
__device__ __forceinline__ void store_split2(__half* ph, __half* pl,
                                             size_t idx, float a, float b){
    __half h0=__float2half_rn(a), h1=__float2half_rn(b);
    *(__half2*)(ph+idx) = __halves2half2(h0,h1);
    __half l0=__float2half_rn(a-__half2float(h0));
    __half l1=__float2half_rn(b-__half2float(h1));
    *(__half2*)(pl+idx) = __halves2half2(l0,l1);
}

// ================= prep kernels =============================================
__global__ __launch_bounds__(256) void packbias_k(const float* __restrict__ bq,
                                                  const float* __restrict__ bk,
                                                  const float* __restrict__ bv){
    int i = blockIdx.x*256 + threadIdx.x;            // 0..6143
    int l = i / (3*DD), n = i % (3*DD);
    float v = (n < DD) ? bq[l*DD + n] : (n < 2*DD) ? bk[l*DD + n - DD] : bv[l*DD + n - 2*DD];
    g_bqkv[i] = v;
}

// transposed fp16 cast: out[n][k] = fp16(in_z[k][n]); in [K][ldin], out ld=K
__global__ __launch_bounds__(256) void tsplit_k(
    const float* __restrict__ in, long sInLo, int zdivIn, long sInHi,
    __half* __restrict__ oh,
    long sOutLo, int zdivOut, long sOutHi,
    int K, int ldin)
{
    __shared__ float t[32][33];
    int z = blockIdx.z;
    const float* I = in + (long)(z % zdivIn)*sInLo + (long)(z / zdivIn)*sInHi;
    long ob = (long)(z % zdivOut)*sOutLo + (long)(z / zdivOut)*sOutHi;
    int nx = blockIdx.x*32, ky = blockIdx.y*32;
    int tx = threadIdx.x, ty = threadIdx.y;  // (32,8)
    #pragma unroll
    for (int i = 0; i < 4; i++)
        t[ty + i*8][tx] = I[(long)(ky + ty + i*8)*ldin + nx + tx];
    __syncthreads();
    #pragma unroll
    for (int i = 0; i < 4; i++){
        int n = nx + ty + i*8, k = ky + tx;
        oh[ob + (long)n*K + k] = __float2half_rn(t[tx][ty + i*8]);
    }
}

__global__ __launch_bounds__(256) void embed_k(const int* __restrict__ x,
                                               const float* __restrict__ tok,
                                               const float* __restrict__ pos){
    int t = blockIdx.x;
    int s = t & (SS - 1);
    int id = x[t];
    int j = threadIdx.x * 4;
    float4 a = *(const float4*)(tok + (size_t)id * DD + j);
    float4 p = *(const float4*)(pos + (size_t)s  * DD + j);
    float4 r; r.x = a.x + p.x; r.y = a.y + p.y; r.z = a.z + p.z; r.w = a.w + p.w;
    size_t idx = (size_t)t * DD + j;
    *(float4*)(g_h + idx) = r;
    store_split4(g_hh, g_hl, idx, r);
}

// ================= split-fp16 GEMM via mma.sync (HMMA) ======================
// C[M,N] = Ah*Bh^T + Al*Bh^T (+bias).  A hi/lo fp16 [M][K], B fp16 [N][K].
// block tile 128x128, Kc=32, 8 warps (warp tile 32x64), cp.async double buffer.
// op0: f32 out + bias.  op1: gelu(out+bias) -> fp16 hi/lo.  op2: bias -> fp16 hi/lo.
#define PADK 40            /* row stride in fp16 elems (80B), conflict-free */
#define OPSZ 10240         /* 128*PADK*2 bytes per operand tile */
#define GM_SMEM (2*3*OPSZ) /* 61440 */
__global__ __launch_bounds__(256, 1) void gemm_mma(
    const __half* __restrict__ Ah, const __half* __restrict__ Al,
    const __half* __restrict__ Bh,
    const float* __restrict__ bias,
    float* __restrict__ Cf,
    __half* __restrict__ Chi, __half* __restrict__ Clo,
    int K_, int ldc, int op)
{
    extern __shared__ char smem[];
    uint32_t sb = smem_to_u32(smem);
    int tid = threadIdx.x, lane = tid & 31, wid = tid >> 5;
    int wm = wid & 3, wn = wid >> 2;            // 4x2 warp grid
    long row0 = (long)blockIdx.x * 128;
    long col0 = (long)blockIdx.y * 128;

    float acc[2][8][4];
    #pragma unroll
    for (int i = 0; i < 2; i++)
        #pragma unroll
        for (int j = 0; j < 8; j++)
            #pragma unroll
            for (int q = 0; q < 4; q++) acc[i][j][q] = 0.f;

    auto load_chunk = [&](int c, int buf){
        long k0 = (long)c * 32;
        uint32_t base = sb + (uint32_t)buf * (3*OPSZ);
        #pragma unroll
        for (int i = tid; i < 512; i += 256){
            int r = i >> 2, seg = (i & 3) * 8;
            uint32_t soff = (uint32_t)(r * PADK + seg) * 2;
            long ga = (row0 + r) * (long)K_ + k0 + seg;
            long gb = (col0 + r) * (long)K_ + k0 + seg;
            cp16(base + soff,           Ah + ga);
            cp16(base + OPSZ   + soff,  Al + ga);
            cp16(base + 2*OPSZ + soff,  Bh + gb);
        }
        asm volatile("cp.async.commit_group;" ::: "memory");
    };

    const int NC = K_ >> 5;
    load_chunk(0, 0);

    int m_local = (lane & 7) | (lane & 8);
    int k_off = (lane >> 4) * 8;

    for (int c = 0; c < NC; ++c){
        int buf = c & 1;
        asm volatile("cp.async.wait_group 0;" ::: "memory");
        __syncthreads();
        if (c + 1 < NC) load_chunk(c + 1, buf ^ 1);

        uint32_t base = sb + (uint32_t)buf * (3*OPSZ);
        #pragma unroll
        for (int ks = 0; ks < 2; ++ks){
            uint32_t a_h[2][4], a_l[2][4];
            #pragma unroll
            for (int am = 0; am < 2; ++am){
                uint32_t roff = (uint32_t)((wm*32 + am*16 + m_local) * PADK + ks*16 + k_off) * 2;
                ldm_x4(a_h[am], base + roff);
                ldm_x4(a_l[am], base + OPSZ + roff);
            }
            uint32_t b_h[4][4];
            #pragma unroll
            for (int nt2 = 0; nt2 < 4; ++nt2){
                uint32_t roff = (uint32_t)((wn*64 + nt2*16 + m_local) * PADK + ks*16 + k_off) * 2;
                ldm_x4(b_h[nt2], base + 2*OPSZ + roff);
            }
            #pragma unroll
            for (int mt = 0; mt < 2; ++mt)
                #pragma unroll
                for (int nt = 0; nt < 8; ++nt){
                    int q = nt >> 1, rs = nt & 1;
                    uint32_t bh0 = b_h[q][rs], bh1 = b_h[q][rs+2];
                    mma16816(acc[mt][nt], a_h[mt], bh0, bh1);
                    mma16816(acc[mt][nt], a_l[mt], bh0, bh1);
                }
        }
    }

    // epilogue
    #pragma unroll
    for (int mt = 0; mt < 2; ++mt){
        #pragma unroll
        for (int nt = 0; nt < 8; ++nt){
            long row = row0 + wm*32 + mt*16 + (lane >> 2);
            long col = col0 + wn*64 + nt*8 + (lane & 3)*2;
            float b0 = bias[col], b1 = bias[col+1];
            float v0 = acc[mt][nt][0] + b0, v1 = acc[mt][nt][1] + b1;
            float v2 = acc[mt][nt][2] + b0, v3 = acc[mt][nt][3] + b1;
            if (op == 0){
                *(float2*)(Cf + row*(long)ldc + col)     = make_float2(v0, v1);
                *(float2*)(Cf + (row+8)*(long)ldc + col) = make_float2(v2, v3);
            } else if (op == 1){
                store_split2(Chi, Clo, (size_t)(row*(long)ldc + col),     gelu_f(v0), gelu_f(v1));
                store_split2(Chi, Clo, (size_t)((row+8)*(long)ldc + col), gelu_f(v2), gelu_f(v3));
            } else {
                store_split2(Chi, Clo, (size_t)(row*(long)ldc + col),     v0, v1);
                store_split2(Chi, Clo, (size_t)((row+8)*(long)ldc + col), v2, v3);
            }
        }
    }
}

// ================= attention via mma ========================================
// scores: att[z][S][S] = (Qh+Ql) @ Kh^T, z = h*4+b.  K=64, single smem load.
#define PADQ 72
#define SC_PLANE (128*PADQ*2)           /* 18432 B */
#define SC_SMEM  (3*SC_PLANE)           /* 55296 B */
__global__ __launch_bounds__(256, 1) void scores_mma(
    const __half* __restrict__ qh, const __half* __restrict__ ql,
    float* __restrict__ att)
{
    extern __shared__ char smem[];
    uint32_t sb = smem_to_u32(smem);
    int z = blockIdx.z; int b = z & 3, hd = z >> 2;
    long qbase = (long)b*SS*(3*DD) + hd*HD;          // q offset
    long kbase = qbase + DD;                          // k offset
    float* C = att + (long)z*SS*SS;

    int tid = threadIdx.x, lane = tid & 31, wid = tid >> 5;
    int wm = wid & 3, wn = wid >> 2;
    long row0 = (long)blockIdx.y * 128;
    long col0 = (long)blockIdx.x * 128;

    // load Qh, Ql (rows row0..+127), Kh (rows col0..+127): 64 halves/row
    #pragma unroll
    for (int i = tid; i < 1024; i += 256){
        int r = i >> 3, u = (i & 7) * 8;
        uint32_t soff = (uint32_t)(r * PADQ + u) * 2;
        cp16(sb + soff,              qh + qbase + (row0 + r)*(long)(3*DD) + u);
        cp16(sb + SC_PLANE + soff,   ql + qbase + (row0 + r)*(long)(3*DD) + u);
        cp16(sb + 2*SC_PLANE + soff, qh + kbase + (col0 + r)*(long)(3*DD) + u);
    }
    asm volatile("cp.async.commit_group;" ::: "memory");
    asm volatile("cp.async.wait_group 0;" ::: "memory");
    __syncthreads();

    int m_local = (lane & 7) | (lane & 8);
    int k_off = (lane >> 4) * 8;

    float acc[2][8][4];
    #pragma unroll
    for (int i = 0; i < 2; i++)
        #pragma unroll
        for (int j = 0; j < 8; j++)
            #pragma unroll
            for (int q = 0; q < 4; q++) acc[i][j][q] = 0.f;

    #pragma unroll
    for (int ks = 0; ks < 4; ++ks){
        uint32_t a_h[2][4], a_l[2][4];
        #pragma unroll
        for (int am = 0; am < 2; ++am){
            uint32_t roff = (uint32_t)((wm*32 + am*16 + m_local) * PADQ + ks*16 + k_off) * 2;
            ldm_x4(a_h[am], sb + roff);
            ldm_x4(a_l[am], sb + SC_PLANE + roff);
        }
        uint32_t b_h[4][4];
        #pragma unroll
        for (int nt2 = 0; nt2 < 4; ++nt2){
            uint32_t roff = (uint32_t)((wn*64 + nt2*16 + m_local) * PADQ + ks*16 + k_off) * 2;
            ldm_x4(b_h[nt2], sb + 2*SC_PLANE + roff);
        }
        #pragma unroll
        for (int mt = 0; mt < 2; ++mt)
            #pragma unroll
            for (int nt = 0; nt < 8; ++nt){
                int q = nt >> 1, rs = nt & 1;
                uint32_t bh0 = b_h[q][rs], bh1 = b_h[q][rs+2];
                mma16816(acc[mt][nt], a_h[mt], bh0, bh1);
                mma16816(acc[mt][nt], a_l[mt], bh0, bh1);
            }
    }

    #pragma unroll
    for (int mt = 0; mt < 2; ++mt){
        #pragma unroll
        for (int nt = 0; nt < 8; ++nt){
            long row = row0 + wm*32 + mt*16 + (lane >> 2);
            long col = col0 + wn*64 + nt*8 + (lane & 3)*2;
            *(float2*)(C + row*(long)SS + col)     = make_float2(acc[mt][nt][0], acc[mt][nt][1]);
            *(float2*)(C + (row+8)*(long)SS + col) = make_float2(acc[mt][nt][2], acc[mt][nt][3]);
        }
    }
}

// softmax: read fp32 scores, write fp16 att
__global__ __launch_bounds__(256) void softmax_k(const float* __restrict__ att,
                                                 __half* __restrict__ atth){
    long rid = blockIdx.x;
    int i = (int)(rid & (SS - 1));
    const float* row = att + rid * (long)SS;
    __half* orow = atth + rid * (long)SS;
    int tid = threadIdx.x;
    __shared__ float shm[8];
    __shared__ float shs[8];

    float4 v4 = *(const float4*)(row + tid * 4);
    float v[4] = {v4.x, v4.y, v4.z, v4.w};
    float m = -1e30f;
    #pragma unroll
    for (int c = 0; c < 4; c++){
        int j = tid * 4 + c;
        v[c] = (j <= i) ? v[c] * 0.125f : -1e30f;
        m = fmaxf(m, v[c]);
    }
    int lane = tid & 31, wid = tid >> 5;
    float wm = warpMax(m);
    if (lane == 0) shm[wid] = wm;
    __syncthreads();
    if (tid < 32){
        float r = (tid < 8) ? shm[tid] : -1e30f;
        r = warpMax(r);
        if (tid == 0) shm[0] = r;
    }
    __syncthreads();
    m = shm[0];
    float s = 0.f;
    #pragma unroll
    for (int c = 0; c < 4; c++){ v[c] = expf(v[c] - m); s += v[c]; }
    float bs = blockSum256(s, shs);
    float inv = 1.f / bs;
    __half2 o0 = __halves2half2(__float2half_rn(v[0]*inv), __float2half_rn(v[1]*inv));
    __half2 o1 = __halves2half2(__float2half_rn(v[2]*inv), __float2half_rn(v[3]*inv));
    *(__half2*)(orow + tid*4)     = o0;
    *(__half2*)(orow + tid*4 + 2) = o1;
}

// AV: o[b*S+s][h*64+e] = att_fp16[z] @ (Vh+Vl)[z], via mma + trans ldmatrix.
// block: 128 rows x 64 cols, K chunks of 64 over S, double buffered.
#define AV_ATT  (128*PADQ*2)                 /* 18432 B */
#define AV_V    (64*PADQ*2)                  /* 9216 B  */
#define AV_BUF  (AV_ATT + 2*AV_V)            /* 36864 B */
#define AV_SMEM (2*AV_BUF)                   /* 73728 B */
__global__ __launch_bounds__(256, 1) void av_mma(
    const __half* __restrict__ atth,
    const __half* __restrict__ qkvh, const __half* __restrict__ qkvl,
    __half* __restrict__ oh, __half* __restrict__ ol)
{
    extern __shared__ char smem[];
    uint32_t sb = smem_to_u32(smem);
    int z = blockIdx.z; int b = z & 3, hd = z >> 2;
    const __half* A = atth + (long)z*SS*SS;
    long vbase = (long)b*SS*(3*DD) + 2*DD + hd*HD;
    long obase = (long)b*SS*DD + hd*HD;

    int tid = threadIdx.x, lane = tid & 31, wid = tid >> 5;
    int wm = wid & 3, wn = wid >> 2;            // 4 x 2; warp tile 32x32
    long row0 = (long)blockIdx.y * 128;

    float acc[2][4][4];
    #pragma unroll
    for (int i = 0; i < 2; i++)
        #pragma unroll
        for (int j = 0; j < 4; j++)
            #pragma unroll
            for (int q = 0; q < 4; q++) acc[i][j][q] = 0.f;

    auto load_chunk = [&](int c, int buf){
        long k0 = (long)c * 64;
        uint32_t base = sb + (uint32_t)buf * AV_BUF;
        #pragma unroll
        for (int i = tid; i < 1024; i += 256){     // att: 128 rows x 64
            int r = i >> 3, u = (i & 7) * 8;
            uint32_t soff = (uint32_t)(r * PADQ + u) * 2;
            cp16(base + soff, A + (row0 + r)*(long)SS + k0 + u);
        }
        #pragma unroll
        for (int i = tid; i < 512; i += 256){      // Vh, Vl: 64 rows x 64
            int r = i >> 3, u = (i & 7) * 8;
            uint32_t soff = (uint32_t)(r * PADQ + u) * 2;
            long g = vbase + (k0 + r)*(long)(3*DD) + u;
            cp16(base + AV_ATT + soff,        qkvh + g);
            cp16(base + AV_ATT + AV_V + soff, qkvl + g);
        }
        asm volatile("cp.async.commit_group;" ::: "memory");
    };

    load_chunk(0, 0);

    int m_local = (lane & 7) | (lane & 8);
    int k_off = (lane >> 4) * 8;
    int t_row = lane & 15, t_col = (lane >> 4) * 8;   // trans ldmatrix addressing

    for (int c = 0; c < 16; ++c){
        int buf = c & 1;
        asm volatile("cp.async.wait_group 0;" ::: "memory");
        __syncthreads();
        if (c + 1 < 16) load_chunk(c + 1, buf ^ 1);

        uint32_t base = sb + (uint32_t)buf * AV_BUF;
        #pragma unroll
        for (int ks = 0; ks < 4; ++ks){
            uint32_t a_f[2][4];
            #pragma unroll
            for (int am = 0; am < 2; ++am){
                uint32_t roff = (uint32_t)((wm*32 + am*16 + m_local) * PADQ + ks*16 + k_off) * 2;
                ldm_x4(a_f[am], base + roff);
            }
            // B: V[k][n] with trans; two 16-col groups per warp
            uint32_t b_h[2][4], b_l[2][4];
            #pragma unroll
            for (int g2 = 0; g2 < 2; ++g2){
                uint32_t voff = (uint32_t)((ks*16 + t_row) * PADQ + wn*32 + g2*16 + t_col) * 2;
                ldm_x4_t(b_h[g2], base + AV_ATT + voff);
                ldm_x4_t(b_l[g2], base + AV_ATT + AV_V + voff);
            }
            #pragma unroll
            for (int mt = 0; mt < 2; ++mt)
                #pragma unroll
                for (int nt = 0; nt < 4; ++nt){
                    int g2 = nt >> 1, sub = (nt & 1) * 2;
                    mma16816(acc[mt][nt], a_f[mt], b_h[g2][sub], b_h[g2][sub+1]);
                    mma16816(acc[mt][nt], a_f[mt], b_l[g2][sub], b_l[g2][sub+1]);
                }
        }
    }

    #pragma unroll
    for (int mt = 0; mt < 2; ++mt){
        #pragma unroll
        for (int nt = 0; nt < 4; ++nt){
            long row = row0 + wm*32 + mt*16 + (lane >> 2);
            long col = wn*32 + nt*8 + (lane & 3)*2;
            size_t idx = (size_t)(obase + row*(long)DD + col);
            store_split2(oh, ol, idx,          acc[mt][nt][0], acc[mt][nt][1]);
            store_split2(oh, ol, idx + 8*DD,   acc[mt][nt][2], acc[mt][nt][3]);
        }
    }
}

// ================= pointwise ================================================
__global__ __launch_bounds__(256) void add_ln_k(float* __restrict__ h,
                                                const float* __restrict__ delta,
                                                const float* __restrict__ w,
                                                const float* __restrict__ b){
    long t = blockIdx.x;
    int tid = threadIdx.x;
    int j = tid * 4;
    __shared__ float sh[8];
    float4 hv = *(const float4*)(h + t * DD + j);
    float4 dv = *(const float4*)(delta + t * DD + j);
    float x[4] = {hv.x + dv.x, hv.y + dv.y, hv.z + dv.z, hv.w + dv.w};
    float s = x[0] + x[1] + x[2] + x[3];
    float mean = blockSum256(s, sh) * (1.f / DD);
    float sq = 0.f;
    #pragma unroll
    for (int c = 0; c < 4; c++){ float d = x[c] - mean; sq += d * d; }
    float var = blockSum256(sq, sh) * (1.f / DD);
    float inv = rsqrtf(var + 1e-5f);
    float4 o;
    o.x = (x[0]-mean)*inv*w[j+0] + b[j+0];
    o.y = (x[1]-mean)*inv*w[j+1] + b[j+1];
    o.z = (x[2]-mean)*inv*w[j+2] + b[j+2];
    o.w = (x[3]-mean)*inv*w[j+3] + b[j+3];
    size_t idx = (size_t)t * DD + j;
    *(float4*)(h + idx) = o;
    store_split4(g_hh, g_hl, idx, o);
}

__global__ __launch_bounds__(256) void copy_h_k(float* __restrict__ dst){
    size_t idx = ((size_t)blockIdx.x * 256 + threadIdx.x) * 4;
    *(float4*)(dst + idx) = *(const float4*)(g_h + idx);
}

// ================= launch ===================================================
extern "C" void kernel_launch(void* const* d_in, const int* in_sizes, int n_in,
                              void* d_out, int out_size)
{
    const int*   x    = (const int*)  d_in[0];
    const float* tok  = (const float*)d_in[1];
    const float* pos  = (const float*)d_in[2];
    const float* Wq   = (const float*)d_in[3];
    const float* bq   = (const float*)d_in[4];
    const float* Wk   = (const float*)d_in[5];
    const float* bk   = (const float*)d_in[6];
    const float* Wv   = (const float*)d_in[7];
    const float* bv   = (const float*)d_in[8];
    const float* Wo   = (const float*)d_in[9];
    const float* bo   = (const float*)d_in[10];
    const float* ln1w = (const float*)d_in[11];
    const float* ln1b = (const float*)d_in[12];
    const float* ln2w = (const float*)d_in[13];
    const float* ln2b = (const float*)d_in[14];
    const float* W1   = (const float*)d_in[15];
    const float* b1   = (const float*)d_in[16];
    const float* W2   = (const float*)d_in[17];
    const float* b2   = (const float*)d_in[18];
    const float* Wout = (const float*)d_in[19];
    const float* bout = (const float*)d_in[20];
    float* out = (float*)d_out;

    static int attr_set = 0;
    if (!attr_set){
        cudaFuncSetAttribute(gemm_mma,   cudaFuncAttributeMaxDynamicSharedMemorySize, GM_SMEM);
        cudaFuncSetAttribute(scores_mma, cudaFuncAttributeMaxDynamicSharedMemorySize, SC_SMEM);
        cudaFuncSetAttribute(av_mma,     cudaFuncAttributeMaxDynamicSharedMemorySize, AV_SMEM);
        attr_set = 1;
    }

    float *h, *att, *t, *bqkv;
    __half *atth, *hh,*hl,*qh,*ql,*oh,*ol,*ffh,*ffl;
    __half *wqh,*woh,*w1h,*w2h,*wouth;
    cudaGetSymbolAddress((void**)&h,    g_h);
    cudaGetSymbolAddress((void**)&att,  g_att);
    cudaGetSymbolAddress((void**)&atth, g_atth);
    cudaGetSymbolAddress((void**)&t,    g_t);
    cudaGetSymbolAddress((void**)&bqkv, g_bqkv);
    cudaGetSymbolAddress((void**)&hh,   g_hh);
    cudaGetSymbolAddress((void**)&hl,   g_hl);
    cudaGetSymbolAddress((void**)&qh,   g_qkvh);
    cudaGetSymbolAddress((void**)&ql,   g_qkvl);
    cudaGetSymbolAddress((void**)&oh,   g_oh);
    cudaGetSymbolAddress((void**)&ol,   g_ol);
    cudaGetSymbolAddress((void**)&ffh,  g_ffh);
    cudaGetSymbolAddress((void**)&ffl,  g_ffl);
    cudaGetSymbolAddress((void**)&wqh,  g_wqkv_h);
    cudaGetSymbolAddress((void**)&woh,  g_wo_h);
    cudaGetSymbolAddress((void**)&w1h,  g_w1_h);
    cudaGetSymbolAddress((void**)&w2h,  g_w2_h);
    cudaGetSymbolAddress((void**)&wouth,g_wout_h);

    dim3 tsb(32, 8);
    // --- weight prep: transpose + fp16 cast ---
    packbias_k<<<24, 256>>>(bq, bk, bv);
    tsplit_k<<<dim3(2,32,32), tsb>>>(Wq, (long)DD*HD, 32, 0,
        wqh + 0*DD*DD, (long)HD*DD, 16, (long)3*DD*DD, DD, HD);
    tsplit_k<<<dim3(2,32,32), tsb>>>(Wk, (long)DD*HD, 32, 0,
        wqh + 1*DD*DD, (long)HD*DD, 16, (long)3*DD*DD, DD, HD);
    tsplit_k<<<dim3(2,32,32), tsb>>>(Wv, (long)DD*HD, 32, 0,
        wqh + 2*DD*DD, (long)HD*DD, 16, (long)3*DD*DD, DD, HD);
    tsplit_k<<<dim3(32,32,2), tsb>>>(Wo, (long)DD*DD, 2, 0,
        woh, (long)DD*DD, 2, 0, DD, DD);
    tsplit_k<<<dim3(128,32,2), tsb>>>(W1, (long)DD*FFD, 2, 0,
        w1h, (long)FFD*DD, 2, 0, DD, FFD);
    tsplit_k<<<dim3(32,128,2), tsb>>>(W2, (long)FFD*DD, 2, 0,
        w2h, (long)DD*FFD, 2, 0, FFD, DD);
    tsplit_k<<<dim3(1000,32,1), tsb>>>(Wout, 0, 1, 0,
        wouth, 0, 1, 0, DD, VV);

    embed_k<<<BS, 256>>>(x, tok, pos);

    for (int l = 0; l < LL; l++){
        // QKV: [4096,1024] x [1024,3072] -> fp16 hi/lo planes
        gemm_mma<<<dim3(BS/128, 3*DD/128), 256, GM_SMEM>>>(
            hh, hl, wqh + (long)l*3*DD*DD,
            bqkv + (long)l*3*DD, 0, qh, ql, DD, 3*DD, 2);
        scores_mma<<<dim3(SS/128, SS/128, HH*BB), 256, SC_SMEM>>>(qh, ql, att);
        softmax_k<<<HH*BB*SS, 256>>>(att, atth);
        av_mma<<<dim3(1, SS/128, HH*BB), 256, AV_SMEM>>>(atth, qh, ql, oh, ol);
        // Wo
        gemm_mma<<<dim3(BS/128, DD/128), 256, GM_SMEM>>>(
            oh, ol, woh + (long)l*DD*DD,
            bo + (long)l*DD, t, 0, 0, DD, DD, 0);
        add_ln_k<<<BS, 256>>>(h, t, ln1w + (long)l*DD, ln1b + (long)l*DD);
        // W1 + GELU -> ff (fp16 hi/lo)
        gemm_mma<<<dim3(BS/128, FFD/128), 256, GM_SMEM>>>(
            hh, hl, w1h + (long)l*FFD*DD,
            b1 + (long)l*FFD, 0, ffh, ffl, DD, FFD, 1);
        // W2
        gemm_mma<<<dim3(BS/128, DD/128), 256, GM_SMEM>>>(
            ffh, ffl, w2h + (long)l*DD*FFD,
            b2 + (long)l*DD, t, 0, 0, FFD, DD, 0);
        add_ln_k<<<BS, 256>>>(h, t, ln2w + (long)l*DD, ln2b + (long)l*DD);
    }

    // logits
    gemm_mma<<<dim3(BS/128, VV/128), 256, GM_SMEM>>>(
        hh, hl, wouth, bout, out, 0, 0, DD, VV, 0);
    copy_h_k<<<(BS*DD)/1024, 256>>>(out + (long)BS*VV);
}

// round 7
// speedup vs baseline: 4.1263x; 1.1301x over previous
#include <cuda_runtime.h>
#include <cuda_fp16.h>
#include <math.h>
#include <stdint.h>

#define LL 2
#define HH 16
#define DD 1024
#define HD 64
#define FFD 4096
#define VV 32000
#define SS 1024
#define BB 4
#define BS (BB*SS)   /* 4096 */

// ================= scratch (device globals) =================================
__device__ float g_h  [(size_t)BS*DD];
__device__ float g_att[(size_t)BB*HH*SS*SS];   // [h*4+b][S][S] fp32 scores
__device__ __half g_atth[(size_t)BB*HH*SS*SS]; // fp16 softmaxed att
__device__ float g_t  [(size_t)BS*DD];

__device__ __half g_hh[(size_t)BS*DD],  g_hl[(size_t)BS*DD];
__device__ __half g_qkvh[(size_t)BS*3*DD], g_qkvl[(size_t)BS*3*DD];
__device__ __half g_oh[(size_t)BS*DD],  g_ol[(size_t)BS*DD];
__device__ __half g_ffh[(size_t)BS*FFD], g_ffl[(size_t)BS*FFD];

__device__ __half g_wqkv_h[(size_t)LL*3*DD*DD];
__device__ __half g_wo_h [(size_t)LL*DD*DD];
__device__ __half g_w1_h [(size_t)LL*FFD*DD];
__device__ __half g_w2_h [(size_t)LL*DD*FFD];
__device__ __half g_wout_h[(size_t)VV*DD];
__device__ float g_bqkv[(size_t)LL*3*DD];

// ================= small helpers ============================================
__device__ __forceinline__ uint32_t smem_to_u32(const void* smem_ptr) {
    uint32_t addr;
    asm("{ .reg .u64 tmp; cvta.to.shared.u64 tmp, %1; cvt.u32.u64 %0, tmp; }"
        : "=r"(addr) : "l"(smem_ptr));
    return addr;
}
__device__ __forceinline__ void cp16(uint32_t d, const void* s){
    asm volatile("cp.async.cg.shared.global [%0], [%1], 16;" :: "r"(d), "l"(s) : "memory");
}
__device__ __forceinline__ void ldm_x4(uint32_t* r, uint32_t addr){
    asm volatile("ldmatrix.sync.aligned.m8n8.x4.shared.b16 {%0,%1,%2,%3}, [%4];"
        : "=r"(r[0]), "=r"(r[1]), "=r"(r[2]), "=r"(r[3]) : "r"(addr));
}
__device__ __forceinline__ void ldm_x4_t(uint32_t* r, uint32_t addr){
    asm volatile("ldmatrix.sync.aligned.m8n8.x4.trans.shared.b16 {%0,%1,%2,%3}, [%4];"
        : "=r"(r[0]), "=r"(r[1]), "=r"(r[2]), "=r"(r[3]) : "r"(addr));
}
__device__ __forceinline__ void mma16816(float* c, const uint32_t* a, uint32_t b0, uint32_t b1){
    asm volatile("mma.sync.aligned.m16n8k16.row.col.f32.f16.f16.f32 "
        "{%0,%1,%2,%3}, {%4,%5,%6,%7}, {%8,%9}, {%0,%1,%2,%3};"
        : "+f"(c[0]), "+f"(c[1]), "+f"(c[2]), "+f"(c[3])
        : "r"(a[0]), "r"(a[1]), "r"(a[2]), "r"(a[3]), "r"(b0), "r"(b1));
}
__device__ __forceinline__ float warpSum(float v){
    #pragma unroll
    for (int o = 16; o > 0; o >>= 1) v += __shfl_xor_sync(0xffffffffu, v, o);
    return v;
}
__device__ __forceinline__ float warpMax(float v){
    #pragma unroll
    for (int o = 16; o > 0; o >>= 1) v = fmaxf(v, __shfl_xor_sync(0xffffffffu, v, o));
    return v;
}
__device__ __forceinline__ float blockSum256(float v, float* sh){
    int lane = threadIdx.x & 31, wid = threadIdx.x >> 5;
    v = warpSum(v);
    if (lane == 0) sh[wid] = v;
    __syncthreads();
    float r = (threadIdx.x < 8) ? sh[threadIdx.x] : 0.f;
    if (threadIdx.x < 32) { r = warpSum(r); if (threadIdx.x == 0) sh[0] = r; }
    __syncthreads();
    float res = sh[0];
    __syncthreads();
    return res;
}
__device__ __forceinline__ float gelu_f(float x){
    return 0.5f * x * (1.0f + erff(x * 0.70710678118654752f));
}
__device__ __forceinline__ void store_split4(__half* ph, __half* pl,
                                             size_t idx, float4 v){
    __half h0=__float2half_rn(v.x), h1=__float2half_rn(v.y),
           h2=__float2half_rn(v.z), h3=__float2half_rn(v.w);
    *(__half2*)(ph+idx)   = __halves2half2(h0,h1);
    *(__half2*)(ph+idx+2) = __halves2half2(h2,h3);
    __half l0=__float2half_rn(v.x-__half2float(h0));
    __half l1=__float2half_rn(v.y-__half2float(h1));
    __half l2=__float2half_rn(v.z-__half2float(h2));
    __half l3=__float2half_rn(v.w-__half2float(h3));
    *(__half2*)(pl+idx)   = __halves2half2(l0,l1);
    *(__half2*)(pl+idx+2) = __halves2half2(l2,l3);
}
__device__ __forceinline__ void store_split2(__half* ph, __half* pl,
                                             size_t idx, float a, float b){
    __half h0=__float2half_rn(a), h1=__float2half_rn(b);
    *(__half2*)(ph+idx) = __halves2half2(h0,h1);
    __half l0=__float2half_rn(a-__half2float(h0));
    __half l1=__float2half_rn(b-__half2float(h1));
    *(__half2*)(pl+idx) = __halves2half2(l0,l1);
}

// ================= prep kernels =============================================
__global__ __launch_bounds__(256) void packbias_k(const float* __restrict__ bq,
                                                  const float* __restrict__ bk,
                                                  const float* __restrict__ bv){
    int i = blockIdx.x*256 + threadIdx.x;            // 0..6143
    int l = i / (3*DD), n = i % (3*DD);
    float v = (n < DD) ? bq[l*DD + n] : (n < 2*DD) ? bk[l*DD + n - DD] : bv[l*DD + n - 2*DD];
    g_bqkv[i] = v;
}

// transposed fp16 cast: out[n][k] = fp16(in_z[k][n]); in [K][ldin], out ld=K
__global__ __launch_bounds__(256) void tsplit_k(
    const float* __restrict__ in, long sInLo, int zdivIn, long sInHi,
    __half* __restrict__ oh,
    long sOutLo, int zdivOut, long sOutHi,
    int K, int ldin)
{
    __shared__ float t[32][33];
    int z = blockIdx.z;
    const float* I = in + (long)(z % zdivIn)*sInLo + (long)(z / zdivIn)*sInHi;
    long ob = (long)(z % zdivOut)*sOutLo + (long)(z / zdivOut)*sOutHi;
    int nx = blockIdx.x*32, ky = blockIdx.y*32;
    int tx = threadIdx.x, ty = threadIdx.y;  // (32,8)
    #pragma unroll
    for (int i = 0; i < 4; i++)
        t[ty + i*8][tx] = I[(long)(ky + ty + i*8)*ldin + nx + tx];
    __syncthreads();
    #pragma unroll
    for (int i = 0; i < 4; i++){
        int n = nx + ty + i*8, k = ky + tx;
        oh[ob + (long)n*K + k] = __float2half_rn(t[tx][ty + i*8]);
    }
}

__global__ __launch_bounds__(256) void embed_k(const int* __restrict__ x,
                                               const float* __restrict__ tok,
                                               const float* __restrict__ pos){
    int t = blockIdx.x;
    int s = t & (SS - 1);
    int id = x[t];
    int j = threadIdx.x * 4;
    float4 a = *(const float4*)(tok + (size_t)id * DD + j);
    float4 p = *(const float4*)(pos + (size_t)s  * DD + j);
    float4 r; r.x = a.x + p.x; r.y = a.y + p.y; r.z = a.z + p.z; r.w = a.w + p.w;
    size_t idx = (size_t)t * DD + j;
    *(float4*)(g_h + idx) = r;
    store_split4(g_hh, g_hl, idx, r);
}

// ================= split-fp16 GEMM via mma.sync (HMMA) ======================
// C[M,N] = Ah*Bh^T (+ Al*Bh^T if Al) (+bias).
// block tile 128x128, Kc=32, 8 warps (warp tile 32x64), cp.async double buffer.
// op0: f32 out + bias.  op1: gelu(out+bias) -> fp16 hi/lo.  op2: bias -> fp16 hi/lo.
#define PADK 40            /* row stride in fp16 elems (80B), conflict-free */
#define OPSZ 10240         /* 128*PADK*2 bytes per operand tile */
#define GM_SMEM (2*3*OPSZ) /* 61440 */
__global__ __launch_bounds__(256, 1) void gemm_mma(
    const __half* __restrict__ Ah, const __half* __restrict__ Al,
    const __half* __restrict__ Bh,
    const float* __restrict__ bias,
    float* __restrict__ Cf,
    __half* __restrict__ Chi, __half* __restrict__ Clo,
    int K_, int ldc, int op)
{
    extern __shared__ char smem[];
    uint32_t sb = smem_to_u32(smem);
    int tid = threadIdx.x, lane = tid & 31, wid = tid >> 5;
    int wm = wid & 3, wn = wid >> 2;            // 4x2 warp grid
    long row0 = (long)blockIdx.x * 128;
    long col0 = (long)blockIdx.y * 128;
    const bool hasL = (Al != 0);

    float acc[2][8][4];
    #pragma unroll
    for (int i = 0; i < 2; i++)
        #pragma unroll
        for (int j = 0; j < 8; j++)
            #pragma unroll
            for (int q = 0; q < 4; q++) acc[i][j][q] = 0.f;

    auto load_chunk = [&](int c, int buf){
        long k0 = (long)c * 32;
        uint32_t base = sb + (uint32_t)buf * (3*OPSZ);
        #pragma unroll
        for (int i = tid; i < 512; i += 256){
            int r = i >> 2, seg = (i & 3) * 8;
            uint32_t soff = (uint32_t)(r * PADK + seg) * 2;
            long ga = (row0 + r) * (long)K_ + k0 + seg;
            long gb = (col0 + r) * (long)K_ + k0 + seg;
            cp16(base + soff,           Ah + ga);
            if (hasL) cp16(base + OPSZ + soff, Al + ga);
            cp16(base + 2*OPSZ + soff,  Bh + gb);
        }
        asm volatile("cp.async.commit_group;" ::: "memory");
    };

    const int NC = K_ >> 5;
    load_chunk(0, 0);

    int m_local = (lane & 7) | (lane & 8);
    int k_off = (lane >> 4) * 8;

    for (int c = 0; c < NC; ++c){
        int buf = c & 1;
        asm volatile("cp.async.wait_group 0;" ::: "memory");
        __syncthreads();
        if (c + 1 < NC) load_chunk(c + 1, buf ^ 1);

        uint32_t base = sb + (uint32_t)buf * (3*OPSZ);
        #pragma unroll
        for (int ks = 0; ks < 2; ++ks){
            uint32_t a_h[2][4], a_l[2][4];
            #pragma unroll
            for (int am = 0; am < 2; ++am){
                uint32_t roff = (uint32_t)((wm*32 + am*16 + m_local) * PADK + ks*16 + k_off) * 2;
                ldm_x4(a_h[am], base + roff);
                if (hasL) ldm_x4(a_l[am], base + OPSZ + roff);
            }
            uint32_t b_h[4][4];
            #pragma unroll
            for (int nt2 = 0; nt2 < 4; ++nt2){
                uint32_t roff = (uint32_t)((wn*64 + nt2*16 + m_local) * PADK + ks*16 + k_off) * 2;
                ldm_x4(b_h[nt2], base + 2*OPSZ + roff);
            }
            #pragma unroll
            for (int mt = 0; mt < 2; ++mt)
                #pragma unroll
                for (int nt = 0; nt < 8; ++nt){
                    int q = nt >> 1, rs = nt & 1;
                    uint32_t bh0 = b_h[q][rs], bh1 = b_h[q][rs+2];
                    mma16816(acc[mt][nt], a_h[mt], bh0, bh1);
                    if (hasL) mma16816(acc[mt][nt], a_l[mt], bh0, bh1);
                }
        }
    }

    // epilogue
    #pragma unroll
    for (int mt = 0; mt < 2; ++mt){
        #pragma unroll
        for (int nt = 0; nt < 8; ++nt){
            long row = row0 + wm*32 + mt*16 + (lane >> 2);
            long col = col0 + wn*64 + nt*8 + (lane & 3)*2;
            float b0 = bias[col], b1 = bias[col+1];
            float v0 = acc[mt][nt][0] + b0, v1 = acc[mt][nt][1] + b1;
            float v2 = acc[mt][nt][2] + b0, v3 = acc[mt][nt][3] + b1;
            if (op == 0){
                *(float2*)(Cf + row*(long)ldc + col)     = make_float2(v0, v1);
                *(float2*)(Cf + (row+8)*(long)ldc + col) = make_float2(v2, v3);
            } else if (op == 1){
                store_split2(Chi, Clo, (size_t)(row*(long)ldc + col),     gelu_f(v0), gelu_f(v1));
                store_split2(Chi, Clo, (size_t)((row+8)*(long)ldc + col), gelu_f(v2), gelu_f(v3));
            } else {
                store_split2(Chi, Clo, (size_t)(row*(long)ldc + col),     v0, v1);
                store_split2(Chi, Clo, (size_t)((row+8)*(long)ldc + col), v2, v3);
            }
        }
    }
}

// ================= attention via mma ========================================
// scores: att[z][S][S] = (Qh+Ql) @ Kh^T, z = h*4+b.  K=64, single smem load.
// causal: blocks entirely above the diagonal are skipped.
#define PADQ 72
#define SC_PLANE (128*PADQ*2)           /* 18432 B */
#define SC_SMEM  (3*SC_PLANE)           /* 55296 B */
__global__ __launch_bounds__(256, 1) void scores_mma(
    const __half* __restrict__ qh, const __half* __restrict__ ql,
    float* __restrict__ att)
{
    long row0 = (long)blockIdx.y * 128;
    long col0 = (long)blockIdx.x * 128;
    if (col0 > row0) return;                        // causal: fully masked block

    extern __shared__ char smem[];
    uint32_t sb = smem_to_u32(smem);
    int z = blockIdx.z; int b = z & 3, hd = z >> 2;
    long qbase = (long)b*SS*(3*DD) + hd*HD;          // q offset
    long kbase = qbase + DD;                          // k offset
    float* C = att + (long)z*SS*SS;

    int tid = threadIdx.x, lane = tid & 31, wid = tid >> 5;
    int wm = wid & 3, wn = wid >> 2;

    #pragma unroll
    for (int i = tid; i < 1024; i += 256){
        int r = i >> 3, u = (i & 7) * 8;
        uint32_t soff = (uint32_t)(r * PADQ + u) * 2;
        cp16(sb + soff,              qh + qbase + (row0 + r)*(long)(3*DD) + u);
        cp16(sb + SC_PLANE + soff,   ql + qbase + (row0 + r)*(long)(3*DD) + u);
        cp16(sb + 2*SC_PLANE + soff, qh + kbase + (col0 + r)*(long)(3*DD) + u);
    }
    asm volatile("cp.async.commit_group;" ::: "memory");
    asm volatile("cp.async.wait_group 0;" ::: "memory");
    __syncthreads();

    int m_local = (lane & 7) | (lane & 8);
    int k_off = (lane >> 4) * 8;

    float acc[2][8][4];
    #pragma unroll
    for (int i = 0; i < 2; i++)
        #pragma unroll
        for (int j = 0; j < 8; j++)
            #pragma unroll
            for (int q = 0; q < 4; q++) acc[i][j][q] = 0.f;

    #pragma unroll
    for (int ks = 0; ks < 4; ++ks){
        uint32_t a_h[2][4], a_l[2][4];
        #pragma unroll
        for (int am = 0; am < 2; ++am){
            uint32_t roff = (uint32_t)((wm*32 + am*16 + m_local) * PADQ + ks*16 + k_off) * 2;
            ldm_x4(a_h[am], sb + roff);
            ldm_x4(a_l[am], sb + SC_PLANE + roff);
        }
        uint32_t b_h[4][4];
        #pragma unroll
        for (int nt2 = 0; nt2 < 4; ++nt2){
            uint32_t roff = (uint32_t)((wn*64 + nt2*16 + m_local) * PADQ + ks*16 + k_off) * 2;
            ldm_x4(b_h[nt2], sb + 2*SC_PLANE + roff);
        }
        #pragma unroll
        for (int mt = 0; mt < 2; ++mt)
            #pragma unroll
            for (int nt = 0; nt < 8; ++nt){
                int q = nt >> 1, rs = nt & 1;
                uint32_t bh0 = b_h[q][rs], bh1 = b_h[q][rs+2];
                mma16816(acc[mt][nt], a_h[mt], bh0, bh1);
                mma16816(acc[mt][nt], a_l[mt], bh0, bh1);
            }
    }

    #pragma unroll
    for (int mt = 0; mt < 2; ++mt){
        #pragma unroll
        for (int nt = 0; nt < 8; ++nt){
            long row = row0 + wm*32 + mt*16 + (lane >> 2);
            long col = col0 + wn*64 + nt*8 + (lane & 3)*2;
            *(float2*)(C + row*(long)SS + col)     = make_float2(acc[mt][nt][0], acc[mt][nt][1]);
            *(float2*)(C + (row+8)*(long)SS + col) = make_float2(acc[mt][nt][2], acc[mt][nt][3]);
        }
    }
}

// softmax: read fp32 scores (causal: only j<=i), write fp16 att up to the
// diagonal block boundary (AV never reads beyond it).
__global__ __launch_bounds__(256) void softmax_k(const float* __restrict__ att,
                                                 __half* __restrict__ atth){
    long rid = blockIdx.x;
    int i = (int)(rid & (SS - 1));
    const float* row = att + rid * (long)SS;
    __half* orow = atth + rid * (long)SS;
    int tid = threadIdx.x;
    __shared__ float shm[8];
    __shared__ float shs[8];

    int j0 = tid * 4;
    float v[4] = {-1e30f, -1e30f, -1e30f, -1e30f};
    if (j0 <= i){
        float4 v4 = *(const float4*)(row + j0);
        v[0]=v4.x; v[1]=v4.y; v[2]=v4.z; v[3]=v4.w;
    }
    float m = -1e30f;
    #pragma unroll
    for (int c = 0; c < 4; c++){
        v[c] = (j0 + c <= i) ? v[c] * 0.125f : -1e30f;
        m = fmaxf(m, v[c]);
    }
    int lane = tid & 31, wid = tid >> 5;
    float wm = warpMax(m);
    if (lane == 0) shm[wid] = wm;
    __syncthreads();
    if (tid < 32){
        float r = (tid < 8) ? shm[tid] : -1e30f;
        r = warpMax(r);
        if (tid == 0) shm[0] = r;
    }
    __syncthreads();
    m = shm[0];
    float s = 0.f;
    #pragma unroll
    for (int c = 0; c < 4; c++){ v[c] = expf(v[c] - m); s += v[c]; }
    float bs = blockSum256(s, shs);
    float inv = 1.f / bs;
    if (j0 < ((i & ~127) + 128)){
        __half2 o0 = __halves2half2(__float2half_rn(v[0]*inv), __float2half_rn(v[1]*inv));
        __half2 o1 = __halves2half2(__float2half_rn(v[2]*inv), __float2half_rn(v[3]*inv));
        *(__half2*)(orow + j0)     = o0;
        *(__half2*)(orow + j0 + 2) = o1;
    }
}

// AV: o = att_fp16[z] @ (Vh+Vl)[z]; causal: only K-chunks up to the diagonal.
#define AV_ATT  (128*PADQ*2)                 /* 18432 B */
#define AV_V    (64*PADQ*2)                  /* 9216 B  */
#define AV_BUF  (AV_ATT + 2*AV_V)            /* 36864 B */
#define AV_SMEM (2*AV_BUF)                   /* 73728 B */
__global__ __launch_bounds__(256, 1) void av_mma(
    const __half* __restrict__ atth,
    const __half* __restrict__ qkvh, const __half* __restrict__ qkvl,
    __half* __restrict__ oh, __half* __restrict__ ol)
{
    extern __shared__ char smem[];
    uint32_t sb = smem_to_u32(smem);
    int z = blockIdx.z; int b = z & 3, hd = z >> 2;
    const __half* A = atth + (long)z*SS*SS;
    long vbase = (long)b*SS*(3*DD) + 2*DD + hd*HD;
    long obase = (long)b*SS*DD + hd*HD;

    int tid = threadIdx.x, lane = tid & 31, wid = tid >> 5;
    int wm = wid & 3, wn = wid >> 2;            // 4 x 2; warp tile 32x32
    long row0 = (long)blockIdx.y * 128;
    const int cmax = (int)(row0 >> 6) + 2;      // causal chunk bound

    float acc[2][4][4];
    #pragma unroll
    for (int i = 0; i < 2; i++)
        #pragma unroll
        for (int j = 0; j < 4; j++)
            #pragma unroll
            for (int q = 0; q < 4; q++) acc[i][j][q] = 0.f;

    auto load_chunk = [&](int c, int buf){
        long k0 = (long)c * 64;
        uint32_t base = sb + (uint32_t)buf * AV_BUF;
        #pragma unroll
        for (int i = tid; i < 1024; i += 256){     // att: 128 rows x 64
            int r = i >> 3, u = (i & 7) * 8;
            uint32_t soff = (uint32_t)(r * PADQ + u) * 2;
            cp16(base + soff, A + (row0 + r)*(long)SS + k0 + u);
        }
        #pragma unroll
        for (int i = tid; i < 512; i += 256){      // Vh, Vl: 64 rows x 64
            int r = i >> 3, u = (i & 7) * 8;
            uint32_t soff = (uint32_t)(r * PADQ + u) * 2;
            long g = vbase + (k0 + r)*(long)(3*DD) + u;
            cp16(base + AV_ATT + soff,        qkvh + g);
            cp16(base + AV_ATT + AV_V + soff, qkvl + g);
        }
        asm volatile("cp.async.commit_group;" ::: "memory");
    };

    load_chunk(0, 0);

    int m_local = (lane & 7) | (lane & 8);
    int k_off = (lane >> 4) * 8;
    int t_row = lane & 15, t_col = (lane >> 4) * 8;   // trans ldmatrix addressing

    for (int c = 0; c < cmax; ++c){
        int buf = c & 1;
        asm volatile("cp.async.wait_group 0;" ::: "memory");
        __syncthreads();
        if (c + 1 < cmax) load_chunk(c + 1, buf ^ 1);

        uint32_t base = sb + (uint32_t)buf * AV_BUF;
        #pragma unroll
        for (int ks = 0; ks < 4; ++ks){
            uint32_t a_f[2][4];
            #pragma unroll
            for (int am = 0; am < 2; ++am){
                uint32_t roff = (uint32_t)((wm*32 + am*16 + m_local) * PADQ + ks*16 + k_off) * 2;
                ldm_x4(a_f[am], base + roff);
            }
            uint32_t b_h[2][4], b_l[2][4];
            #pragma unroll
            for (int g2 = 0; g2 < 2; ++g2){
                uint32_t voff = (uint32_t)((ks*16 + t_row) * PADQ + wn*32 + g2*16 + t_col) * 2;
                ldm_x4_t(b_h[g2], base + AV_ATT + voff);
                ldm_x4_t(b_l[g2], base + AV_ATT + AV_V + voff);
            }
            #pragma unroll
            for (int mt = 0; mt < 2; ++mt)
                #pragma unroll
                for (int nt = 0; nt < 4; ++nt){
                    int g2 = nt >> 1, sub = (nt & 1) * 2;
                    mma16816(acc[mt][nt], a_f[mt], b_h[g2][sub], b_h[g2][sub+1]);
                    mma16816(acc[mt][nt], a_f[mt], b_l[g2][sub], b_l[g2][sub+1]);
                }
        }
    }

    #pragma unroll
    for (int mt = 0; mt < 2; ++mt){
        #pragma unroll
        for (int nt = 0; nt < 4; ++nt){
            long row = row0 + wm*32 + mt*16 + (lane >> 2);
            long col = wn*32 + nt*8 + (lane & 3)*2;
            size_t idx = (size_t)(obase + row*(long)DD + col);
            store_split2(oh, ol, idx,          acc[mt][nt][0], acc[mt][nt][1]);
            store_split2(oh, ol, idx + 8*DD,   acc[mt][nt][2], acc[mt][nt][3]);
        }
    }
}

// ================= pointwise ================================================
__global__ __launch_bounds__(256) void add_ln_k(float* __restrict__ h,
                                                const float* __restrict__ delta,
                                                const float* __restrict__ w,
                                                const float* __restrict__ b){
    long t = blockIdx.x;
    int tid = threadIdx.x;
    int j = tid * 4;
    __shared__ float sh[8];
    float4 hv = *(const float4*)(h + t * DD + j);
    float4 dv = *(const float4*)(delta + t * DD + j);
    float x[4] = {hv.x + dv.x, hv.y + dv.y, hv.z + dv.z, hv.w + dv.w};
    float s = x[0] + x[1] + x[2] + x[3];
    float mean = blockSum256(s, sh) * (1.f / DD);
    float sq = 0.f;
    #pragma unroll
    for (int c = 0; c < 4; c++){ float d = x[c] - mean; sq += d * d; }
    float var = blockSum256(sq, sh) * (1.f / DD);
    float inv = rsqrtf(var + 1e-5f);
    float4 o;
    o.x = (x[0]-mean)*inv*w[j+0] + b[j+0];
    o.y = (x[1]-mean)*inv*w[j+1] + b[j+1];
    o.z = (x[2]-mean)*inv*w[j+2] + b[j+2];
    o.w = (x[3]-mean)*inv*w[j+3] + b[j+3];
    size_t idx = (size_t)t * DD + j;
    *(float4*)(h + idx) = o;
    store_split4(g_hh, g_hl, idx, o);
}

__global__ __launch_bounds__(256) void copy_h_k(float* __restrict__ dst){
    size_t idx = ((size_t)blockIdx.x * 256 + threadIdx.x) * 4;
    *(float4*)(dst + idx) = *(const float4*)(g_h + idx);
}

// ================= launch ===================================================
extern "C" void kernel_launch(void* const* d_in, const int* in_sizes, int n_in,
                              void* d_out, int out_size)
{
    const int*   x    = (const int*)  d_in[0];
    const float* tok  = (const float*)d_in[1];
    const float* pos  = (const float*)d_in[2];
    const float* Wq   = (const float*)d_in[3];
    const float* bq   = (const float*)d_in[4];
    const float* Wk   = (const float*)d_in[5];
    const float* bk   = (const float*)d_in[6];
    const float* Wv   = (const float*)d_in[7];
    const float* bv   = (const float*)d_in[8];
    const float* Wo   = (const float*)d_in[9];
    const float* bo   = (const float*)d_in[10];
    const float* ln1w = (const float*)d_in[11];
    const float* ln1b = (const float*)d_in[12];
    const float* ln2w = (const float*)d_in[13];
    const float* ln2b = (const float*)d_in[14];
    const float* W1   = (const float*)d_in[15];
    const float* b1   = (const float*)d_in[16];
    const float* W2   = (const float*)d_in[17];
    const float* b2   = (const float*)d_in[18];
    const float* Wout = (const float*)d_in[19];
    const float* bout = (const float*)d_in[20];
    float* out = (float*)d_out;

    static int attr_set = 0;
    if (!attr_set){
        cudaFuncSetAttribute(gemm_mma,   cudaFuncAttributeMaxDynamicSharedMemorySize, GM_SMEM);
        cudaFuncSetAttribute(scores_mma, cudaFuncAttributeMaxDynamicSharedMemorySize, SC_SMEM);
        cudaFuncSetAttribute(av_mma,     cudaFuncAttributeMaxDynamicSharedMemorySize, AV_SMEM);
        attr_set = 1;
    }

    float *h, *att, *t, *bqkv;
    __half *atth, *hh,*hl,*qh,*ql,*oh,*ol,*ffh,*ffl;
    __half *wqh,*woh,*w1h,*w2h,*wouth;
    cudaGetSymbolAddress((void**)&h,    g_h);
    cudaGetSymbolAddress((void**)&att,  g_att);
    cudaGetSymbolAddress((void**)&atth, g_atth);
    cudaGetSymbolAddress((void**)&t,    g_t);
    cudaGetSymbolAddress((void**)&bqkv, g_bqkv);
    cudaGetSymbolAddress((void**)&hh,   g_hh);
    cudaGetSymbolAddress((void**)&hl,   g_hl);
    cudaGetSymbolAddress((void**)&qh,   g_qkvh);
    cudaGetSymbolAddress((void**)&ql,   g_qkvl);
    cudaGetSymbolAddress((void**)&oh,   g_oh);
    cudaGetSymbolAddress((void**)&ol,   g_ol);
    cudaGetSymbolAddress((void**)&ffh,  g_ffh);
    cudaGetSymbolAddress((void**)&ffl,  g_ffl);
    cudaGetSymbolAddress((void**)&wqh,  g_wqkv_h);
    cudaGetSymbolAddress((void**)&woh,  g_wo_h);
    cudaGetSymbolAddress((void**)&w1h,  g_w1_h);
    cudaGetSymbolAddress((void**)&w2h,  g_w2_h);
    cudaGetSymbolAddress((void**)&wouth,g_wout_h);

    dim3 tsb(32, 8);
    // --- weight prep: transpose + fp16 cast ---
    packbias_k<<<24, 256>>>(bq, bk, bv);
    tsplit_k<<<dim3(2,32,32), tsb>>>(Wq, (long)DD*HD, 32, 0,
        wqh + 0*DD*DD, (long)HD*DD, 16, (long)3*DD*DD, DD, HD);
    tsplit_k<<<dim3(2,32,32), tsb>>>(Wk, (long)DD*HD, 32, 0,
        wqh + 1*DD*DD, (long)HD*DD, 16, (long)3*DD*DD, DD, HD);
    tsplit_k<<<dim3(2,32,32), tsb>>>(Wv, (long)DD*HD, 32, 0,
        wqh + 2*DD*DD, (long)HD*DD, 16, (long)3*DD*DD, DD, HD);
    tsplit_k<<<dim3(32,32,2), tsb>>>(Wo, (long)DD*DD, 2, 0,
        woh, (long)DD*DD, 2, 0, DD, DD);
    tsplit_k<<<dim3(128,32,2), tsb>>>(W1, (long)DD*FFD, 2, 0,
        w1h, (long)FFD*DD, 2, 0, DD, FFD);
    tsplit_k<<<dim3(32,128,2), tsb>>>(W2, (long)FFD*DD, 2, 0,
        w2h, (long)DD*FFD, 2, 0, FFD, DD);
    tsplit_k<<<dim3(1000,32,1), tsb>>>(Wout, 0, 1, 0,
        wouth, 0, 1, 0, DD, VV);

    embed_k<<<BS, 256>>>(x, tok, pos);

    for (int l = 0; l < LL; l++){
        // QKV: [4096,1024] x [1024,3072] -> fp16 hi/lo planes
        gemm_mma<<<dim3(BS/128, 3*DD/128), 256, GM_SMEM>>>(
            hh, hl, wqh + (long)l*3*DD*DD,
            bqkv + (long)l*3*DD, 0, qh, ql, DD, 3*DD, 2);
        scores_mma<<<dim3(SS/128, SS/128, HH*BB), 256, SC_SMEM>>>(qh, ql, att);
        softmax_k<<<HH*BB*SS, 256>>>(att, atth);
        av_mma<<<dim3(1, SS/128, HH*BB), 256, AV_SMEM>>>(atth, qh, ql, oh, ol);
        // Wo
        gemm_mma<<<dim3(BS/128, DD/128), 256, GM_SMEM>>>(
            oh, ol, woh + (long)l*DD*DD,
            bo + (long)l*DD, t, 0, 0, DD, DD, 0);
        add_ln_k<<<BS, 256>>>(h, t, ln1w + (long)l*DD, ln1b + (long)l*DD);
        // W1 + GELU -> ff (fp16 hi/lo)
        gemm_mma<<<dim3(BS/128, FFD/128), 256, GM_SMEM>>>(
            hh, hl, w1h + (long)l*FFD*DD,
            b1 + (long)l*FFD, 0, ffh, ffl, DD, FFD, 1);
        // W2
        gemm_mma<<<dim3(BS/128, DD/128), 256, GM_SMEM>>>(
            ffh, ffl, w2h + (long)l*DD*FFD,
            b2 + (long)l*DD, t, 0, 0, FFD, DD, 0);
        add_ln_k<<<BS, 256>>>(h, t, ln2w + (long)l*DD, ln2b + (long)l*DD);
    }

    // logits: single-fp16 A (Al = null) — halves the largest GEMM
    gemm_mma<<<dim3(BS/128, VV/128), 256, GM_SMEM>>>(
        hh, (const __half*)0, wouth, bout, out, 0, 0, DD, VV, 0);
    copy_h_k<<<(BS*DD)/1024, 256>>>(out + (long)BS*VV);
}

// round 8
// speedup vs baseline: 5.8482x; 1.4173x over previous
#include <cuda_runtime.h>
#include <cuda_fp16.h>
#include <math.h>
#include <stdint.h>

#define LL 2
#define HH 16
#define DD 1024
#define HD 64
#define FFD 4096
#define VV 32000
#define SS 1024
#define BB 4
#define BS (BB*SS)   /* 4096 */

// ================= scratch (device globals) =================================
__device__ float g_h  [(size_t)BS*DD];
__device__ float g_att[(size_t)BB*HH*SS*SS];   // [h*4+b][S][S] fp32 scores
__device__ __half g_atth[(size_t)BB*HH*SS*SS]; // fp16 softmaxed att
__device__ float g_t  [(size_t)BS*DD];

__device__ __half g_hh [(size_t)BS*DD];
__device__ __half g_qkvh[(size_t)BS*3*DD];
__device__ __half g_oh [(size_t)BS*DD];
__device__ __half g_ffh[(size_t)BS*FFD];

__device__ __half g_wqkv_h[(size_t)LL*3*DD*DD];
__device__ __half g_wo_h [(size_t)LL*DD*DD];
__device__ __half g_w1_h [(size_t)LL*FFD*DD];
__device__ __half g_w2_h [(size_t)LL*DD*FFD];
__device__ __half g_wout_h[(size_t)VV*DD];
__device__ float g_bqkv[(size_t)LL*3*DD];

// ================= small helpers ============================================
__device__ __forceinline__ uint32_t smem_to_u32(const void* smem_ptr) {
    uint32_t addr;
    asm("{ .reg .u64 tmp; cvta.to.shared.u64 tmp, %1; cvt.u32.u64 %0, tmp; }"
        : "=r"(addr) : "l"(smem_ptr));
    return addr;
}
__device__ __forceinline__ void cp16(uint32_t d, const void* s){
    asm volatile("cp.async.cg.shared.global [%0], [%1], 16;" :: "r"(d), "l"(s) : "memory");
}
__device__ __forceinline__ void ldm_x4(uint32_t* r, uint32_t addr){
    asm volatile("ldmatrix.sync.aligned.m8n8.x4.shared.b16 {%0,%1,%2,%3}, [%4];"
        : "=r"(r[0]), "=r"(r[1]), "=r"(r[2]), "=r"(r[3]) : "r"(addr));
}
__device__ __forceinline__ void ldm_x4_t(uint32_t* r, uint32_t addr){
    asm volatile("ldmatrix.sync.aligned.m8n8.x4.trans.shared.b16 {%0,%1,%2,%3}, [%4];"
        : "=r"(r[0]), "=r"(r[1]), "=r"(r[2]), "=r"(r[3]) : "r"(addr));
}
__device__ __forceinline__ void mma16816(float* c, const uint32_t* a, uint32_t b0, uint32_t b1){
    asm volatile("mma.sync.aligned.m16n8k16.row.col.f32.f16.f16.f32 "
        "{%0,%1,%2,%3}, {%4,%5,%6,%7}, {%8,%9}, {%0,%1,%2,%3};"
        : "+f"(c[0]), "+f"(c[1]), "+f"(c[2]), "+f"(c[3])
        : "r"(a[0]), "r"(a[1]), "r"(a[2]), "r"(a[3]), "r"(b0), "r"(b1));
}
__device__ __forceinline__ float warpSum(float v){
    #pragma unroll
    for (int o = 16; o > 0; o >>= 1) v += __shfl_xor_sync(0xffffffffu, v, o);
    return v;
}
__device__ __forceinline__ float warpMax(float v){
    #pragma unroll
    for (int o = 16; o > 0; o >>= 1) v = fmaxf(v, __shfl_xor_sync(0xffffffffu, v, o));
    return v;
}
__device__ __forceinline__ float blockSum256(float v, float* sh){
    int lane = threadIdx.x & 31, wid = threadIdx.x >> 5;
    v = warpSum(v);
    if (lane == 0) sh[wid] = v;
    __syncthreads();
    float r = (threadIdx.x < 8) ? sh[threadIdx.x] : 0.f;
    if (threadIdx.x < 32) { r = warpSum(r); if (threadIdx.x == 0) sh[0] = r; }
    __syncthreads();
    float res = sh[0];
    __syncthreads();
    return res;
}
__device__ __forceinline__ float gelu_f(float x){
    return 0.5f * x * (1.0f + erff(x * 0.70710678118654752f));
}
__device__ __forceinline__ void store_half4(__half* p, size_t idx, float4 v){
    *(__half2*)(p+idx)   = __halves2half2(__float2half_rn(v.x), __float2half_rn(v.y));
    *(__half2*)(p+idx+2) = __halves2half2(__float2half_rn(v.z), __float2half_rn(v.w));
}
__device__ __forceinline__ void store_half2(__half* p, size_t idx, float a, float b){
    *(__half2*)(p+idx) = __halves2half2(__float2half_rn(a), __float2half_rn(b));
}

// ================= prep kernels =============================================
__global__ __launch_bounds__(256) void packbias_k(const float* __restrict__ bq,
                                                  const float* __restrict__ bk,
                                                  const float* __restrict__ bv){
    int i = blockIdx.x*256 + threadIdx.x;            // 0..6143
    int l = i / (3*DD), n = i % (3*DD);
    float v = (n < DD) ? bq[l*DD + n] : (n < 2*DD) ? bk[l*DD + n - DD] : bv[l*DD + n - 2*DD];
    g_bqkv[i] = v;
}

// transposed fp16 cast: out[n][k] = fp16(in_z[k][n]); in [K][ldin], out ld=K
__global__ __launch_bounds__(256) void tsplit_k(
    const float* __restrict__ in, long sInLo, int zdivIn, long sInHi,
    __half* __restrict__ oh,
    long sOutLo, int zdivOut, long sOutHi,
    int K, int ldin)
{
    __shared__ float t[32][33];
    int z = blockIdx.z;
    const float* I = in + (long)(z % zdivIn)*sInLo + (long)(z / zdivIn)*sInHi;
    long ob = (long)(z % zdivOut)*sOutLo + (long)(z / zdivOut)*sOutHi;
    int nx = blockIdx.x*32, ky = blockIdx.y*32;
    int tx = threadIdx.x, ty = threadIdx.y;  // (32,8)
    #pragma unroll
    for (int i = 0; i < 4; i++)
        t[ty + i*8][tx] = I[(long)(ky + ty + i*8)*ldin + nx + tx];
    __syncthreads();
    #pragma unroll
    for (int i = 0; i < 4; i++){
        int n = nx + ty + i*8, k = ky + tx;
        oh[ob + (long)n*K + k] = __float2half_rn(t[tx][ty + i*8]);
    }
}

__global__ __launch_bounds__(256) void embed_k(const int* __restrict__ x,
                                               const float* __restrict__ tok,
                                               const float* __restrict__ pos){
    int t = blockIdx.x;
    int s = t & (SS - 1);
    int id = x[t];
    int j = threadIdx.x * 4;
    float4 a = *(const float4*)(tok + (size_t)id * DD + j);
    float4 p = *(const float4*)(pos + (size_t)s  * DD + j);
    float4 r; r.x = a.x + p.x; r.y = a.y + p.y; r.z = a.z + p.z; r.w = a.w + p.w;
    size_t idx = (size_t)t * DD + j;
    *(float4*)(g_h + idx) = r;
    store_half4(g_hh, idx, r);
}

// ================= fp16 GEMM via mma.sync (HMMA) ============================
// C[M,N] = A*B^T (+bias).  A fp16 [M][K], B fp16 [N][K].
// block tile 128x128, Kc=32, 8 warps (warp tile 32x64), cp.async double buffer.
// op0: f32 out + bias.  op1: gelu(out+bias) -> fp16.  op2: bias -> fp16.
#define PADK 40            /* row stride in fp16 elems (80B), conflict-free */
#define OPSZ 10240         /* 128*PADK*2 bytes per operand tile */
#define GM_SMEM (2*2*OPSZ) /* 40960 */
__global__ __launch_bounds__(256, 2) void gemm_mma(
    const __half* __restrict__ A, const __half* __restrict__ B,
    const float* __restrict__ bias,
    float* __restrict__ Cf, __half* __restrict__ Ch,
    int K_, int ldc, int op)
{
    extern __shared__ char smem[];
    uint32_t sb = smem_to_u32(smem);
    int tid = threadIdx.x, lane = tid & 31, wid = tid >> 5;
    int wm = wid & 3, wn = wid >> 2;            // 4x2 warp grid
    long row0 = (long)blockIdx.x * 128;
    long col0 = (long)blockIdx.y * 128;

    float acc[2][8][4];
    #pragma unroll
    for (int i = 0; i < 2; i++)
        #pragma unroll
        for (int j = 0; j < 8; j++)
            #pragma unroll
            for (int q = 0; q < 4; q++) acc[i][j][q] = 0.f;

    auto load_chunk = [&](int c, int buf){
        long k0 = (long)c * 32;
        uint32_t base = sb + (uint32_t)buf * (2*OPSZ);
        #pragma unroll
        for (int i = tid; i < 512; i += 256){
            int r = i >> 2, seg = (i & 3) * 8;
            uint32_t soff = (uint32_t)(r * PADK + seg) * 2;
            cp16(base + soff,        A + (row0 + r) * (long)K_ + k0 + seg);
            cp16(base + OPSZ + soff, B + (col0 + r) * (long)K_ + k0 + seg);
        }
        asm volatile("cp.async.commit_group;" ::: "memory");
    };

    const int NC = K_ >> 5;
    load_chunk(0, 0);

    int m_local = (lane & 7) | (lane & 8);
    int k_off = (lane >> 4) * 8;

    for (int c = 0; c < NC; ++c){
        int buf = c & 1;
        asm volatile("cp.async.wait_group 0;" ::: "memory");
        __syncthreads();
        if (c + 1 < NC) load_chunk(c + 1, buf ^ 1);

        uint32_t base = sb + (uint32_t)buf * (2*OPSZ);
        #pragma unroll
        for (int ks = 0; ks < 2; ++ks){
            uint32_t a_h[2][4];
            #pragma unroll
            for (int am = 0; am < 2; ++am){
                uint32_t roff = (uint32_t)((wm*32 + am*16 + m_local) * PADK + ks*16 + k_off) * 2;
                ldm_x4(a_h[am], base + roff);
            }
            uint32_t b_h[4][4];
            #pragma unroll
            for (int nt2 = 0; nt2 < 4; ++nt2){
                uint32_t roff = (uint32_t)((wn*64 + nt2*16 + m_local) * PADK + ks*16 + k_off) * 2;
                ldm_x4(b_h[nt2], base + OPSZ + roff);
            }
            #pragma unroll
            for (int mt = 0; mt < 2; ++mt)
                #pragma unroll
                for (int nt = 0; nt < 8; ++nt){
                    int q = nt >> 1, rs = nt & 1;
                    mma16816(acc[mt][nt], a_h[mt], b_h[q][rs], b_h[q][rs+2]);
                }
        }
    }

    // epilogue
    #pragma unroll
    for (int mt = 0; mt < 2; ++mt){
        #pragma unroll
        for (int nt = 0; nt < 8; ++nt){
            long row = row0 + wm*32 + mt*16 + (lane >> 2);
            long col = col0 + wn*64 + nt*8 + (lane & 3)*2;
            float b0 = bias[col], b1 = bias[col+1];
            float v0 = acc[mt][nt][0] + b0, v1 = acc[mt][nt][1] + b1;
            float v2 = acc[mt][nt][2] + b0, v3 = acc[mt][nt][3] + b1;
            if (op == 0){
                *(float2*)(Cf + row*(long)ldc + col)     = make_float2(v0, v1);
                *(float2*)(Cf + (row+8)*(long)ldc + col) = make_float2(v2, v3);
            } else if (op == 1){
                store_half2(Ch, (size_t)(row*(long)ldc + col),     gelu_f(v0), gelu_f(v1));
                store_half2(Ch, (size_t)((row+8)*(long)ldc + col), gelu_f(v2), gelu_f(v3));
            } else {
                store_half2(Ch, (size_t)(row*(long)ldc + col),     v0, v1);
                store_half2(Ch, (size_t)((row+8)*(long)ldc + col), v2, v3);
            }
        }
    }
}

// ================= attention via mma ========================================
// scores: att[z][S][S] = Q @ K^T, z = h*4+b.  K=64, single smem load.
// causal: blocks entirely above the diagonal are skipped.
#define PADQ 72
#define SC_PLANE (128*PADQ*2)           /* 18432 B */
#define SC_SMEM  (2*SC_PLANE)           /* 36864 B */
__global__ __launch_bounds__(256, 2) void scores_mma(
    const __half* __restrict__ qkvh, float* __restrict__ att)
{
    long row0 = (long)blockIdx.y * 128;
    long col0 = (long)blockIdx.x * 128;
    if (col0 > row0) return;                        // causal: fully masked block

    extern __shared__ char smem[];
    uint32_t sb = smem_to_u32(smem);
    int z = blockIdx.z; int b = z & 3, hd = z >> 2;
    long qbase = (long)b*SS*(3*DD) + hd*HD;          // q offset
    long kbase = qbase + DD;                          // k offset
    float* C = att + (long)z*SS*SS;

    int tid = threadIdx.x, lane = tid & 31, wid = tid >> 5;
    int wm = wid & 3, wn = wid >> 2;

    #pragma unroll
    for (int i = tid; i < 1024; i += 256){
        int r = i >> 3, u = (i & 7) * 8;
        uint32_t soff = (uint32_t)(r * PADQ + u) * 2;
        cp16(sb + soff,            qkvh + qbase + (row0 + r)*(long)(3*DD) + u);
        cp16(sb + SC_PLANE + soff, qkvh + kbase + (col0 + r)*(long)(3*DD) + u);
    }
    asm volatile("cp.async.commit_group;" ::: "memory");
    asm volatile("cp.async.wait_group 0;" ::: "memory");
    __syncthreads();

    int m_local = (lane & 7) | (lane & 8);
    int k_off = (lane >> 4) * 8;

    float acc[2][8][4];
    #pragma unroll
    for (int i = 0; i < 2; i++)
        #pragma unroll
        for (int j = 0; j < 8; j++)
            #pragma unroll
            for (int q = 0; q < 4; q++) acc[i][j][q] = 0.f;

    #pragma unroll
    for (int ks = 0; ks < 4; ++ks){
        uint32_t a_h[2][4];
        #pragma unroll
        for (int am = 0; am < 2; ++am){
            uint32_t roff = (uint32_t)((wm*32 + am*16 + m_local) * PADQ + ks*16 + k_off) * 2;
            ldm_x4(a_h[am], sb + roff);
        }
        uint32_t b_h[4][4];
        #pragma unroll
        for (int nt2 = 0; nt2 < 4; ++nt2){
            uint32_t roff = (uint32_t)((wn*64 + nt2*16 + m_local) * PADQ + ks*16 + k_off) * 2;
            ldm_x4(b_h[nt2], sb + SC_PLANE + roff);
        }
        #pragma unroll
        for (int mt = 0; mt < 2; ++mt)
            #pragma unroll
            for (int nt = 0; nt < 8; ++nt){
                int q = nt >> 1, rs = nt & 1;
                mma16816(acc[mt][nt], a_h[mt], b_h[q][rs], b_h[q][rs+2]);
            }
    }

    #pragma unroll
    for (int mt = 0; mt < 2; ++mt){
        #pragma unroll
        for (int nt = 0; nt < 8; ++nt){
            long row = row0 + wm*32 + mt*16 + (lane >> 2);
            long col = col0 + wn*64 + nt*8 + (lane & 3)*2;
            *(float2*)(C + row*(long)SS + col)     = make_float2(acc[mt][nt][0], acc[mt][nt][1]);
            *(float2*)(C + (row+8)*(long)SS + col) = make_float2(acc[mt][nt][2], acc[mt][nt][3]);
        }
    }
}

// softmax: read fp32 scores (causal: only j<=i), write fp16 att up to the
// diagonal block boundary (AV never reads beyond it).
__global__ __launch_bounds__(256) void softmax_k(const float* __restrict__ att,
                                                 __half* __restrict__ atth){
    long rid = blockIdx.x;
    int i = (int)(rid & (SS - 1));
    const float* row = att + rid * (long)SS;
    __half* orow = atth + rid * (long)SS;
    int tid = threadIdx.x;
    __shared__ float shm[8];
    __shared__ float shs[8];

    int j0 = tid * 4;
    float v[4] = {-1e30f, -1e30f, -1e30f, -1e30f};
    if (j0 <= i){
        float4 v4 = *(const float4*)(row + j0);
        v[0]=v4.x; v[1]=v4.y; v[2]=v4.z; v[3]=v4.w;
    }
    float m = -1e30f;
    #pragma unroll
    for (int c = 0; c < 4; c++){
        v[c] = (j0 + c <= i) ? v[c] * 0.125f : -1e30f;
        m = fmaxf(m, v[c]);
    }
    int lane = tid & 31, wid = tid >> 5;
    float wm = warpMax(m);
    if (lane == 0) shm[wid] = wm;
    __syncthreads();
    if (tid < 32){
        float r = (tid < 8) ? shm[tid] : -1e30f;
        r = warpMax(r);
        if (tid == 0) shm[0] = r;
    }
    __syncthreads();
    m = shm[0];
    float s = 0.f;
    #pragma unroll
    for (int c = 0; c < 4; c++){ v[c] = expf(v[c] - m); s += v[c]; }
    float bs = blockSum256(s, shs);
    float inv = 1.f / bs;
    if (j0 < ((i & ~127) + 128)){
        *(__half2*)(orow + j0)     = __halves2half2(__float2half_rn(v[0]*inv), __float2half_rn(v[1]*inv));
        *(__half2*)(orow + j0 + 2) = __halves2half2(__float2half_rn(v[2]*inv), __float2half_rn(v[3]*inv));
    }
}

// AV: o = att_fp16[z] @ V[z]; causal: only K-chunks up to the diagonal.
#define AV_ATT  (128*PADQ*2)                 /* 18432 B */
#define AV_V    (64*PADQ*2)                  /* 9216 B  */
#define AV_BUF  (AV_ATT + AV_V)              /* 27648 B */
#define AV_SMEM (2*AV_BUF)                   /* 55296 B */
__global__ __launch_bounds__(256, 2) void av_mma(
    const __half* __restrict__ atth,
    const __half* __restrict__ qkvh,
    __half* __restrict__ oh)
{
    extern __shared__ char smem[];
    uint32_t sb = smem_to_u32(smem);
    int z = blockIdx.z; int b = z & 3, hd = z >> 2;
    const __half* A = atth + (long)z*SS*SS;
    long vbase = (long)b*SS*(3*DD) + 2*DD + hd*HD;
    long obase = (long)b*SS*DD + hd*HD;

    int tid = threadIdx.x, lane = tid & 31, wid = tid >> 5;
    int wm = wid & 3, wn = wid >> 2;            // 4 x 2; warp tile 32x32
    long row0 = (long)blockIdx.y * 128;
    const int cmax = (int)(row0 >> 6) + 2;      // causal chunk bound

    float acc[2][4][4];
    #pragma unroll
    for (int i = 0; i < 2; i++)
        #pragma unroll
        for (int j = 0; j < 4; j++)
            #pragma unroll
            for (int q = 0; q < 4; q++) acc[i][j][q] = 0.f;

    auto load_chunk = [&](int c, int buf){
        long k0 = (long)c * 64;
        uint32_t base = sb + (uint32_t)buf * AV_BUF;
        #pragma unroll
        for (int i = tid; i < 1024; i += 256){     // att: 128 rows x 64
            int r = i >> 3, u = (i & 7) * 8;
            uint32_t soff = (uint32_t)(r * PADQ + u) * 2;
            cp16(base + soff, A + (row0 + r)*(long)SS + k0 + u);
        }
        #pragma unroll
        for (int i = tid; i < 512; i += 256){      // V: 64 rows x 64
            int r = i >> 3, u = (i & 7) * 8;
            uint32_t soff = (uint32_t)(r * PADQ + u) * 2;
            cp16(base + AV_ATT + soff, qkvh + vbase + (k0 + r)*(long)(3*DD) + u);
        }
        asm volatile("cp.async.commit_group;" ::: "memory");
    };

    load_chunk(0, 0);

    int m_local = (lane & 7) | (lane & 8);
    int k_off = (lane >> 4) * 8;
    int t_row = lane & 15, t_col = (lane >> 4) * 8;   // trans ldmatrix addressing

    for (int c = 0; c < cmax; ++c){
        int buf = c & 1;
        asm volatile("cp.async.wait_group 0;" ::: "memory");
        __syncthreads();
        if (c + 1 < cmax) load_chunk(c + 1, buf ^ 1);

        uint32_t base = sb + (uint32_t)buf * AV_BUF;
        #pragma unroll
        for (int ks = 0; ks < 4; ++ks){
            uint32_t a_f[2][4];
            #pragma unroll
            for (int am = 0; am < 2; ++am){
                uint32_t roff = (uint32_t)((wm*32 + am*16 + m_local) * PADQ + ks*16 + k_off) * 2;
                ldm_x4(a_f[am], base + roff);
            }
            uint32_t b_h[2][4];
            #pragma unroll
            for (int g2 = 0; g2 < 2; ++g2){
                uint32_t voff = (uint32_t)((ks*16 + t_row) * PADQ + wn*32 + g2*16 + t_col) * 2;
                ldm_x4_t(b_h[g2], base + AV_ATT + voff);
            }
            #pragma unroll
            for (int mt = 0; mt < 2; ++mt)
                #pragma unroll
                for (int nt = 0; nt < 4; ++nt){
                    int g2 = nt >> 1, sub = (nt & 1) * 2;
                    mma16816(acc[mt][nt], a_f[mt], b_h[g2][sub], b_h[g2][sub+1]);
                }
        }
    }

    #pragma unroll
    for (int mt = 0; mt < 2; ++mt){
        #pragma unroll
        for (int nt = 0; nt < 4; ++nt){
            long row = row0 + wm*32 + mt*16 + (lane >> 2);
            long col = wn*32 + nt*8 + (lane & 3)*2;
            size_t idx = (size_t)(obase + row*(long)DD + col);
            store_half2(oh, idx,        acc[mt][nt][0], acc[mt][nt][1]);
            store_half2(oh, idx + 8*DD, acc[mt][nt][2], acc[mt][nt][3]);
        }
    }
}

// ================= pointwise ================================================
__global__ __launch_bounds__(256) void add_ln_k(float* __restrict__ h,
                                                const float* __restrict__ delta,
                                                const float* __restrict__ w,
                                                const float* __restrict__ b){
    long t = blockIdx.x;
    int tid = threadIdx.x;
    int j = tid * 4;
    __shared__ float sh[8];
    float4 hv = *(const float4*)(h + t * DD + j);
    float4 dv = *(const float4*)(delta + t * DD + j);
    float x[4] = {hv.x + dv.x, hv.y + dv.y, hv.z + dv.z, hv.w + dv.w};
    float s = x[0] + x[1] + x[2] + x[3];
    float mean = blockSum256(s, sh) * (1.f / DD);
    float sq = 0.f;
    #pragma unroll
    for (int c = 0; c < 4; c++){ float d = x[c] - mean; sq += d * d; }
    float var = blockSum256(sq, sh) * (1.f / DD);
    float inv = rsqrtf(var + 1e-5f);
    float4 o;
    o.x = (x[0]-mean)*inv*w[j+0] + b[j+0];
    o.y = (x[1]-mean)*inv*w[j+1] + b[j+1];
    o.z = (x[2]-mean)*inv*w[j+2] + b[j+2];
    o.w = (x[3]-mean)*inv*w[j+3] + b[j+3];
    size_t idx = (size_t)t * DD + j;
    *(float4*)(h + idx) = o;
    store_half4(g_hh, idx, o);
}

__global__ __launch_bounds__(256) void copy_h_k(float* __restrict__ dst){
    size_t idx = ((size_t)blockIdx.x * 256 + threadIdx.x) * 4;
    *(float4*)(dst + idx) = *(const float4*)(g_h + idx);
}

// ================= launch ===================================================
extern "C" void kernel_launch(void* const* d_in, const int* in_sizes, int n_in,
                              void* d_out, int out_size)
{
    const int*   x    = (const int*)  d_in[0];
    const float* tok  = (const float*)d_in[1];
    const float* pos  = (const float*)d_in[2];
    const float* Wq   = (const float*)d_in[3];
    const float* bq   = (const float*)d_in[4];
    const float* Wk   = (const float*)d_in[5];
    const float* bk   = (const float*)d_in[6];
    const float* Wv   = (const float*)d_in[7];
    const float* bv   = (const float*)d_in[8];
    const float* Wo   = (const float*)d_in[9];
    const float* bo   = (const float*)d_in[10];
    const float* ln1w = (const float*)d_in[11];
    const float* ln1b = (const float*)d_in[12];
    const float* ln2w = (const float*)d_in[13];
    const float* ln2b = (const float*)d_in[14];
    const float* W1   = (const float*)d_in[15];
    const float* b1   = (const float*)d_in[16];
    const float* W2   = (const float*)d_in[17];
    const float* b2   = (const float*)d_in[18];
    const float* Wout = (const float*)d_in[19];
    const float* bout = (const float*)d_in[20];
    float* out = (float*)d_out;

    static int attr_set = 0;
    if (!attr_set){
        cudaFuncSetAttribute(gemm_mma,   cudaFuncAttributeMaxDynamicSharedMemorySize, GM_SMEM);
        cudaFuncSetAttribute(scores_mma, cudaFuncAttributeMaxDynamicSharedMemorySize, SC_SMEM);
        cudaFuncSetAttribute(av_mma,     cudaFuncAttributeMaxDynamicSharedMemorySize, AV_SMEM);
        attr_set = 1;
    }

    float *h, *att, *t, *bqkv;
    __half *atth, *hh, *qh, *oh, *ffh;
    __half *wqh, *woh, *w1h, *w2h, *wouth;
    cudaGetSymbolAddress((void**)&h,    g_h);
    cudaGetSymbolAddress((void**)&att,  g_att);
    cudaGetSymbolAddress((void**)&atth, g_atth);
    cudaGetSymbolAddress((void**)&t,    g_t);
    cudaGetSymbolAddress((void**)&bqkv, g_bqkv);
    cudaGetSymbolAddress((void**)&hh,   g_hh);
    cudaGetSymbolAddress((void**)&qh,   g_qkvh);
    cudaGetSymbolAddress((void**)&oh,   g_oh);
    cudaGetSymbolAddress((void**)&ffh,  g_ffh);
    cudaGetSymbolAddress((void**)&wqh,  g_wqkv_h);
    cudaGetSymbolAddress((void**)&woh,  g_wo_h);
    cudaGetSymbolAddress((void**)&w1h,  g_w1_h);
    cudaGetSymbolAddress((void**)&w2h,  g_w2_h);
    cudaGetSymbolAddress((void**)&wouth,g_wout_h);

    dim3 tsb(32, 8);
    // --- weight prep: transpose + fp16 cast ---
    packbias_k<<<24, 256>>>(bq, bk, bv);
    tsplit_k<<<dim3(2,32,32), tsb>>>(Wq, (long)DD*HD, 32, 0,
        wqh + 0*DD*DD, (long)HD*DD, 16, (long)3*DD*DD, DD, HD);
    tsplit_k<<<dim3(2,32,32), tsb>>>(Wk, (long)DD*HD, 32, 0,
        wqh + 1*DD*DD, (long)HD*DD, 16, (long)3*DD*DD, DD, HD);
    tsplit_k<<<dim3(2,32,32), tsb>>>(Wv, (long)DD*HD, 32, 0,
        wqh + 2*DD*DD, (long)HD*DD, 16, (long)3*DD*DD, DD, HD);
    tsplit_k<<<dim3(32,32,2), tsb>>>(Wo, (long)DD*DD, 2, 0,
        woh, (long)DD*DD, 2, 0, DD, DD);
    tsplit_k<<<dim3(128,32,2), tsb>>>(W1, (long)DD*FFD, 2, 0,
        w1h, (long)FFD*DD, 2, 0, DD, FFD);
    tsplit_k<<<dim3(32,128,2), tsb>>>(W2, (long)FFD*DD, 2, 0,
        w2h, (long)DD*FFD, 2, 0, FFD, DD);
    tsplit_k<<<dim3(1000,32,1), tsb>>>(Wout, 0, 1, 0,
        wouth, 0, 1, 0, DD, VV);

    embed_k<<<BS, 256>>>(x, tok, pos);

    for (int l = 0; l < LL; l++){
        // QKV: [4096,1024] x [1024,3072] -> fp16
        gemm_mma<<<dim3(BS/128, 3*DD/128), 256, GM_SMEM>>>(
            hh, wqh + (long)l*3*DD*DD,
            bqkv + (long)l*3*DD, 0, qh, DD, 3*DD, 2);
        scores_mma<<<dim3(SS/128, SS/128, HH*BB), 256, SC_SMEM>>>(qh, att);
        softmax_k<<<HH*BB*SS, 256>>>(att, atth);
        av_mma<<<dim3(1, SS/128, HH*BB), 256, AV_SMEM>>>(atth, qh, oh);
        // Wo
        gemm_mma<<<dim3(BS/128, DD/128), 256, GM_SMEM>>>(
            oh, woh + (long)l*DD*DD,
            bo + (long)l*DD, t, 0, DD, DD, 0);
        add_ln_k<<<BS, 256>>>(h, t, ln1w + (long)l*DD, ln1b + (long)l*DD);
        // W1 + GELU -> ff (fp16)
        gemm_mma<<<dim3(BS/128, FFD/128), 256, GM_SMEM>>>(
            hh, w1h + (long)l*FFD*DD,
            b1 + (long)l*FFD, 0, ffh, DD, FFD, 1);
        // W2
        gemm_mma<<<dim3(BS/128, DD/128), 256, GM_SMEM>>>(
            ffh, w2h + (long)l*DD*FFD,
            b2 + (long)l*DD, t, 0, FFD, DD, 0);
        add_ln_k<<<BS, 256>>>(h, t, ln2w + (long)l*DD, ln2b + (long)l*DD);
    }

    // logits
    gemm_mma<<<dim3(BS/128, VV/128), 256, GM_SMEM>>>(
        hh, wouth, bout, out, 0, DD, VV, 0);
    copy_h_k<<<(BS*DD)/1024, 256>>>(out + (long)BS*VV);
}

// round 9
// speedup vs baseline: 6.4751x; 1.1072x over previous
#include <cuda_runtime.h>
#include <cuda_fp16.h>
#include <math.h>
#include <stdint.h>

#define LL 2
#define HH 16
#define DD 1024
#define HD 64
#define FFD 4096
#define VV 32000
#define SS 1024
#define BB 4
#define BS (BB*SS)   /* 4096 */

// ================= scratch (device globals) =================================
__device__ float g_h  [(size_t)BS*DD];
__device__ float g_t  [(size_t)BS*DD];

__device__ __half g_hh [(size_t)BS*DD];
__device__ __half g_qkvh[(size_t)BS*3*DD];
__device__ __half g_oh [(size_t)BS*DD];
__device__ __half g_ffh[(size_t)BS*FFD];

__device__ __half g_wqkv_h[(size_t)LL*3*DD*DD];
__device__ __half g_wo_h [(size_t)LL*DD*DD];
__device__ __half g_w1_h [(size_t)LL*FFD*DD];
__device__ __half g_w2_h [(size_t)LL*DD*FFD];
__device__ __half g_wout_h[(size_t)VV*DD];
__device__ float g_bqkv[(size_t)LL*3*DD];

// ================= small helpers ============================================
__device__ __forceinline__ uint32_t smem_to_u32(const void* smem_ptr) {
    uint32_t addr;
    asm("{ .reg .u64 tmp; cvta.to.shared.u64 tmp, %1; cvt.u32.u64 %0, tmp; }"
        : "=r"(addr) : "l"(smem_ptr));
    return addr;
}
__device__ __forceinline__ void cp16(uint32_t d, const void* s){
    asm volatile("cp.async.cg.shared.global [%0], [%1], 16;" :: "r"(d), "l"(s) : "memory");
}
__device__ __forceinline__ void ldm_x4(uint32_t* r, uint32_t addr){
    asm volatile("ldmatrix.sync.aligned.m8n8.x4.shared.b16 {%0,%1,%2,%3}, [%4];"
        : "=r"(r[0]), "=r"(r[1]), "=r"(r[2]), "=r"(r[3]) : "r"(addr));
}
__device__ __forceinline__ void ldm_x4_t(uint32_t* r, uint32_t addr){
    asm volatile("ldmatrix.sync.aligned.m8n8.x4.trans.shared.b16 {%0,%1,%2,%3}, [%4];"
        : "=r"(r[0]), "=r"(r[1]), "=r"(r[2]), "=r"(r[3]) : "r"(addr));
}
__device__ __forceinline__ void mma16816(float* c, const uint32_t* a, uint32_t b0, uint32_t b1){
    asm volatile("mma.sync.aligned.m16n8k16.row.col.f32.f16.f16.f32 "
        "{%0,%1,%2,%3}, {%4,%5,%6,%7}, {%8,%9}, {%0,%1,%2,%3};"
        : "+f"(c[0]), "+f"(c[1]), "+f"(c[2]), "+f"(c[3])
        : "r"(a[0]), "r"(a[1]), "r"(a[2]), "r"(a[3]), "r"(b0), "r"(b1));
}
__device__ __forceinline__ float warpSum(float v){
    #pragma unroll
    for (int o = 16; o > 0; o >>= 1) v += __shfl_xor_sync(0xffffffffu, v, o);
    return v;
}
__device__ __forceinline__ float blockSum256(float v, float* sh){
    int lane = threadIdx.x & 31, wid = threadIdx.x >> 5;
    v = warpSum(v);
    if (lane == 0) sh[wid] = v;
    __syncthreads();
    float r = (threadIdx.x < 8) ? sh[threadIdx.x] : 0.f;
    if (threadIdx.x < 32) { r = warpSum(r); if (threadIdx.x == 0) sh[0] = r; }
    __syncthreads();
    float res = sh[0];
    __syncthreads();
    return res;
}
__device__ __forceinline__ float gelu_f(float x){
    return 0.5f * x * (1.0f + erff(x * 0.70710678118654752f));
}
__device__ __forceinline__ void store_half4(__half* p, size_t idx, float4 v){
    *(__half2*)(p+idx)   = __halves2half2(__float2half_rn(v.x), __float2half_rn(v.y));
    *(__half2*)(p+idx+2) = __halves2half2(__float2half_rn(v.z), __float2half_rn(v.w));
}
__device__ __forceinline__ void store_half2(__half* p, size_t idx, float a, float b){
    *(__half2*)(p+idx) = __halves2half2(__float2half_rn(a), __float2half_rn(b));
}
__device__ __forceinline__ uint32_t pack_h2(float a, float b){
    __half2 h = __halves2half2(__float2half_rn(a), __float2half_rn(b));
    return *(uint32_t*)&h;
}

// ================= prep kernels =============================================
__global__ __launch_bounds__(256) void packbias_k(const float* __restrict__ bq,
                                                  const float* __restrict__ bk,
                                                  const float* __restrict__ bv){
    int i = blockIdx.x*256 + threadIdx.x;            // 0..6143
    int l = i / (3*DD), n = i % (3*DD);
    float v = (n < DD) ? bq[l*DD + n] : (n < 2*DD) ? bk[l*DD + n - DD] : bv[l*DD + n - 2*DD];
    g_bqkv[i] = v;
}

// transposed fp16 cast: out[n][k] = fp16(in_z[k][n]); in [K][ldin], out ld=K
__global__ __launch_bounds__(256) void tsplit_k(
    const float* __restrict__ in, long sInLo, int zdivIn, long sInHi,
    __half* __restrict__ oh,
    long sOutLo, int zdivOut, long sOutHi,
    int K, int ldin)
{
    __shared__ float t[32][33];
    int z = blockIdx.z;
    const float* I = in + (long)(z % zdivIn)*sInLo + (long)(z / zdivIn)*sInHi;
    long ob = (long)(z % zdivOut)*sOutLo + (long)(z / zdivOut)*sOutHi;
    int nx = blockIdx.x*32, ky = blockIdx.y*32;
    int tx = threadIdx.x, ty = threadIdx.y;  // (32,8)
    #pragma unroll
    for (int i = 0; i < 4; i++)
        t[ty + i*8][tx] = I[(long)(ky + ty + i*8)*ldin + nx + tx];
    __syncthreads();
    #pragma unroll
    for (int i = 0; i < 4; i++){
        int n = nx + ty + i*8, k = ky + tx;
        oh[ob + (long)n*K + k] = __float2half_rn(t[tx][ty + i*8]);
    }
}

__global__ __launch_bounds__(256) void embed_k(const int* __restrict__ x,
                                               const float* __restrict__ tok,
                                               const float* __restrict__ pos){
    int t = blockIdx.x;
    int s = t & (SS - 1);
    int id = x[t];
    int j = threadIdx.x * 4;
    float4 a = *(const float4*)(tok + (size_t)id * DD + j);
    float4 p = *(const float4*)(pos + (size_t)s  * DD + j);
    float4 r; r.x = a.x + p.x; r.y = a.y + p.y; r.z = a.z + p.z; r.w = a.w + p.w;
    size_t idx = (size_t)t * DD + j;
    *(float4*)(g_h + idx) = r;
    store_half4(g_hh, idx, r);
}

// ================= fp16 GEMM via mma.sync (HMMA) ============================
// C[M,N] = A*B^T (+bias).  A fp16 [M][K], B fp16 [N][K].
// block tile 128x128, Kc=32, 8 warps (warp tile 32x64), cp.async double buffer.
// op0: f32 out + bias.  op1: gelu(out+bias) -> fp16.  op2: bias -> fp16.
#define PADK 40            /* row stride in fp16 elems (80B), conflict-free */
#define OPSZ 10240         /* 128*PADK*2 bytes per operand tile */
#define GM_SMEM (2*2*OPSZ) /* 40960 */
__global__ __launch_bounds__(256, 2) void gemm_mma(
    const __half* __restrict__ A, const __half* __restrict__ B,
    const float* __restrict__ bias,
    float* __restrict__ Cf, __half* __restrict__ Ch,
    int K_, int ldc, int op)
{
    extern __shared__ char smem[];
    uint32_t sb = smem_to_u32(smem);
    int tid = threadIdx.x, lane = tid & 31, wid = tid >> 5;
    int wm = wid & 3, wn = wid >> 2;            // 4x2 warp grid
    long row0 = (long)blockIdx.x * 128;
    long col0 = (long)blockIdx.y * 128;

    float acc[2][8][4];
    #pragma unroll
    for (int i = 0; i < 2; i++)
        #pragma unroll
        for (int j = 0; j < 8; j++)
            #pragma unroll
            for (int q = 0; q < 4; q++) acc[i][j][q] = 0.f;

    auto load_chunk = [&](int c, int buf){
        long k0 = (long)c * 32;
        uint32_t base = sb + (uint32_t)buf * (2*OPSZ);
        #pragma unroll
        for (int i = tid; i < 512; i += 256){
            int r = i >> 2, seg = (i & 3) * 8;
            uint32_t soff = (uint32_t)(r * PADK + seg) * 2;
            cp16(base + soff,        A + (row0 + r) * (long)K_ + k0 + seg);
            cp16(base + OPSZ + soff, B + (col0 + r) * (long)K_ + k0 + seg);
        }
        asm volatile("cp.async.commit_group;" ::: "memory");
    };

    const int NC = K_ >> 5;
    load_chunk(0, 0);

    int m_local = (lane & 7) | (lane & 8);
    int k_off = (lane >> 4) * 8;

    for (int c = 0; c < NC; ++c){
        int buf = c & 1;
        asm volatile("cp.async.wait_group 0;" ::: "memory");
        __syncthreads();
        if (c + 1 < NC) load_chunk(c + 1, buf ^ 1);

        uint32_t base = sb + (uint32_t)buf * (2*OPSZ);
        #pragma unroll
        for (int ks = 0; ks < 2; ++ks){
            uint32_t a_h[2][4];
            #pragma unroll
            for (int am = 0; am < 2; ++am){
                uint32_t roff = (uint32_t)((wm*32 + am*16 + m_local) * PADK + ks*16 + k_off) * 2;
                ldm_x4(a_h[am], base + roff);
            }
            uint32_t b_h[4][4];
            #pragma unroll
            for (int nt2 = 0; nt2 < 4; ++nt2){
                uint32_t roff = (uint32_t)((wn*64 + nt2*16 + m_local) * PADK + ks*16 + k_off) * 2;
                ldm_x4(b_h[nt2], base + OPSZ + roff);
            }
            #pragma unroll
            for (int mt = 0; mt < 2; ++mt)
                #pragma unroll
                for (int nt = 0; nt < 8; ++nt){
                    int q = nt >> 1, rs = nt & 1;
                    mma16816(acc[mt][nt], a_h[mt], b_h[q][rs], b_h[q][rs+2]);
                }
        }
    }

    // epilogue
    #pragma unroll
    for (int mt = 0; mt < 2; ++mt){
        #pragma unroll
        for (int nt = 0; nt < 8; ++nt){
            long row = row0 + wm*32 + mt*16 + (lane >> 2);
            long col = col0 + wn*64 + nt*8 + (lane & 3)*2;
            float b0 = bias[col], b1 = bias[col+1];
            float v0 = acc[mt][nt][0] + b0, v1 = acc[mt][nt][1] + b1;
            float v2 = acc[mt][nt][2] + b0, v3 = acc[mt][nt][3] + b1;
            if (op == 0){
                *(float2*)(Cf + row*(long)ldc + col)     = make_float2(v0, v1);
                *(float2*)(Cf + (row+8)*(long)ldc + col) = make_float2(v2, v3);
            } else if (op == 1){
                store_half2(Ch, (size_t)(row*(long)ldc + col),     gelu_f(v0), gelu_f(v1));
                store_half2(Ch, (size_t)((row+8)*(long)ldc + col), gelu_f(v2), gelu_f(v3));
            } else {
                store_half2(Ch, (size_t)(row*(long)ldc + col),     v0, v1);
                store_half2(Ch, (size_t)((row+8)*(long)ldc + col), v2, v3);
            }
        }
    }
}

// ================= fused flash attention ====================================
// One CTA = (z = h*4+b, 128-row block). Online softmax, P kept in fragments.
// 8 warps, each warp owns 16 rows. K/V chunks of 128 keys, double buffered.
#define PADQ 72
#define FL_Q   (128*PADQ*2)              /* 18432 */
#define FL_KV  (128*PADQ*2)              /* 18432 each for K and V */
#define FL_BUF (2*FL_KV)                 /* 36864 */
#define FL_SMEM (FL_Q + 2*FL_BUF)        /* 92160 */
__global__ __launch_bounds__(256, 1) void flash_k(
    const __half* __restrict__ qkvh, __half* __restrict__ oh)
{
    extern __shared__ char smem[];
    uint32_t sb = smem_to_u32(smem);
    int z = blockIdx.x; int b = z & 3, hd = z >> 2;
    int rb = blockIdx.y;
    long qbase = (long)b*SS*(3*DD) + hd*HD;
    long kbase = qbase + DD;
    long vbase = qbase + 2*DD;
    long obase = (long)b*SS*DD + hd*HD;
    int tid = threadIdx.x, lane = tid & 31, wid = tid >> 5;
    long row0 = (long)rb * 128;

    // load Q tile (128 x 64)
    #pragma unroll
    for (int i = tid; i < 1024; i += 256){
        int r = i >> 3, u = (i & 7) * 8;
        cp16(sb + (uint32_t)(r*PADQ + u)*2, qkvh + qbase + (row0 + r)*(long)(3*DD) + u);
    }
    asm volatile("cp.async.commit_group;" ::: "memory");

    auto load_kv = [&](int c, int buf){
        uint32_t base = sb + FL_Q + (uint32_t)buf * FL_BUF;
        long k0 = (long)c * 128;
        #pragma unroll
        for (int i = tid; i < 1024; i += 256){
            int r = i >> 3, u = (i & 7) * 8;
            uint32_t soff = (uint32_t)(r*PADQ + u)*2;
            cp16(base + soff,         qkvh + kbase + (k0 + r)*(long)(3*DD) + u);
            cp16(base + FL_KV + soff, qkvh + vbase + (k0 + r)*(long)(3*DD) + u);
        }
        asm volatile("cp.async.commit_group;" ::: "memory");
    };
    const int nchunks = rb + 1;
    load_kv(0, 0);
    asm volatile("cp.async.wait_group 0;" ::: "memory");
    __syncthreads();

    int m_local = (lane & 7) | (lane & 8);
    int k_off = (lane >> 4) * 8;
    int t_row = lane & 15, t_col = (lane >> 4) * 8;
    int rA = lane >> 2;                   // local row within 16
    int colb = (lane & 3) * 2;

    // preload Q fragments (16 rows x 64 k)
    uint32_t qf[4][4];
    #pragma unroll
    for (int ks = 0; ks < 4; ++ks){
        uint32_t roff = (uint32_t)((wid*16 + m_local)*PADQ + ks*16 + k_off)*2;
        ldm_x4(qf[ks], sb + roff);
    }

    float oacc[8][4];
    #pragma unroll
    for (int j = 0; j < 8; j++)
        #pragma unroll
        for (int q = 0; q < 4; q++) oacc[j][q] = 0.f;
    float m0 = -1e30f, m1 = -1e30f, l0 = 0.f, l1 = 0.f;

    for (int c = 0; c < nchunks; ++c){
        int buf = c & 1;
        if (c > 0){
            asm volatile("cp.async.wait_group 0;" ::: "memory");
            __syncthreads();
        }
        if (c + 1 < nchunks) load_kv(c + 1, buf ^ 1);
        uint32_t kb = sb + FL_Q + (uint32_t)buf * FL_BUF;

        // S = Q @ K^T (16 x 128 per warp)
        float s[16][4];
        #pragma unroll
        for (int j = 0; j < 16; j++)
            #pragma unroll
            for (int q = 0; q < 4; q++) s[j][q] = 0.f;
        #pragma unroll
        for (int ks = 0; ks < 4; ++ks){
            uint32_t bh[8][4];
            #pragma unroll
            for (int nt2 = 0; nt2 < 8; ++nt2){
                uint32_t roff = (uint32_t)((nt2*16 + m_local)*PADQ + ks*16 + k_off)*2;
                ldm_x4(bh[nt2], kb + roff);
            }
            #pragma unroll
            for (int nt = 0; nt < 16; ++nt){
                int q = nt >> 1, rs = nt & 1;
                mma16816(s[nt], qf[ks], bh[q][rs], bh[q][rs+2]);
            }
        }

        // scale + causal mask (diag chunk only) + row stats
        bool diag = (c == rb);
        float cm0 = -1e30f, cm1 = -1e30f;
        #pragma unroll
        for (int nt = 0; nt < 16; ++nt){
            int cl = nt*8 + colb;               // local col of regs 0/1
            int r_lo = wid*16 + rA, r_hi = r_lo + 8;
            #pragma unroll
            for (int q = 0; q < 4; q++) s[nt][q] *= 0.125f;
            if (diag){
                if (cl     > r_lo) s[nt][0] = -1e30f;
                if (cl + 1 > r_lo) s[nt][1] = -1e30f;
                if (cl     > r_hi) s[nt][2] = -1e30f;
                if (cl + 1 > r_hi) s[nt][3] = -1e30f;
            }
            cm0 = fmaxf(cm0, fmaxf(s[nt][0], s[nt][1]));
            cm1 = fmaxf(cm1, fmaxf(s[nt][2], s[nt][3]));
        }
        cm0 = fmaxf(cm0, __shfl_xor_sync(0xffffffffu, cm0, 1));
        cm0 = fmaxf(cm0, __shfl_xor_sync(0xffffffffu, cm0, 2));
        cm1 = fmaxf(cm1, __shfl_xor_sync(0xffffffffu, cm1, 1));
        cm1 = fmaxf(cm1, __shfl_xor_sync(0xffffffffu, cm1, 2));
        float mn0 = fmaxf(m0, cm0), mn1 = fmaxf(m1, cm1);
        float al0 = expf(m0 - mn0), al1 = expf(m1 - mn1);
        m0 = mn0; m1 = mn1;

        // exponentiate (s -> p), partial sums
        float ls0 = 0.f, ls1 = 0.f;
        #pragma unroll
        for (int nt = 0; nt < 16; ++nt){
            s[nt][0] = expf(s[nt][0] - mn0);
            s[nt][1] = expf(s[nt][1] - mn0);
            s[nt][2] = expf(s[nt][2] - mn1);
            s[nt][3] = expf(s[nt][3] - mn1);
            ls0 += s[nt][0] + s[nt][1];
            ls1 += s[nt][2] + s[nt][3];
        }
        ls0 += __shfl_xor_sync(0xffffffffu, ls0, 1);
        ls0 += __shfl_xor_sync(0xffffffffu, ls0, 2);
        ls1 += __shfl_xor_sync(0xffffffffu, ls1, 1);
        ls1 += __shfl_xor_sync(0xffffffffu, ls1, 2);
        l0 = l0 * al0 + ls0;
        l1 = l1 * al1 + ls1;

        // rescale O
        #pragma unroll
        for (int nt = 0; nt < 8; ++nt){
            oacc[nt][0] *= al0; oacc[nt][1] *= al0;
            oacc[nt][2] *= al1; oacc[nt][3] *= al1;
        }

        // O += P @ V  (P fragments direct from s)
        uint32_t vb = kb + FL_KV;
        #pragma unroll
        for (int kk = 0; kk < 8; ++kk){
            uint32_t a[4];
            a[0] = pack_h2(s[2*kk][0],   s[2*kk][1]);
            a[1] = pack_h2(s[2*kk][2],   s[2*kk][3]);
            a[2] = pack_h2(s[2*kk+1][0], s[2*kk+1][1]);
            a[3] = pack_h2(s[2*kk+1][2], s[2*kk+1][3]);
            uint32_t bv[4][4];
            #pragma unroll
            for (int g2 = 0; g2 < 4; ++g2){
                uint32_t voff = (uint32_t)((kk*16 + t_row)*PADQ + g2*16 + t_col)*2;
                ldm_x4_t(bv[g2], vb + voff);
            }
            #pragma unroll
            for (int nt = 0; nt < 8; ++nt){
                int g2 = nt >> 1, sub = (nt & 1) * 2;
                mma16816(oacc[nt], a, bv[g2][sub], bv[g2][sub+1]);
            }
        }
    }

    // epilogue: normalize, write fp16 o
    float inv0 = 1.f / l0, inv1 = 1.f / l1;
    #pragma unroll
    for (int nt = 0; nt < 8; ++nt){
        long row = row0 + wid*16 + rA;
        long col = nt*8 + colb;
        size_t idx = (size_t)(obase + row*(long)DD + col);
        store_half2(oh, idx,        oacc[nt][0]*inv0, oacc[nt][1]*inv0);
        store_half2(oh, idx + 8*DD, oacc[nt][2]*inv1, oacc[nt][3]*inv1);
    }
}

// ================= pointwise ================================================
__global__ __launch_bounds__(256) void add_ln_k(float* __restrict__ h,
                                                const float* __restrict__ delta,
                                                const float* __restrict__ w,
                                                const float* __restrict__ b){
    long t = blockIdx.x;
    int tid = threadIdx.x;
    int j = tid * 4;
    __shared__ float sh[8];
    float4 hv = *(const float4*)(h + t * DD + j);
    float4 dv = *(const float4*)(delta + t * DD + j);
    float x[4] = {hv.x + dv.x, hv.y + dv.y, hv.z + dv.z, hv.w + dv.w};
    float s = x[0] + x[1] + x[2] + x[3];
    float mean = blockSum256(s, sh) * (1.f / DD);
    float sq = 0.f;
    #pragma unroll
    for (int c = 0; c < 4; c++){ float d = x[c] - mean; sq += d * d; }
    float var = blockSum256(sq, sh) * (1.f / DD);
    float inv = rsqrtf(var + 1e-5f);
    float4 o;
    o.x = (x[0]-mean)*inv*w[j+0] + b[j+0];
    o.y = (x[1]-mean)*inv*w[j+1] + b[j+1];
    o.z = (x[2]-mean)*inv*w[j+2] + b[j+2];
    o.w = (x[3]-mean)*inv*w[j+3] + b[j+3];
    size_t idx = (size_t)t * DD + j;
    *(float4*)(h + idx) = o;
    store_half4(g_hh, idx, o);
}

__global__ __launch_bounds__(256) void copy_h_k(float* __restrict__ dst){
    size_t idx = ((size_t)blockIdx.x * 256 + threadIdx.x) * 4;
    *(float4*)(dst + idx) = *(const float4*)(g_h + idx);
}

// ================= launch ===================================================
extern "C" void kernel_launch(void* const* d_in, const int* in_sizes, int n_in,
                              void* d_out, int out_size)
{
    const int*   x    = (const int*)  d_in[0];
    const float* tok  = (const float*)d_in[1];
    const float* pos  = (const float*)d_in[2];
    const float* Wq   = (const float*)d_in[3];
    const float* bq   = (const float*)d_in[4];
    const float* Wk   = (const float*)d_in[5];
    const float* bk   = (const float*)d_in[6];
    const float* Wv   = (const float*)d_in[7];
    const float* bv   = (const float*)d_in[8];
    const float* Wo   = (const float*)d_in[9];
    const float* bo   = (const float*)d_in[10];
    const float* ln1w = (const float*)d_in[11];
    const float* ln1b = (const float*)d_in[12];
    const float* ln2w = (const float*)d_in[13];
    const float* ln2b = (const float*)d_in[14];
    const float* W1   = (const float*)d_in[15];
    const float* b1   = (const float*)d_in[16];
    const float* W2   = (const float*)d_in[17];
    const float* b2   = (const float*)d_in[18];
    const float* Wout = (const float*)d_in[19];
    const float* bout = (const float*)d_in[20];
    float* out = (float*)d_out;

    static int attr_set = 0;
    if (!attr_set){
        cudaFuncSetAttribute(gemm_mma, cudaFuncAttributeMaxDynamicSharedMemorySize, GM_SMEM);
        cudaFuncSetAttribute(flash_k,  cudaFuncAttributeMaxDynamicSharedMemorySize, FL_SMEM);
        attr_set = 1;
    }

    float *h, *t, *bqkv;
    __half *hh, *qh, *oh, *ffh;
    __half *wqh, *woh, *w1h, *w2h, *wouth;
    cudaGetSymbolAddress((void**)&h,    g_h);
    cudaGetSymbolAddress((void**)&t,    g_t);
    cudaGetSymbolAddress((void**)&bqkv, g_bqkv);
    cudaGetSymbolAddress((void**)&hh,   g_hh);
    cudaGetSymbolAddress((void**)&qh,   g_qkvh);
    cudaGetSymbolAddress((void**)&oh,   g_oh);
    cudaGetSymbolAddress((void**)&ffh,  g_ffh);
    cudaGetSymbolAddress((void**)&wqh,  g_wqkv_h);
    cudaGetSymbolAddress((void**)&woh,  g_wo_h);
    cudaGetSymbolAddress((void**)&w1h,  g_w1_h);
    cudaGetSymbolAddress((void**)&w2h,  g_w2_h);
    cudaGetSymbolAddress((void**)&wouth,g_wout_h);

    dim3 tsb(32, 8);
    // --- weight prep: transpose + fp16 cast ---
    packbias_k<<<24, 256>>>(bq, bk, bv);
    tsplit_k<<<dim3(2,32,32), tsb>>>(Wq, (long)DD*HD, 32, 0,
        wqh + 0*DD*DD, (long)HD*DD, 16, (long)3*DD*DD, DD, HD);
    tsplit_k<<<dim3(2,32,32), tsb>>>(Wk, (long)DD*HD, 32, 0,
        wqh + 1*DD*DD, (long)HD*DD, 16, (long)3*DD*DD, DD, HD);
    tsplit_k<<<dim3(2,32,32), tsb>>>(Wv, (long)DD*HD, 32, 0,
        wqh + 2*DD*DD, (long)HD*DD, 16, (long)3*DD*DD, DD, HD);
    tsplit_k<<<dim3(32,32,2), tsb>>>(Wo, (long)DD*DD, 2, 0,
        woh, (long)DD*DD, 2, 0, DD, DD);
    tsplit_k<<<dim3(128,32,2), tsb>>>(W1, (long)DD*FFD, 2, 0,
        w1h, (long)FFD*DD, 2, 0, DD, FFD);
    tsplit_k<<<dim3(32,128,2), tsb>>>(W2, (long)FFD*DD, 2, 0,
        w2h, (long)DD*FFD, 2, 0, FFD, DD);
    tsplit_k<<<dim3(1000,32,1), tsb>>>(Wout, 0, 1, 0,
        wouth, 0, 1, 0, DD, VV);

    embed_k<<<BS, 256>>>(x, tok, pos);

    for (int l = 0; l < LL; l++){
        // QKV: [4096,1024] x [1024,3072] -> fp16
        gemm_mma<<<dim3(BS/128, 3*DD/128), 256, GM_SMEM>>>(
            hh, wqh + (long)l*3*DD*DD,
            bqkv + (long)l*3*DD, 0, qh, DD, 3*DD, 2);
        // fused attention
        flash_k<<<dim3(HH*BB, SS/128), 256, FL_SMEM>>>(qh, oh);
        // Wo
        gemm_mma<<<dim3(BS/128, DD/128), 256, GM_SMEM>>>(
            oh, woh + (long)l*DD*DD,
            bo + (long)l*DD, t, 0, DD, DD, 0);
        add_ln_k<<<BS, 256>>>(h, t, ln1w + (long)l*DD, ln1b + (long)l*DD);
        // W1 + GELU -> ff (fp16)
        gemm_mma<<<dim3(BS/128, FFD/128), 256, GM_SMEM>>>(
            hh, w1h + (long)l*FFD*DD,
            b1 + (long)l*FFD, 0, ffh, DD, FFD, 1);
        // W2
        gemm_mma<<<dim3(BS/128, DD/128), 256, GM_SMEM>>>(
            ffh, w2h + (long)l*DD*FFD,
            b2 + (long)l*DD, t, 0, FFD, DD, 0);
        add_ln_k<<<BS, 256>>>(h, t, ln2w + (long)l*DD, ln2b + (long)l*DD);
    }

    // logits
    gemm_mma<<<dim3(BS/128, VV/128), 256, GM_SMEM>>>(
        hh, wouth, bout, out, 0, DD, VV, 0);
    copy_h_k<<<(BS*DD)/1024, 256>>>(out + (long)BS*VV);
}

// round 11
// speedup vs baseline: 7.1314x; 1.1014x over previous
#include <cuda_runtime.h>
#include <cuda_fp16.h>
#include <math.h>
#include <stdint.h>

#define LL 2
#define HH 16
#define DD 1024
#define HD 64
#define FFD 4096
#define VV 32000
#define SS 1024
#define BB 4
#define BS (BB*SS)   /* 4096 */

// ================= scratch (device globals) =================================
__device__ float g_h  [(size_t)BS*DD];

__device__ __half g_hh [(size_t)BS*DD];
__device__ __half g_qkvh[(size_t)BS*3*DD];
__device__ __half g_oh [(size_t)BS*DD];
__device__ __half g_ffh[(size_t)BS*FFD];
__device__ __half g_th [(size_t)BS*DD];

__device__ __half g_wqkvn[(size_t)LL*DD*3*DD];   // [L][D][3*D]  (K x N)
__device__ __half g_wo_n [(size_t)LL*DD*DD];     // [L][D][D]
__device__ __half g_w1_n [(size_t)LL*DD*FFD];    // [L][D][FF]
__device__ __half g_w2_n [(size_t)LL*FFD*DD];    // [L][FF][D]
__device__ __half g_woutn[(size_t)DD*VV];        // [D][V]
__device__ float g_bqkv[(size_t)LL*3*DD];

// ================= small helpers ============================================
__device__ __forceinline__ uint32_t smem_to_u32(const void* smem_ptr) {
    uint32_t addr;
    asm("{ .reg .u64 tmp; cvta.to.shared.u64 tmp, %1; cvt.u32.u64 %0, tmp; }"
        : "=r"(addr) : "l"(smem_ptr));
    return addr;
}
__device__ __forceinline__ void cp16(uint32_t d, const void* s){
    asm volatile("cp.async.cg.shared.global [%0], [%1], 16;" :: "r"(d), "l"(s) : "memory");
}
__device__ __forceinline__ void ldm_x4(uint32_t* r, uint32_t addr){
    asm volatile("ldmatrix.sync.aligned.m8n8.x4.shared.b16 {%0,%1,%2,%3}, [%4];"
        : "=r"(r[0]), "=r"(r[1]), "=r"(r[2]), "=r"(r[3]) : "r"(addr));
}
__device__ __forceinline__ void ldm_x4_t(uint32_t* r, uint32_t addr){
    asm volatile("ldmatrix.sync.aligned.m8n8.x4.trans.shared.b16 {%0,%1,%2,%3}, [%4];"
        : "=r"(r[0]), "=r"(r[1]), "=r"(r[2]), "=r"(r[3]) : "r"(addr));
}
__device__ __forceinline__ void mma16816(float* c, const uint32_t* a, uint32_t b0, uint32_t b1){
    asm volatile("mma.sync.aligned.m16n8k16.row.col.f32.f16.f16.f32 "
        "{%0,%1,%2,%3}, {%4,%5,%6,%7}, {%8,%9}, {%0,%1,%2,%3};"
        : "+f"(c[0]), "+f"(c[1]), "+f"(c[2]), "+f"(c[3])
        : "r"(a[0]), "r"(a[1]), "r"(a[2]), "r"(a[3]), "r"(b0), "r"(b1));
}
__device__ __forceinline__ float warpSum(float v){
    #pragma unroll
    for (int o = 16; o > 0; o >>= 1) v += __shfl_xor_sync(0xffffffffu, v, o);
    return v;
}
__device__ __forceinline__ float blockSum256(float v, float* sh){
    int lane = threadIdx.x & 31, wid = threadIdx.x >> 5;
    v = warpSum(v);
    if (lane == 0) sh[wid] = v;
    __syncthreads();
    float r = (threadIdx.x < 8) ? sh[threadIdx.x] : 0.f;
    if (threadIdx.x < 32) { r = warpSum(r); if (threadIdx.x == 0) sh[0] = r; }
    __syncthreads();
    float res = sh[0];
    __syncthreads();
    return res;
}
__device__ __forceinline__ float gelu_f(float x){
    return 0.5f * x * (1.0f + erff(x * 0.70710678118654752f));
}
__device__ __forceinline__ void store_half4(__half* p, size_t idx, float4 v){
    *(__half2*)(p+idx)   = __halves2half2(__float2half_rn(v.x), __float2half_rn(v.y));
    *(__half2*)(p+idx+2) = __halves2half2(__float2half_rn(v.z), __float2half_rn(v.w));
}
__device__ __forceinline__ void store_half2(__half* p, size_t idx, float a, float b){
    *(__half2*)(p+idx) = __halves2half2(__float2half_rn(a), __float2half_rn(b));
}
__device__ __forceinline__ uint32_t pack_h2(float a, float b){
    __half2 h = __halves2half2(__float2half_rn(a), __float2half_rn(b));
    return *(uint32_t*)&h;
}

// ================= prep kernels =============================================
__global__ __launch_bounds__(256) void packbias_k(const float* __restrict__ bq,
                                                  const float* __restrict__ bk,
                                                  const float* __restrict__ bv){
    int i = blockIdx.x*256 + threadIdx.x;            // 0..6143
    int l = i / (3*DD), n = i % (3*DD);
    float v = (n < DD) ? bq[l*DD + n] : (n < 2*DD) ? bk[l*DD + n - DD] : bv[l*DD + n - 2*DD];
    g_bqkv[i] = v;
}

// plain fp32 -> fp16 cast, float4 per thread
__global__ __launch_bounds__(256) void cast_k(const float* __restrict__ in,
                                              __half* __restrict__ out){
    size_t i = ((size_t)blockIdx.x*256 + threadIdx.x)*4;
    float4 v = *(const float4*)(in + i);
    store_half4(out, i, v);
}

// QKV weight permute+cast: out[l][d][sec*1024 + h*64 + e] = W[l][h][d][e]
__global__ __launch_bounds__(256) void qkvpack_k(const float* __restrict__ W,
                                                 __half* __restrict__ out, int sec){
    size_t i = (size_t)blockIdx.x*256 + threadIdx.x;  // 524288 total
    int e4 = (int)(i & 15);
    int d  = (int)((i >> 4) & 1023);
    int h  = (int)((i >> 14) & 15);
    int l  = (int)(i >> 18);
    float4 v = *(const float4*)(W + (((size_t)(l*16 + h)*1024 + d)*64 + e4*4));
    size_t o = ((size_t)(l*1024 + d)*3072) + sec*1024 + h*64 + e4*4;
    store_half4(out, o, v);
}

__global__ __launch_bounds__(256) void embed_k(const int* __restrict__ x,
                                               const float* __restrict__ tok,
                                               const float* __restrict__ pos){
    int t = blockIdx.x;
    int s = t & (SS - 1);
    int id = x[t];
    int j = threadIdx.x * 4;
    float4 a = *(const float4*)(tok + (size_t)id * DD + j);
    float4 p = *(const float4*)(pos + (size_t)s  * DD + j);
    float4 r; r.x = a.x + p.x; r.y = a.y + p.y; r.z = a.z + p.z; r.w = a.w + p.w;
    size_t idx = (size_t)t * DD + j;
    *(float4*)(g_h + idx) = r;
    store_half4(g_hh, idx, r);
}

// ================= fp16 NN GEMM via mma.sync ================================
// C[M,N] = A[M][K] * B[K][N] (+bias).  B fed via ldmatrix.trans.
// block tile 128x128, Kc=32, 8 warps (warp tile 32x64), cp.async double buffer.
// op0: f32 out + bias.  op1: gelu(out+bias) -> fp16.  op2: bias -> fp16.
#define PADK 40            /* A row stride, fp16 elems */
#define PADN 136           /* B row stride, fp16 elems (272 B, conflict-free) */
#define ASZ (128*PADK*2)   /* 10240 */
#define BSZ (32*PADN*2)    /* 8704  */
#define GBUF (ASZ+BSZ)     /* 18944 */
#define GM_SMEM (2*GBUF)   /* 37888 */
__global__ __launch_bounds__(256, 2) void gemm_nn(
    const __half* __restrict__ A, const __half* __restrict__ B,
    const float* __restrict__ bias,
    float* __restrict__ Cf, __half* __restrict__ Ch,
    int K_, int ldb, int ldc, int op)
{
    extern __shared__ char smem[];
    uint32_t sb = smem_to_u32(smem);
    int tid = threadIdx.x, lane = tid & 31, wid = tid >> 5;
    int wm = wid & 3, wn = wid >> 2;            // 4x2 warp grid
    long row0 = (long)blockIdx.x * 128;
    long col0 = (long)blockIdx.y * 128;

    float acc[2][8][4];
    #pragma unroll
    for (int i = 0; i < 2; i++)
        #pragma unroll
        for (int j = 0; j < 8; j++)
            #pragma unroll
            for (int q = 0; q < 4; q++) acc[i][j][q] = 0.f;

    auto load_chunk = [&](int c, int buf){
        long k0 = (long)c * 32;
        uint32_t base = sb + (uint32_t)buf * GBUF;
        #pragma unroll
        for (int i = tid; i < 512; i += 256){       // A: 128 rows x 4 units
            int r = i >> 2, seg = (i & 3) * 8;
            cp16(base + (uint32_t)(r*PADK + seg)*2, A + (row0 + r)*(long)K_ + k0 + seg);
        }
        #pragma unroll
        for (int i = tid; i < 512; i += 256){       // B: 32 k-rows x 16 units
            int r = i >> 4, u = (i & 15) * 8;
            cp16(base + ASZ + (uint32_t)(r*PADN + u)*2, B + (k0 + r)*(long)ldb + col0 + u);
        }
        asm volatile("cp.async.commit_group;" ::: "memory");
    };

    const int NC = K_ >> 5;
    load_chunk(0, 0);

    int m_local = (lane & 7) | (lane & 8);
    int k_off = (lane >> 4) * 8;
    int t_row = lane & 15, t_col = (lane >> 4) * 8;

    for (int c = 0; c < NC; ++c){
        int buf = c & 1;
        asm volatile("cp.async.wait_group 0;" ::: "memory");
        __syncthreads();
        if (c + 1 < NC) load_chunk(c + 1, buf ^ 1);

        uint32_t base = sb + (uint32_t)buf * GBUF;
        #pragma unroll
        for (int ks = 0; ks < 2; ++ks){
            uint32_t a_h[2][4];
            #pragma unroll
            for (int am = 0; am < 2; ++am){
                uint32_t roff = (uint32_t)((wm*32 + am*16 + m_local) * PADK + ks*16 + k_off) * 2;
                ldm_x4(a_h[am], base + roff);
            }
            uint32_t bt[4][4];
            #pragma unroll
            for (int g2 = 0; g2 < 4; ++g2){
                uint32_t voff = (uint32_t)((ks*16 + t_row)*PADN + wn*64 + g2*16 + t_col) * 2;
                ldm_x4_t(bt[g2], base + ASZ + voff);
            }
            #pragma unroll
            for (int mt = 0; mt < 2; ++mt)
                #pragma unroll
                for (int nt = 0; nt < 8; ++nt){
                    int g2 = nt >> 1, sub = (nt & 1) * 2;
                    mma16816(acc[mt][nt], a_h[mt], bt[g2][sub], bt[g2][sub+1]);
                }
        }
    }

    // epilogue
    #pragma unroll
    for (int mt = 0; mt < 2; ++mt){
        #pragma unroll
        for (int nt = 0; nt < 8; ++nt){
            long row = row0 + wm*32 + mt*16 + (lane >> 2);
            long col = col0 + wn*64 + nt*8 + (lane & 3)*2;
            float b0 = bias[col], b1 = bias[col+1];
            float v0 = acc[mt][nt][0] + b0, v1 = acc[mt][nt][1] + b1;
            float v2 = acc[mt][nt][2] + b0, v3 = acc[mt][nt][3] + b1;
            if (op == 0){
                *(float2*)(Cf + row*(long)ldc + col)     = make_float2(v0, v1);
                *(float2*)(Cf + (row+8)*(long)ldc + col) = make_float2(v2, v3);
            } else if (op == 1){
                store_half2(Ch, (size_t)(row*(long)ldc + col),     gelu_f(v0), gelu_f(v1));
                store_half2(Ch, (size_t)((row+8)*(long)ldc + col), gelu_f(v2), gelu_f(v3));
            } else {
                store_half2(Ch, (size_t)(row*(long)ldc + col),     v0, v1);
                store_half2(Ch, (size_t)((row+8)*(long)ldc + col), v2, v3);
            }
        }
    }
}

// ================= fused flash attention ====================================
#define PADQ 72
#define FL_Q   (128*PADQ*2)              /* 18432 */
#define FL_KV  (128*PADQ*2)
#define FL_BUF (2*FL_KV)                 /* 36864 */
#define FL_SMEM (FL_Q + 2*FL_BUF)        /* 92160 */
__global__ __launch_bounds__(256, 1) void flash_k(
    const __half* __restrict__ qkvh, __half* __restrict__ oh)
{
    extern __shared__ char smem[];
    uint32_t sb = smem_to_u32(smem);
    int z = blockIdx.x; int b = z & 3, hd = z >> 2;
    int rb = blockIdx.y;
    long qbase = (long)b*SS*(3*DD) + hd*HD;
    long kbase = qbase + DD;
    long vbase = qbase + 2*DD;
    long obase = (long)b*SS*DD + hd*HD;
    int tid = threadIdx.x, lane = tid & 31, wid = tid >> 5;
    long row0 = (long)rb * 128;

    #pragma unroll
    for (int i = tid; i < 1024; i += 256){
        int r = i >> 3, u = (i & 7) * 8;
        cp16(sb + (uint32_t)(r*PADQ + u)*2, qkvh + qbase + (row0 + r)*(long)(3*DD) + u);
    }
    asm volatile("cp.async.commit_group;" ::: "memory");

    auto load_kv = [&](int c, int buf){
        uint32_t base = sb + FL_Q + (uint32_t)buf * FL_BUF;
        long k0 = (long)c * 128;
        #pragma unroll
        for (int i = tid; i < 1024; i += 256){
            int r = i >> 3, u = (i & 7) * 8;
            uint32_t soff = (uint32_t)(r*PADQ + u)*2;
            cp16(base + soff,         qkvh + kbase + (k0 + r)*(long)(3*DD) + u);
            cp16(base + FL_KV + soff, qkvh + vbase + (k0 + r)*(long)(3*DD) + u);
        }
        asm volatile("cp.async.commit_group;" ::: "memory");
    };
    const int nchunks = rb + 1;
    load_kv(0, 0);
    asm volatile("cp.async.wait_group 0;" ::: "memory");
    __syncthreads();

    int m_local = (lane & 7) | (lane & 8);
    int k_off = (lane >> 4) * 8;
    int t_row = lane & 15, t_col = (lane >> 4) * 8;
    int rA = lane >> 2;
    int colb = (lane & 3) * 2;

    uint32_t qf[4][4];
    #pragma unroll
    for (int ks = 0; ks < 4; ++ks){
        uint32_t roff = (uint32_t)((wid*16 + m_local)*PADQ + ks*16 + k_off)*2;
        ldm_x4(qf[ks], sb + roff);
    }

    float oacc[8][4];
    #pragma unroll
    for (int j = 0; j < 8; j++)
        #pragma unroll
        for (int q = 0; q < 4; q++) oacc[j][q] = 0.f;
    float m0 = -1e30f, m1 = -1e30f, l0 = 0.f, l1 = 0.f;

    for (int c = 0; c < nchunks; ++c){
        int buf = c & 1;
        if (c > 0){
            asm volatile("cp.async.wait_group 0;" ::: "memory");
            __syncthreads();
        }
        if (c + 1 < nchunks) load_kv(c + 1, buf ^ 1);
        uint32_t kb = sb + FL_Q + (uint32_t)buf * FL_BUF;

        float s[16][4];
        #pragma unroll
        for (int j = 0; j < 16; j++)
            #pragma unroll
            for (int q = 0; q < 4; q++) s[j][q] = 0.f;
        #pragma unroll
        for (int ks = 0; ks < 4; ++ks){
            uint32_t bh[8][4];
            #pragma unroll
            for (int nt2 = 0; nt2 < 8; ++nt2){
                uint32_t roff = (uint32_t)((nt2*16 + m_local)*PADQ + ks*16 + k_off)*2;
                ldm_x4(bh[nt2], kb + roff);
            }
            #pragma unroll
            for (int nt = 0; nt < 16; ++nt){
                int q = nt >> 1, rs = nt & 1;
                mma16816(s[nt], qf[ks], bh[q][rs], bh[q][rs+2]);
            }
        }

        bool diag = (c == rb);
        float cm0 = -1e30f, cm1 = -1e30f;
        #pragma unroll
        for (int nt = 0; nt < 16; ++nt){
            int cl = nt*8 + colb;
            int r_lo = wid*16 + rA, r_hi = r_lo + 8;
            #pragma unroll
            for (int q = 0; q < 4; q++) s[nt][q] *= 0.125f;
            if (diag){
                if (cl     > r_lo) s[nt][0] = -1e30f;
                if (cl + 1 > r_lo) s[nt][1] = -1e30f;
                if (cl     > r_hi) s[nt][2] = -1e30f;
                if (cl + 1 > r_hi) s[nt][3] = -1e30f;
            }
            cm0 = fmaxf(cm0, fmaxf(s[nt][0], s[nt][1]));
            cm1 = fmaxf(cm1, fmaxf(s[nt][2], s[nt][3]));
        }
        cm0 = fmaxf(cm0, __shfl_xor_sync(0xffffffffu, cm0, 1));
        cm0 = fmaxf(cm0, __shfl_xor_sync(0xffffffffu, cm0, 2));
        cm1 = fmaxf(cm1, __shfl_xor_sync(0xffffffffu, cm1, 1));
        cm1 = fmaxf(cm1, __shfl_xor_sync(0xffffffffu, cm1, 2));
        float mn0 = fmaxf(m0, cm0), mn1 = fmaxf(m1, cm1);
        float al0 = expf(m0 - mn0), al1 = expf(m1 - mn1);
        m0 = mn0; m1 = mn1;

        float ls0 = 0.f, ls1 = 0.f;
        #pragma unroll
        for (int nt = 0; nt < 16; ++nt){
            s[nt][0] = expf(s[nt][0] - mn0);
            s[nt][1] = expf(s[nt][1] - mn0);
            s[nt][2] = expf(s[nt][2] - mn1);
            s[nt][3] = expf(s[nt][3] - mn1);
            ls0 += s[nt][0] + s[nt][1];
            ls1 += s[nt][2] + s[nt][3];
        }
        ls0 += __shfl_xor_sync(0xffffffffu, ls0, 1);
        ls0 += __shfl_xor_sync(0xffffffffu, ls0, 2);
        ls1 += __shfl_xor_sync(0xffffffffu, ls1, 1);
        ls1 += __shfl_xor_sync(0xffffffffu, ls1, 2);
        l0 = l0 * al0 + ls0;
        l1 = l1 * al1 + ls1;

        #pragma unroll
        for (int nt = 0; nt < 8; ++nt){
            oacc[nt][0] *= al0; oacc[nt][1] *= al0;
            oacc[nt][2] *= al1; oacc[nt][3] *= al1;
        }

        uint32_t vb = kb + FL_KV;
        #pragma unroll
        for (int kk = 0; kk < 8; ++kk){
            uint32_t a[4];
            a[0] = pack_h2(s[2*kk][0],   s[2*kk][1]);
            a[1] = pack_h2(s[2*kk][2],   s[2*kk][3]);
            a[2] = pack_h2(s[2*kk+1][0], s[2*kk+1][1]);
            a[3] = pack_h2(s[2*kk+1][2], s[2*kk+1][3]);
            uint32_t bv[4][4];
            #pragma unroll
            for (int g2 = 0; g2 < 4; ++g2){
                uint32_t voff = (uint32_t)((kk*16 + t_row)*PADQ + g2*16 + t_col)*2;
                ldm_x4_t(bv[g2], vb + voff);
            }
            #pragma unroll
            for (int nt = 0; nt < 8; ++nt){
                int g2 = nt >> 1, sub = (nt & 1) * 2;
                mma16816(oacc[nt], a, bv[g2][sub], bv[g2][sub+1]);
            }
        }
    }

    float inv0 = 1.f / l0, inv1 = 1.f / l1;
    #pragma unroll
    for (int nt = 0; nt < 8; ++nt){
        long row = row0 + wid*16 + rA;
        long col = nt*8 + colb;
        size_t idx = (size_t)(obase + row*(long)DD + col);
        store_half2(oh, idx,        oacc[nt][0]*inv0, oacc[nt][1]*inv0);
        store_half2(oh, idx + 8*DD, oacc[nt][2]*inv1, oacc[nt][3]*inv1);
    }
}

// ================= pointwise ================================================
// add + LN; delta fp16; optionally mirrors fp32 result into out2 (final layer).
__global__ __launch_bounds__(256) void add_ln_k(float* __restrict__ h,
                                                const __half* __restrict__ delta,
                                                const float* __restrict__ w,
                                                const float* __restrict__ b,
                                                float* __restrict__ out2){
    long t = blockIdx.x;
    int tid = threadIdx.x;
    int j = tid * 4;
    __shared__ float sh[8];
    float4 hv = *(const float4*)(h + t * DD + j);
    __half2 d0 = *(const __half2*)(delta + t * DD + j);
    __half2 d1 = *(const __half2*)(delta + t * DD + j + 2);
    float x[4] = {hv.x + __low2float(d0), hv.y + __high2float(d0),
                  hv.z + __low2float(d1), hv.w + __high2float(d1)};
    float s = x[0] + x[1] + x[2] + x[3];
    float mean = blockSum256(s, sh) * (1.f / DD);
    float sq = 0.f;
    #pragma unroll
    for (int c = 0; c < 4; c++){ float d = x[c] - mean; sq += d * d; }
    float var = blockSum256(sq, sh) * (1.f / DD);
    float inv = rsqrtf(var + 1e-5f);
    float4 o;
    o.x = (x[0]-mean)*inv*w[j+0] + b[j+0];
    o.y = (x[1]-mean)*inv*w[j+1] + b[j+1];
    o.z = (x[2]-mean)*inv*w[j+2] + b[j+2];
    o.w = (x[3]-mean)*inv*w[j+3] + b[j+3];
    size_t idx = (size_t)t * DD + j;
    *(float4*)(h + idx) = o;
    store_half4(g_hh, idx, o);
    if (out2) *(float4*)(out2 + idx) = o;
}

// ================= launch ===================================================
extern "C" void kernel_launch(void* const* d_in, const int* in_sizes, int n_in,
                              void* d_out, int out_size)
{
    const int*   x    = (const int*)  d_in[0];
    const float* tok  = (const float*)d_in[1];
    const float* pos  = (const float*)d_in[2];
    const float* Wq   = (const float*)d_in[3];
    const float* bq   = (const float*)d_in[4];
    const float* Wk   = (const float*)d_in[5];
    const float* bk   = (const float*)d_in[6];
    const float* Wv   = (const float*)d_in[7];
    const float* bv   = (const float*)d_in[8];
    const float* Wo   = (const float*)d_in[9];
    const float* bo   = (const float*)d_in[10];
    const float* ln1w = (const float*)d_in[11];
    const float* ln1b = (const float*)d_in[12];
    const float* ln2w = (const float*)d_in[13];
    const float* ln2b = (const float*)d_in[14];
    const float* W1   = (const float*)d_in[15];
    const float* b1   = (const float*)d_in[16];
    const float* W2   = (const float*)d_in[17];
    const float* b2   = (const float*)d_in[18];
    const float* Wout = (const float*)d_in[19];
    const float* bout = (const float*)d_in[20];
    float* out = (float*)d_out;

    static int attr_set = 0;
    if (!attr_set){
        cudaFuncSetAttribute(gemm_nn, cudaFuncAttributeMaxDynamicSharedMemorySize, GM_SMEM);
        cudaFuncSetAttribute(flash_k, cudaFuncAttributeMaxDynamicSharedMemorySize, FL_SMEM);
        attr_set = 1;
    }

    float *h, *bqkv;
    __half *hh, *qh, *oh, *ffh, *th;
    __half *wqn, *won, *w1n, *w2n, *woutn;
    cudaGetSymbolAddress((void**)&h,    g_h);
    cudaGetSymbolAddress((void**)&bqkv, g_bqkv);
    cudaGetSymbolAddress((void**)&hh,   g_hh);
    cudaGetSymbolAddress((void**)&qh,   g_qkvh);
    cudaGetSymbolAddress((void**)&oh,   g_oh);
    cudaGetSymbolAddress((void**)&ffh,  g_ffh);
    cudaGetSymbolAddress((void**)&th,   g_th);
    cudaGetSymbolAddress((void**)&wqn,  g_wqkvn);
    cudaGetSymbolAddress((void**)&won,  g_wo_n);
    cudaGetSymbolAddress((void**)&w1n,  g_w1_n);
    cudaGetSymbolAddress((void**)&w2n,  g_w2_n);
    cudaGetSymbolAddress((void**)&woutn,g_woutn);

    // --- weight prep: permute/cast only (no transposes) ---
    packbias_k<<<24, 256>>>(bq, bk, bv);
    qkvpack_k<<<2048, 256>>>(Wq, wqn, 0);
    qkvpack_k<<<2048, 256>>>(Wk, wqn, 1);
    qkvpack_k<<<2048, 256>>>(Wv, wqn, 2);
    cast_k<<<2048,  256>>>(Wo,   won);    // 2*1024*1024
    cast_k<<<8192,  256>>>(W1,   w1n);    // 2*1024*4096
    cast_k<<<8192,  256>>>(W2,   w2n);    // 2*4096*1024
    cast_k<<<32000, 256>>>(Wout, woutn);  // 1024*32000

    embed_k<<<BS, 256>>>(x, tok, pos);

    for (int l = 0; l < LL; l++){
        // QKV: [4096,1024] x [1024,3072] -> fp16
        gemm_nn<<<dim3(BS/128, 3*DD/128), 256, GM_SMEM>>>(
            hh, wqn + (long)l*DD*3*DD, bqkv + (long)l*3*DD,
            0, qh, DD, 3*DD, 3*DD, 2);
        // fused attention
        flash_k<<<dim3(HH*BB, SS/128), 256, FL_SMEM>>>(qh, oh);
        // Wo -> fp16 delta
        gemm_nn<<<dim3(BS/128, DD/128), 256, GM_SMEM>>>(
            oh, won + (long)l*DD*DD, bo + (long)l*DD,
            0, th, DD, DD, DD, 2);
        add_ln_k<<<BS, 256>>>(h, th, ln1w + (long)l*DD, ln1b + (long)l*DD, 0);
        // W1 + GELU -> ff (fp16)
        gemm_nn<<<dim3(BS/128, FFD/128), 256, GM_SMEM>>>(
            hh, w1n + (long)l*DD*FFD, b1 + (long)l*FFD,
            0, ffh, DD, FFD, FFD, 1);
        // W2 -> fp16 delta
        gemm_nn<<<dim3(BS/128, DD/128), 256, GM_SMEM>>>(
            ffh, w2n + (long)l*FFD*DD, b2 + (long)l*DD,
            0, th, FFD, DD, DD, 2);
        add_ln_k<<<BS, 256>>>(h, th, ln2w + (long)l*DD, ln2b + (long)l*DD,
                              (l == LL-1) ? (out + (long)BS*VV) : 0);
    }

    // logits (fp32 out)
    gemm_nn<<<dim3(BS/128, VV/128), 256, GM_SMEM>>>(
        hh, woutn, bout, out, 0, DD, VV, VV, 0);
}